// round 6
// baseline (speedup 1.0000x reference)
#include <cuda_runtime.h>
#include <cuda_bf16.h>
#include <math.h>
#include <stdint.h>

#define T_  2048
#define D_  4096
#define H_  16
#define DH_ 256
#define RR_ 64
#define FF_ 16384

// GEMM tiling
#define MT   128
#define NTT  128
#define KC   64
#define STAGE_B 65536            // Ah(16K)+Al(16K)+Bh(16K)+Bl(16K)
#define NSTAGE 3
#define GEMM_SMEM_BYTES (NSTAGE * STAGE_B)
#define RASTER_G 8               // m-tiles per rasterization group

typedef __nv_bfloat16 bf16;

// ---------------- scratch (static device arrays: allocation-free) -----------
__device__ float g_q   [(size_t)T_ * D_];
__device__ float g_k   [(size_t)T_ * D_];
__device__ float g_v   [(size_t)T_ * D_];
__device__ float g_attn[(size_t)T_ * D_];
__device__ float g_sc  [(size_t)H_ * T_ * T_];

__device__ bf16 g_xnh [(size_t)T_ * D_];
__device__ bf16 g_xnl [(size_t)T_ * D_];
__device__ bf16 g_qh  [(size_t)T_ * D_];
__device__ bf16 g_ql  [(size_t)T_ * D_];
__device__ bf16 g_kh  [(size_t)T_ * D_];
__device__ bf16 g_kl  [(size_t)T_ * D_];
__device__ bf16 g_vth [(size_t)H_ * DH_ * T_];
__device__ bf16 g_vtl [(size_t)H_ * DH_ * T_];
__device__ bf16 g_sch [(size_t)H_ * T_ * T_];
__device__ bf16 g_scl [(size_t)H_ * T_ * T_];
__device__ bf16 g_cxh [(size_t)T_ * D_];
__device__ bf16 g_cxl [(size_t)T_ * D_];
__device__ bf16 g_hbh [(size_t)T_ * FF_];
__device__ bf16 g_hbl [(size_t)T_ * FF_];
__device__ bf16 g_wqh [(size_t)D_ * D_];
__device__ bf16 g_wql [(size_t)D_ * D_];
__device__ bf16 g_wkh [(size_t)D_ * D_];
__device__ bf16 g_wkl [(size_t)D_ * D_];
__device__ bf16 g_wvh [(size_t)D_ * D_];
__device__ bf16 g_wvl [(size_t)D_ * D_];
__device__ bf16 g_woh [(size_t)D_ * D_];
__device__ bf16 g_wol [(size_t)D_ * D_];
__device__ bf16 g_w1h [(size_t)D_ * FF_];
__device__ bf16 g_w1l [(size_t)D_ * FF_];
__device__ bf16 g_w2h [(size_t)D_ * FF_];
__device__ bf16 g_w2l [(size_t)D_ * FF_];

// ---------------- helpers ----------------------------------------------------
__device__ __forceinline__ uint32_t smem_u32(const void* p) {
    uint32_t a;
    asm("{ .reg .u64 t; cvta.to.shared.u64 t, %1; cvt.u32.u64 %0, t; }"
        : "=r"(a) : "l"(p));
    return a;
}

#define SWZ(o) ((o) ^ (((o) >> 3) & 0x70))

#define CP16(dst, src) \
    asm volatile("cp.async.cg.shared.global [%0], [%1], 16;" \
                 :: "r"(dst), "l"(src))
#define CPCOMMIT() asm volatile("cp.async.commit_group;" ::: "memory")
#define CPWAIT1()  asm volatile("cp.async.wait_group 1;" ::: "memory")
#define CPWAIT0()  asm volatile("cp.async.wait_group 0;" ::: "memory")

__device__ __forceinline__ void ldm_x4(uint32_t* r, uint32_t a) {
    asm volatile("ldmatrix.sync.aligned.m8n8.x4.shared.b16 {%0,%1,%2,%3}, [%4];"
                 : "=r"(r[0]), "=r"(r[1]), "=r"(r[2]), "=r"(r[3]) : "r"(a));
}

__device__ __forceinline__ void mma16816(float* d, const uint32_t* a, const uint32_t* b) {
    asm volatile("mma.sync.aligned.m16n8k16.row.col.f32.bf16.bf16.f32 "
                 "{%0,%1,%2,%3}, {%4,%5,%6,%7}, {%8,%9}, {%0,%1,%2,%3};"
                 : "+f"(d[0]), "+f"(d[1]), "+f"(d[2]), "+f"(d[3])
                 : "r"(a[0]), "r"(a[1]), "r"(a[2]), "r"(a[3]),
                   "r"(b[0]), "r"(b[1]));
}

// split fp32 pair -> packed bf16x2 hi and lo
__device__ __forceinline__ void split2(float x, float y, uint32_t& hi, uint32_t& lo) {
    bf16 hx = __float2bfloat16_rn(x);
    bf16 hy = __float2bfloat16_rn(y);
    float rx = x - __bfloat162float(hx);
    float ry = y - __bfloat162float(hy);
    bf16 lx = __float2bfloat16_rn(rx);
    bf16 ly = __float2bfloat16_rn(ry);
    hi = ((uint32_t)__bfloat16_as_ushort(hy) << 16) | (uint32_t)__bfloat16_as_ushort(hx);
    lo = ((uint32_t)__bfloat16_as_ushort(ly) << 16) | (uint32_t)__bfloat16_as_ushort(lx);
}

__device__ __forceinline__ float gelu_f(float x)
{
    const float x3 = x * x * x;
    return 0.5f * x * (1.0f + tanhf(0.7978845608028654f * (x + 0.044715f * x3)));
}

// ---------------- LayerNorm -> split bf16 ------------------------------------
__global__ void ln_split_kernel(const float* __restrict__ x,
                                const float* __restrict__ scale,
                                const float* __restrict__ offset,
                                bf16* __restrict__ oh, bf16* __restrict__ ol)
{
    const int t = blockIdx.x;
    const float* xr = x + (size_t)t * D_;
    const int base = threadIdx.x * 16;
    __shared__ float red[256];

    float v[16];
#pragma unroll
    for (int i = 0; i < 16; i += 4)
        *reinterpret_cast<float4*>(v + i) =
            *reinterpret_cast<const float4*>(xr + base + i);

    float s = 0.f;
#pragma unroll
    for (int i = 0; i < 16; i++) s += v[i];
    red[threadIdx.x] = s; __syncthreads();
    for (int o = 128; o > 0; o >>= 1) {
        if (threadIdx.x < o) red[threadIdx.x] += red[threadIdx.x + o];
        __syncthreads();
    }
    const float mean = red[0] * (1.0f / D_);
    __syncthreads();

    float vv = 0.f;
#pragma unroll
    for (int i = 0; i < 16; i++) { float d = v[i] - mean; vv += d * d; }
    red[threadIdx.x] = vv; __syncthreads();
    for (int o = 128; o > 0; o >>= 1) {
        if (threadIdx.x < o) red[threadIdx.x] += red[threadIdx.x + o];
        __syncthreads();
    }
    const float rstd = rsqrtf(red[0] * (1.0f / D_) + 1e-5f);

    bf16* ohr = oh + (size_t)t * D_ + base;
    bf16* olr = ol + (size_t)t * D_ + base;
#pragma unroll
    for (int i = 0; i < 16; i += 2) {
        float y0 = (v[i]     - mean) * rstd * scale[base + i]     + offset[base + i];
        float y1 = (v[i + 1] - mean) * rstd * scale[base + i + 1] + offset[base + i + 1];
        uint32_t hi, lo;
        split2(y0, y1, hi, lo);
        *reinterpret_cast<uint32_t*>(ohr + i) = hi;
        *reinterpret_cast<uint32_t*>(olr + i) = lo;
    }
}

// ---------------- RoPE + split (q, k) ----------------------------------------
__global__ void rope_split_kernel(const float* __restrict__ q,
                                  const float* __restrict__ k,
                                  bf16* __restrict__ qh, bf16* __restrict__ ql,
                                  bf16* __restrict__ kh, bf16* __restrict__ kl)
{
    const int t = blockIdx.x;
    const int d0 = threadIdx.x * 16;
    const size_t rb = (size_t)t * D_ + d0;

#pragma unroll
    for (int j = 0; j < 8; j++) {
        const int d = d0 + 2 * j;
        float2 qv = *reinterpret_cast<const float2*>(q + rb + 2 * j);
        float2 kv = *reinterpret_cast<const float2*>(k + rb + 2 * j);
        const int dd = d & (DH_ - 1);
        if (dd < RR_) {
            const int i = dd >> 1;
            const double inv = pow(10000.0, -2.0 * (double)i / (double)RR_);
            const double ang = (double)t * inv;
            const float c = (float)cos(ang);
            const float s = (float)sin(ang);
            float q0 = qv.x, q1 = qv.y;
            qv.x = q0 * c - q1 * s; qv.y = q1 * c + q0 * s;
            float k0 = kv.x, k1 = kv.y;
            kv.x = k0 * c - k1 * s; kv.y = k1 * c + k0 * s;
        }
        uint32_t hi, lo;
        split2(qv.x, qv.y, hi, lo);
        *reinterpret_cast<uint32_t*>(qh + rb + 2 * j) = hi;
        *reinterpret_cast<uint32_t*>(ql + rb + 2 * j) = lo;
        split2(kv.x, kv.y, hi, lo);
        *reinterpret_cast<uint32_t*>(kh + rb + 2 * j) = hi;
        *reinterpret_cast<uint32_t*>(kl + rb + 2 * j) = lo;
    }
}

// ---------------- softmax -> split bf16 --------------------------------------
__global__ void softmax_split_kernel(const float* __restrict__ scores,
                                     bf16* __restrict__ ph, bf16* __restrict__ pl)
{
    const size_t row = blockIdx.x;
    const float* r = scores + row * (size_t)T_;
    const int base = threadIdx.x * 8;
    __shared__ float red[256];

    float v[8];
#pragma unroll
    for (int i = 0; i < 8; i += 4)
        *reinterpret_cast<float4*>(v + i) =
            *reinterpret_cast<const float4*>(r + base + i);

    float m = -1e30f;
#pragma unroll
    for (int i = 0; i < 8; i++) m = fmaxf(m, v[i]);
    red[threadIdx.x] = m; __syncthreads();
    for (int o = 128; o > 0; o >>= 1) {
        if (threadIdx.x < o) red[threadIdx.x] = fmaxf(red[threadIdx.x], red[threadIdx.x + o]);
        __syncthreads();
    }
    m = red[0]; __syncthreads();

    float s = 0.f;
#pragma unroll
    for (int i = 0; i < 8; i++) { v[i] = __expf(v[i] - m); s += v[i]; }
    red[threadIdx.x] = s; __syncthreads();
    for (int o = 128; o > 0; o >>= 1) {
        if (threadIdx.x < o) red[threadIdx.x] += red[threadIdx.x + o];
        __syncthreads();
    }
    const float invs = 1.0f / red[0];

    bf16* phr = ph + row * (size_t)T_ + base;
    bf16* plr = pl + row * (size_t)T_ + base;
#pragma unroll
    for (int i = 0; i < 8; i += 2) {
        uint32_t hi, lo;
        split2(v[i] * invs, v[i + 1] * invs, hi, lo);
        *reinterpret_cast<uint32_t*>(phr + i) = hi;
        *reinterpret_cast<uint32_t*>(plr + i) = lo;
    }
}

// ---------------- transpose + split: in[R][C] fp32 -> out[C][R] bf16 hi/lo ---
__global__ void transpose_split_kernel(const float* __restrict__ in,
                                       bf16* __restrict__ oh, bf16* __restrict__ ol,
                                       int R, int C)
{
    __shared__ float t[32][33];
    const int c0 = blockIdx.x * 32, r0 = blockIdx.y * 32;
    const int x = threadIdx.x, y = threadIdx.y;
#pragma unroll
    for (int i = 0; i < 32; i += 8)
        t[y + i][x] = in[(size_t)(r0 + y + i) * C + c0 + x];
    __syncthreads();
#pragma unroll
    for (int i = 0; i < 32; i += 8) {
        const float vv = t[x][y + i];
        bf16 h = __float2bfloat16_rn(vv);
        bf16 l = __float2bfloat16_rn(vv - __bfloat162float(h));
        const size_t o = (size_t)(c0 + y + i) * R + r0 + x;
        oh[o] = h; ol[o] = l;
    }
}

// per-head transpose+split of V: vt[h][d][t] = v[t][h*DH + d]
__global__ void transpose_v_split_kernel(const float* __restrict__ v,
                                         bf16* __restrict__ oh, bf16* __restrict__ ol)
{
    __shared__ float s[32][33];
    const int h = blockIdx.z;
    const int d0 = blockIdx.x * 32, t0 = blockIdx.y * 32;
    const int x = threadIdx.x, y = threadIdx.y;
#pragma unroll
    for (int i = 0; i < 32; i += 8)
        s[y + i][x] = v[(size_t)(t0 + y + i) * D_ + (size_t)h * DH_ + d0 + x];
    __syncthreads();
#pragma unroll
    for (int i = 0; i < 32; i += 8) {
        const float vv = s[x][y + i];
        bf16 hh = __float2bfloat16_rn(vv);
        bf16 ll = __float2bfloat16_rn(vv - __bfloat162float(hh));
        const size_t o = ((size_t)h * DH_ + d0 + y + i) * T_ + t0 + x;
        oh[o] = hh; ol[o] = ll;
    }
}

// ---------------- split-bf16 mma.sync GEMM (cp.async pipelined) ---------------
// C[z][m][n] = alpha * sum_k (Ah+Al)[z][m][k] * (Bh+Bl)[z][n][k]  (3 products)
enum { E_F32 = 0, E_CAUSAL = 1, E_SPLIT = 2, E_GELU_SPLIT = 3, E_BIASRES = 4 };

__global__ void __launch_bounds__(256, 1)
mma_gemm(int K,
         const bf16* __restrict__ Ah, const bf16* __restrict__ Al,
         int lda, long long sA,
         const bf16* __restrict__ Bh, const bf16* __restrict__ Bl,
         int ldb, long long sB,
         float* __restrict__ C, bf16* __restrict__ Chi, bf16* __restrict__ Clo,
         int ldc, long long sC,
         float alpha, int epi,
         const float* __restrict__ bias,
         const float* __restrict__ res, int ldres)
{
    extern __shared__ char smem[];
    const uint32_t sbase = smem_u32(smem);
    const int tid = threadIdx.x;
    const int wid = tid >> 5, lid = tid & 31;

    // L2-aware rasterization: m-tiles vary fastest within groups of RASTER_G.
    // launch grid: x = n-tiles, y = m-tiles (x-fast launch order).
    int bm, bn;
    {
        const int nbx = gridDim.x, nby = gridDim.y;
        const int bid = blockIdx.y * nbx + blockIdx.x;
        const int tpg = RASTER_G * nbx;
        const int grp = bid / tpg;
        const int r   = bid % tpg;
        const int gm  = grp * RASTER_G;
        const int rows = (nby - gm < RASTER_G) ? (nby - gm) : RASTER_G;
        bm = gm + (r % rows);
        bn = r / rows;
    }
    const int m0 = bm * MT, n0 = bn * NTT;

    Ah += (size_t)blockIdx.z * sA;
    Al += (size_t)blockIdx.z * sA;
    Bh += (size_t)blockIdx.z * sB;
    Bl += (size_t)blockIdx.z * sB;
    if (C)   C   += (size_t)blockIdx.z * sC;
    if (Chi) { Chi += (size_t)blockIdx.z * sC; Clo += (size_t)blockIdx.z * sC; }

    // fully-masked causal tile: write mask, skip compute
    if (epi == E_CAUSAL && n0 > m0 + (MT - 1)) {
        for (int idx = tid * 4; idx < MT * NTT; idx += 256 * 4) {
            const int r = idx / NTT, cc = idx % NTT;
            float4 mv = make_float4(-1e10f, -1e10f, -1e10f, -1e10f);
            *reinterpret_cast<float4*>(C + (size_t)(m0 + r) * ldc + n0 + cc) = mv;
        }
        return;
    }

    const int wm = (wid >> 2) * 64;
    const int wn = (wid & 3) * 32;

    float acc[4][4][4];
#pragma unroll
    for (int i = 0; i < 4; i++)
#pragma unroll
        for (int j = 0; j < 4; j++)
#pragma unroll
            for (int r = 0; r < 4; r++) acc[i][j][r] = 0.f;

    // cp.async chunk assignment
    const int lrow = tid >> 3;     // 0..31 (plus p*32)
    const int lcol = tid & 7;      // 16B column within 128B row

    const int NC = K / KC;

#define ISSUE_STAGE(stg, kc_) do {                                              \
        const int kc__ = (kc_);                                                 \
        _Pragma("unroll")                                                       \
        for (int p = 0; p < 4; p++) {                                           \
            const int row = lrow + p * 32;                                      \
            const uint32_t dsw = SWZ((uint32_t)(row * 128 + lcol * 16));        \
            const uint32_t db = sbase + (uint32_t)(stg) * STAGE_B + dsw;        \
            CP16(db,          Ah + (size_t)(m0 + row) * lda + kc__ + lcol * 8); \
            CP16(db + 16384u, Al + (size_t)(m0 + row) * lda + kc__ + lcol * 8); \
            CP16(db + 32768u, Bh + (size_t)(n0 + row) * ldb + kc__ + lcol * 8); \
            CP16(db + 49152u, Bl + (size_t)(n0 + row) * ldb + kc__ + lcol * 8); \
        }                                                                       \
        CPCOMMIT();                                                             \
    } while (0)

    ISSUE_STAGE(0, 0);
    ISSUE_STAGE(1, KC);

    const uint32_t aRawBase = (uint32_t)((wm + (lid & 15)) * 128 + (lid >> 4) * 16);
    const uint32_t bRawBase = (uint32_t)((wn + (lid & 7) + ((lid >> 4) << 3)) * 128
                                         + (((lid >> 3) & 1) << 4));

    // single-sync pipeline: wait(stage c) -> sync -> issue(stage c+2) -> compute(c)
    // With NSTAGE=3, issue at iter c overwrites stage (c+2)%3 == (c-1)%3, whose
    // last readers (iter c-1 compute) are all past the sync.
    for (int c = 0; c < NC; ++c) {
        if (c + 2 < NC) { CPWAIT1(); } else { CPWAIT0(); }
        __syncthreads();
        if (c + 2 < NC) ISSUE_STAGE((c + 2) % NSTAGE, (c + 2) * KC);

        const uint32_t st = sbase + (uint32_t)(c % NSTAGE) * STAGE_B;

#pragma unroll
        for (int ks = 0; ks < 4; ks++) {
            const uint32_t kb = (uint32_t)ks * 32;
            uint32_t ah[4][4], al[4][4], bh[4][2], bl[4][2];
#pragma unroll
            for (int i = 0; i < 4; i++) {
                const uint32_t raw = aRawBase + (uint32_t)i * (16 * 128) + kb;
                ldm_x4(ah[i], st + SWZ(raw));
                ldm_x4(al[i], st + 16384u + SWZ(raw));
            }
#pragma unroll
            for (int j2 = 0; j2 < 2; j2++) {
                const uint32_t raw = bRawBase + (uint32_t)j2 * (16 * 128) + kb;
                uint32_t t4[4];
                ldm_x4(t4, st + 32768u + SWZ(raw));
                bh[2 * j2][0] = t4[0]; bh[2 * j2][1] = t4[1];
                bh[2 * j2 + 1][0] = t4[2]; bh[2 * j2 + 1][1] = t4[3];
                ldm_x4(t4, st + 49152u + SWZ(raw));
                bl[2 * j2][0] = t4[0]; bl[2 * j2][1] = t4[1];
                bl[2 * j2 + 1][0] = t4[2]; bl[2 * j2 + 1][1] = t4[3];
            }
#pragma unroll
            for (int i = 0; i < 4; i++)
#pragma unroll
                for (int j = 0; j < 4; j++) {
                    mma16816(acc[i][j], ah[i], bh[j]);
                    mma16816(acc[i][j], ah[i], bl[j]);
                    mma16816(acc[i][j], al[i], bh[j]);
                }
        }
    }
#undef ISSUE_STAGE

    // ---------------- epilogue ----------------
    const int tr = lid >> 2, tc = (lid & 3) * 2;
#pragma unroll
    for (int i = 0; i < 4; i++) {
        const int m1 = m0 + wm + i * 16 + tr;
        const int m2 = m1 + 8;
#pragma unroll
        for (int j = 0; j < 4; j++) {
            const int n = n0 + wn + j * 8 + tc;
            float v0 = acc[i][j][0] * alpha;
            float v1 = acc[i][j][1] * alpha;
            float v2 = acc[i][j][2] * alpha;
            float v3 = acc[i][j][3] * alpha;
            if (epi == E_CAUSAL) {
                if (n     > m1) v0 = -1e10f;
                if (n + 1 > m1) v1 = -1e10f;
                if (n     > m2) v2 = -1e10f;
                if (n + 1 > m2) v3 = -1e10f;
            } else if (epi == E_GELU_SPLIT) {
                const float b0 = bias[n], b1 = bias[n + 1];
                v0 = gelu_f(v0 + b0); v1 = gelu_f(v1 + b1);
                v2 = gelu_f(v2 + b0); v3 = gelu_f(v3 + b1);
            } else if (epi == E_BIASRES) {
                const float b0 = bias[n], b1 = bias[n + 1];
                const float2 r1 = *reinterpret_cast<const float2*>(res + (size_t)m1 * ldres + n);
                const float2 r2 = *reinterpret_cast<const float2*>(res + (size_t)m2 * ldres + n);
                v0 += b0 + r1.x; v1 += b1 + r1.y;
                v2 += b0 + r2.x; v3 += b1 + r2.y;
            }
            if (epi == E_SPLIT || epi == E_GELU_SPLIT) {
                uint32_t hi, lo;
                split2(v0, v1, hi, lo);
                *reinterpret_cast<uint32_t*>(Chi + (size_t)m1 * ldc + n) = hi;
                *reinterpret_cast<uint32_t*>(Clo + (size_t)m1 * ldc + n) = lo;
                split2(v2, v3, hi, lo);
                *reinterpret_cast<uint32_t*>(Chi + (size_t)m2 * ldc + n) = hi;
                *reinterpret_cast<uint32_t*>(Clo + (size_t)m2 * ldc + n) = lo;
            } else {
                *reinterpret_cast<float2*>(C + (size_t)m1 * ldc + n) = make_float2(v0, v1);
                *reinterpret_cast<float2*>(C + (size_t)m2 * ldc + n) = make_float2(v2, v3);
            }
        }
    }
}

// ---------------- launch -----------------------------------------------------
extern "C" void kernel_launch(void* const* d_in, const int* in_sizes, int n_in,
                              void* d_out, int out_size)
{
    const float* x    = (const float*)d_in[0];
    const float* ln_s = (const float*)d_in[1];
    const float* ln_o = (const float*)d_in[2];
    const float* wq   = (const float*)d_in[3];
    const float* wk   = (const float*)d_in[4];
    const float* wv   = (const float*)d_in[5];
    const float* wo   = (const float*)d_in[6];
    const float* w1   = (const float*)d_in[7];
    const float* b1   = (const float*)d_in[8];
    const float* w2   = (const float*)d_in[9];
    const float* b2   = (const float*)d_in[10];
    float* out = (float*)d_out;

    float *q, *k, *v, *attn, *sc;
    bf16 *xnh, *xnl, *qh, *ql, *kh, *kl, *vth, *vtl, *sch, *scl;
    bf16 *cxh, *cxl, *hbh, *hbl;
    bf16 *wqh, *wql, *wkh, *wkl, *wvh, *wvl, *woh, *wol, *w1h, *w1l, *w2h, *w2l;

    cudaGetSymbolAddress((void**)&q,    g_q);
    cudaGetSymbolAddress((void**)&k,    g_k);
    cudaGetSymbolAddress((void**)&v,    g_v);
    cudaGetSymbolAddress((void**)&attn, g_attn);
    cudaGetSymbolAddress((void**)&sc,   g_sc);
    cudaGetSymbolAddress((void**)&xnh,  g_xnh);
    cudaGetSymbolAddress((void**)&xnl,  g_xnl);
    cudaGetSymbolAddress((void**)&qh,   g_qh);
    cudaGetSymbolAddress((void**)&ql,   g_ql);
    cudaGetSymbolAddress((void**)&kh,   g_kh);
    cudaGetSymbolAddress((void**)&kl,   g_kl);
    cudaGetSymbolAddress((void**)&vth,  g_vth);
    cudaGetSymbolAddress((void**)&vtl,  g_vtl);
    cudaGetSymbolAddress((void**)&sch,  g_sch);
    cudaGetSymbolAddress((void**)&scl,  g_scl);
    cudaGetSymbolAddress((void**)&cxh,  g_cxh);
    cudaGetSymbolAddress((void**)&cxl,  g_cxl);
    cudaGetSymbolAddress((void**)&hbh,  g_hbh);
    cudaGetSymbolAddress((void**)&hbl,  g_hbl);
    cudaGetSymbolAddress((void**)&wqh,  g_wqh);
    cudaGetSymbolAddress((void**)&wql,  g_wql);
    cudaGetSymbolAddress((void**)&wkh,  g_wkh);
    cudaGetSymbolAddress((void**)&wkl,  g_wkl);
    cudaGetSymbolAddress((void**)&wvh,  g_wvh);
    cudaGetSymbolAddress((void**)&wvl,  g_wvl);
    cudaGetSymbolAddress((void**)&woh,  g_woh);
    cudaGetSymbolAddress((void**)&wol,  g_wol);
    cudaGetSymbolAddress((void**)&w1h,  g_w1h);
    cudaGetSymbolAddress((void**)&w1l,  g_w1l);
    cudaGetSymbolAddress((void**)&w2h,  g_w2h);
    cudaGetSymbolAddress((void**)&w2l,  g_w2l);

    cudaFuncSetAttribute(mma_gemm, cudaFuncAttributeMaxDynamicSharedMemorySize,
                         GEMM_SMEM_BYTES);

    const dim3 tb32(32, 8);

    // 0) weight transpose+split: W[k][n] -> WT hi/lo [n][k]
    transpose_split_kernel<<<dim3(D_ / 32, D_ / 32), tb32>>>(wq, wqh, wql, D_, D_);
    transpose_split_kernel<<<dim3(D_ / 32, D_ / 32), tb32>>>(wk, wkh, wkl, D_, D_);
    transpose_split_kernel<<<dim3(D_ / 32, D_ / 32), tb32>>>(wv, wvh, wvl, D_, D_);
    transpose_split_kernel<<<dim3(D_ / 32, D_ / 32), tb32>>>(wo, woh, wol, D_, D_);
    transpose_split_kernel<<<dim3(FF_ / 32, D_ / 32), tb32>>>(w1, w1h, w1l, D_, FF_);
    transpose_split_kernel<<<dim3(D_ / 32, FF_ / 32), tb32>>>(w2, w2h, w2l, FF_, D_);

    // 1) LayerNorm -> xn hi/lo
    ln_split_kernel<<<T_, 256>>>(x, ln_s, ln_o, xnh, xnl);

    // 2) Q/K/V projections (fp32 out)
    {
        dim3 g(D_ / NTT, T_ / MT, 1);
        mma_gemm<<<g, 256, GEMM_SMEM_BYTES>>>(D_, xnh, xnl, D_, 0, wqh, wql, D_, 0,
            q, nullptr, nullptr, D_, 0, 1.f, E_F32, nullptr, nullptr, 0);
        mma_gemm<<<g, 256, GEMM_SMEM_BYTES>>>(D_, xnh, xnl, D_, 0, wkh, wkl, D_, 0,
            k, nullptr, nullptr, D_, 0, 1.f, E_F32, nullptr, nullptr, 0);
        mma_gemm<<<g, 256, GEMM_SMEM_BYTES>>>(D_, xnh, xnl, D_, 0, wvh, wvl, D_, 0,
            v, nullptr, nullptr, D_, 0, 1.f, E_F32, nullptr, nullptr, 0);
    }

    // 3) RoPE + split q,k
    rope_split_kernel<<<T_, 256>>>(q, k, qh, ql, kh, kl);

    // 4) V transpose + split
    transpose_v_split_kernel<<<dim3(DH_ / 32, T_ / 32, H_), tb32>>>(v, vth, vtl);

    // 5) scores = scale * Q_h @ K_h^T + causal (fp32)
    {
        dim3 g(T_ / NTT, T_ / MT, H_);
        mma_gemm<<<g, 256, GEMM_SMEM_BYTES>>>(DH_,
            qh, ql, D_, DH_,
            kh, kl, D_, DH_,
            sc, nullptr, nullptr, T_, (long long)T_ * T_,
            0.0625f, E_CAUSAL, nullptr, nullptr, 0);
    }

    // 6) softmax -> P hi/lo
    softmax_split_kernel<<<H_ * T_, 256>>>(sc, sch, scl);

    // 7) ctx = P_h @ V_h  (split out)
    {
        dim3 g(DH_ / NTT, T_ / MT, H_);
        mma_gemm<<<g, 256, GEMM_SMEM_BYTES>>>(T_,
            sch, scl, T_, (long long)T_ * T_,
            vth, vtl, T_, (long long)DH_ * T_,
            nullptr, cxh, cxl, D_, DH_,
            1.f, E_SPLIT, nullptr, nullptr, 0);
    }

    // 8) attn_out = ctx @ wo (fp32)
    {
        dim3 g(D_ / NTT, T_ / MT, 1);
        mma_gemm<<<g, 256, GEMM_SMEM_BYTES>>>(D_, cxh, cxl, D_, 0, woh, wol, D_, 0,
            attn, nullptr, nullptr, D_, 0, 1.f, E_F32, nullptr, nullptr, 0);
    }

    // 9) h = gelu(xn @ w1 + b1)  (split out)
    {
        dim3 g(FF_ / NTT, T_ / MT, 1);
        mma_gemm<<<g, 256, GEMM_SMEM_BYTES>>>(D_, xnh, xnl, D_, 0, w1h, w1l, D_, 0,
            nullptr, hbh, hbl, FF_, 0, 1.f, E_GELU_SPLIT, b1, nullptr, 0);
    }

    // 10) out = h @ w2 + b2 + attn_out
    {
        dim3 g(D_ / NTT, T_ / MT, 1);
        mma_gemm<<<g, 256, GEMM_SMEM_BYTES>>>(FF_, hbh, hbl, FF_, 0, w2h, w2l, FF_, 0,
            out, nullptr, nullptr, D_, 0, 1.f, E_BIASRES, b2, attn, D_);
    }
}

// round 7
// speedup vs baseline: 1.0136x; 1.0136x over previous
#include <cuda_runtime.h>
#include <cuda_bf16.h>
#include <math.h>
#include <stdint.h>

#define T_  2048
#define D_  4096
#define H_  16
#define DH_ 256
#define RR_ 64
#define FF_ 16384

// GEMM tiling
#define MT   128
#define NTT  128
#define KC   32
#define STAGE_B 32768            // Ah(8K)+Al(8K)+Bh(8K)+Bl(8K)
#define NSTAGE 3
#define GEMM_SMEM_BYTES (NSTAGE * STAGE_B)   // 96KB -> 2 CTAs/SM

typedef __nv_bfloat16 bf16;

// ---------------- scratch (static device arrays: allocation-free) -----------
__device__ float g_q   [(size_t)T_ * D_];
__device__ float g_k   [(size_t)T_ * D_];
__device__ float g_v   [(size_t)T_ * D_];
__device__ float g_attn[(size_t)T_ * D_];
__device__ float g_sc  [(size_t)H_ * T_ * T_];

__device__ bf16 g_xnh [(size_t)T_ * D_];
__device__ bf16 g_xnl [(size_t)T_ * D_];
__device__ bf16 g_qh  [(size_t)T_ * D_];
__device__ bf16 g_ql  [(size_t)T_ * D_];
__device__ bf16 g_kh  [(size_t)T_ * D_];
__device__ bf16 g_kl  [(size_t)T_ * D_];
__device__ bf16 g_vth [(size_t)H_ * DH_ * T_];
__device__ bf16 g_vtl [(size_t)H_ * DH_ * T_];
__device__ bf16 g_sch [(size_t)H_ * T_ * T_];
__device__ bf16 g_scl [(size_t)H_ * T_ * T_];
__device__ bf16 g_cxh [(size_t)T_ * D_];
__device__ bf16 g_cxl [(size_t)T_ * D_];
__device__ bf16 g_hbh [(size_t)T_ * FF_];
__device__ bf16 g_hbl [(size_t)T_ * FF_];
__device__ bf16 g_wqh [(size_t)D_ * D_];
__device__ bf16 g_wql [(size_t)D_ * D_];
__device__ bf16 g_wkh [(size_t)D_ * D_];
__device__ bf16 g_wkl [(size_t)D_ * D_];
__device__ bf16 g_wvh [(size_t)D_ * D_];
__device__ bf16 g_wvl [(size_t)D_ * D_];
__device__ bf16 g_woh [(size_t)D_ * D_];
__device__ bf16 g_wol [(size_t)D_ * D_];
__device__ bf16 g_w1h [(size_t)D_ * FF_];
__device__ bf16 g_w1l [(size_t)D_ * FF_];
__device__ bf16 g_w2h [(size_t)D_ * FF_];
__device__ bf16 g_w2l [(size_t)D_ * FF_];

// ---------------- helpers ----------------------------------------------------
__device__ __forceinline__ uint32_t smem_u32(const void* p) {
    uint32_t a;
    asm("{ .reg .u64 t; cvta.to.shared.u64 t, %1; cvt.u32.u64 %0, t; }"
        : "=r"(a) : "l"(p));
    return a;
}

// SW64 swizzle for 64B rows (conflict-free ldmatrix on 128x32 bf16 tiles)
#define SWZ64(o) ((o) ^ (((o) >> 3) & 0x30))

#define CP16(dst, src) \
    asm volatile("cp.async.cg.shared.global [%0], [%1], 16;" \
                 :: "r"(dst), "l"(src))
#define CPCOMMIT() asm volatile("cp.async.commit_group;" ::: "memory")
#define CPWAIT2()  asm volatile("cp.async.wait_group 2;" ::: "memory")
#define CPWAIT0()  asm volatile("cp.async.wait_group 0;" ::: "memory")

__device__ __forceinline__ void ldm_x4(uint32_t* r, uint32_t a) {
    asm volatile("ldmatrix.sync.aligned.m8n8.x4.shared.b16 {%0,%1,%2,%3}, [%4];"
                 : "=r"(r[0]), "=r"(r[1]), "=r"(r[2]), "=r"(r[3]) : "r"(a));
}

__device__ __forceinline__ void mma16816(float* d, const uint32_t* a, const uint32_t* b) {
    asm volatile("mma.sync.aligned.m16n8k16.row.col.f32.bf16.bf16.f32 "
                 "{%0,%1,%2,%3}, {%4,%5,%6,%7}, {%8,%9}, {%0,%1,%2,%3};"
                 : "+f"(d[0]), "+f"(d[1]), "+f"(d[2]), "+f"(d[3])
                 : "r"(a[0]), "r"(a[1]), "r"(a[2]), "r"(a[3]),
                   "r"(b[0]), "r"(b[1]));
}

// split fp32 pair -> packed bf16x2 hi and lo
__device__ __forceinline__ void split2(float x, float y, uint32_t& hi, uint32_t& lo) {
    bf16 hx = __float2bfloat16_rn(x);
    bf16 hy = __float2bfloat16_rn(y);
    float rx = x - __bfloat162float(hx);
    float ry = y - __bfloat162float(hy);
    bf16 lx = __float2bfloat16_rn(rx);
    bf16 ly = __float2bfloat16_rn(ry);
    hi = ((uint32_t)__bfloat16_as_ushort(hy) << 16) | (uint32_t)__bfloat16_as_ushort(hx);
    lo = ((uint32_t)__bfloat16_as_ushort(ly) << 16) | (uint32_t)__bfloat16_as_ushort(lx);
}

__device__ __forceinline__ float gelu_f(float x)
{
    const float x3 = x * x * x;
    return 0.5f * x * (1.0f + tanhf(0.7978845608028654f * (x + 0.044715f * x3)));
}

// ---------------- LayerNorm -> split bf16 ------------------------------------
__global__ void ln_split_kernel(const float* __restrict__ x,
                                const float* __restrict__ scale,
                                const float* __restrict__ offset,
                                bf16* __restrict__ oh, bf16* __restrict__ ol)
{
    const int t = blockIdx.x;
    const float* xr = x + (size_t)t * D_;
    const int base = threadIdx.x * 16;
    __shared__ float red[256];

    float v[16];
#pragma unroll
    for (int i = 0; i < 16; i += 4)
        *reinterpret_cast<float4*>(v + i) =
            *reinterpret_cast<const float4*>(xr + base + i);

    float s = 0.f;
#pragma unroll
    for (int i = 0; i < 16; i++) s += v[i];
    red[threadIdx.x] = s; __syncthreads();
    for (int o = 128; o > 0; o >>= 1) {
        if (threadIdx.x < o) red[threadIdx.x] += red[threadIdx.x + o];
        __syncthreads();
    }
    const float mean = red[0] * (1.0f / D_);
    __syncthreads();

    float vv = 0.f;
#pragma unroll
    for (int i = 0; i < 16; i++) { float d = v[i] - mean; vv += d * d; }
    red[threadIdx.x] = vv; __syncthreads();
    for (int o = 128; o > 0; o >>= 1) {
        if (threadIdx.x < o) red[threadIdx.x] += red[threadIdx.x + o];
        __syncthreads();
    }
    const float rstd = rsqrtf(red[0] * (1.0f / D_) + 1e-5f);

    bf16* ohr = oh + (size_t)t * D_ + base;
    bf16* olr = ol + (size_t)t * D_ + base;
#pragma unroll
    for (int i = 0; i < 16; i += 2) {
        float y0 = (v[i]     - mean) * rstd * scale[base + i]     + offset[base + i];
        float y1 = (v[i + 1] - mean) * rstd * scale[base + i + 1] + offset[base + i + 1];
        uint32_t hi, lo;
        split2(y0, y1, hi, lo);
        *reinterpret_cast<uint32_t*>(ohr + i) = hi;
        *reinterpret_cast<uint32_t*>(olr + i) = lo;
    }
}

// ---------------- RoPE + split (q, k) ----------------------------------------
__global__ void rope_split_kernel(const float* __restrict__ q,
                                  const float* __restrict__ k,
                                  bf16* __restrict__ qh, bf16* __restrict__ ql,
                                  bf16* __restrict__ kh, bf16* __restrict__ kl)
{
    const int t = blockIdx.x;
    const int d0 = threadIdx.x * 16;
    const size_t rb = (size_t)t * D_ + d0;

#pragma unroll
    for (int j = 0; j < 8; j++) {
        const int d = d0 + 2 * j;
        float2 qv = *reinterpret_cast<const float2*>(q + rb + 2 * j);
        float2 kv = *reinterpret_cast<const float2*>(k + rb + 2 * j);
        const int dd = d & (DH_ - 1);
        if (dd < RR_) {
            const int i = dd >> 1;
            const double inv = pow(10000.0, -2.0 * (double)i / (double)RR_);
            const double ang = (double)t * inv;
            const float c = (float)cos(ang);
            const float s = (float)sin(ang);
            float q0 = qv.x, q1 = qv.y;
            qv.x = q0 * c - q1 * s; qv.y = q1 * c + q0 * s;
            float k0 = kv.x, k1 = kv.y;
            kv.x = k0 * c - k1 * s; kv.y = k1 * c + k0 * s;
        }
        uint32_t hi, lo;
        split2(qv.x, qv.y, hi, lo);
        *reinterpret_cast<uint32_t*>(qh + rb + 2 * j) = hi;
        *reinterpret_cast<uint32_t*>(ql + rb + 2 * j) = lo;
        split2(kv.x, kv.y, hi, lo);
        *reinterpret_cast<uint32_t*>(kh + rb + 2 * j) = hi;
        *reinterpret_cast<uint32_t*>(kl + rb + 2 * j) = lo;
    }
}

// ---------------- softmax -> split bf16 --------------------------------------
__global__ void softmax_split_kernel(const float* __restrict__ scores,
                                     bf16* __restrict__ ph, bf16* __restrict__ pl)
{
    const size_t row = blockIdx.x;
    const float* r = scores + row * (size_t)T_;
    const int base = threadIdx.x * 8;
    __shared__ float red[256];

    float v[8];
#pragma unroll
    for (int i = 0; i < 8; i += 4)
        *reinterpret_cast<float4*>(v + i) =
            *reinterpret_cast<const float4*>(r + base + i);

    float m = -1e30f;
#pragma unroll
    for (int i = 0; i < 8; i++) m = fmaxf(m, v[i]);
    red[threadIdx.x] = m; __syncthreads();
    for (int o = 128; o > 0; o >>= 1) {
        if (threadIdx.x < o) red[threadIdx.x] = fmaxf(red[threadIdx.x], red[threadIdx.x + o]);
        __syncthreads();
    }
    m = red[0]; __syncthreads();

    float s = 0.f;
#pragma unroll
    for (int i = 0; i < 8; i++) { v[i] = __expf(v[i] - m); s += v[i]; }
    red[threadIdx.x] = s; __syncthreads();
    for (int o = 128; o > 0; o >>= 1) {
        if (threadIdx.x < o) red[threadIdx.x] += red[threadIdx.x + o];
        __syncthreads();
    }
    const float invs = 1.0f / red[0];

    bf16* phr = ph + row * (size_t)T_ + base;
    bf16* plr = pl + row * (size_t)T_ + base;
#pragma unroll
    for (int i = 0; i < 8; i += 2) {
        uint32_t hi, lo;
        split2(v[i] * invs, v[i + 1] * invs, hi, lo);
        *reinterpret_cast<uint32_t*>(phr + i) = hi;
        *reinterpret_cast<uint32_t*>(plr + i) = lo;
    }
}

// ---------------- transpose + split: in[R][C] fp32 -> out[C][R] bf16 hi/lo ---
__global__ void transpose_split_kernel(const float* __restrict__ in,
                                       bf16* __restrict__ oh, bf16* __restrict__ ol,
                                       int R, int C)
{
    __shared__ float t[32][33];
    const int c0 = blockIdx.x * 32, r0 = blockIdx.y * 32;
    const int x = threadIdx.x, y = threadIdx.y;
#pragma unroll
    for (int i = 0; i < 32; i += 8)
        t[y + i][x] = in[(size_t)(r0 + y + i) * C + c0 + x];
    __syncthreads();
#pragma unroll
    for (int i = 0; i < 32; i += 8) {
        const float vv = t[x][y + i];
        bf16 h = __float2bfloat16_rn(vv);
        bf16 l = __float2bfloat16_rn(vv - __bfloat162float(h));
        const size_t o = (size_t)(c0 + y + i) * R + r0 + x;
        oh[o] = h; ol[o] = l;
    }
}

// per-head transpose+split of V: vt[h][d][t] = v[t][h*DH + d]
__global__ void transpose_v_split_kernel(const float* __restrict__ v,
                                         bf16* __restrict__ oh, bf16* __restrict__ ol)
{
    __shared__ float s[32][33];
    const int h = blockIdx.z;
    const int d0 = blockIdx.x * 32, t0 = blockIdx.y * 32;
    const int x = threadIdx.x, y = threadIdx.y;
#pragma unroll
    for (int i = 0; i < 32; i += 8)
        s[y + i][x] = v[(size_t)(t0 + y + i) * D_ + (size_t)h * DH_ + d0 + x];
    __syncthreads();
#pragma unroll
    for (int i = 0; i < 32; i += 8) {
        const float vv = s[x][y + i];
        bf16 hh = __float2bfloat16_rn(vv);
        bf16 ll = __float2bfloat16_rn(vv - __bfloat162float(hh));
        const size_t o = ((size_t)h * DH_ + d0 + y + i) * T_ + t0 + x;
        oh[o] = hh; ol[o] = ll;
    }
}

// ---------------- split-bf16 mma.sync GEMM (cp.async pipelined) ---------------
// C[z][m][n] = alpha * sum_k (Ah+Al)[z][m][k] * (Bh+Bl)[z][n][k]  (3 products)
enum { E_F32 = 0, E_CAUSAL = 1, E_SPLIT = 2, E_GELU_SPLIT = 3, E_BIASRES = 4 };

__global__ void __launch_bounds__(256, 2)
mma_gemm(int K,
         const bf16* __restrict__ Ah, const bf16* __restrict__ Al,
         int lda, long long sA,
         const bf16* __restrict__ Bh, const bf16* __restrict__ Bl,
         int ldb, long long sB,
         float* __restrict__ C, bf16* __restrict__ Chi, bf16* __restrict__ Clo,
         int ldc, long long sC,
         float alpha, int epi,
         const float* __restrict__ bias,
         const float* __restrict__ res, int ldres)
{
    extern __shared__ char smem[];
    const uint32_t sbase = smem_u32(smem);
    const int tid = threadIdx.x;
    const int wid = tid >> 5, lid = tid & 31;
    const int m0 = blockIdx.y * MT, n0 = blockIdx.x * NTT;

    Ah += (size_t)blockIdx.z * sA;
    Al += (size_t)blockIdx.z * sA;
    Bh += (size_t)blockIdx.z * sB;
    Bl += (size_t)blockIdx.z * sB;
    if (C)   C   += (size_t)blockIdx.z * sC;
    if (Chi) { Chi += (size_t)blockIdx.z * sC; Clo += (size_t)blockIdx.z * sC; }

    // fully-masked causal tile: write mask, skip compute
    if (epi == E_CAUSAL && n0 > m0 + (MT - 1)) {
        for (int idx = tid * 4; idx < MT * NTT; idx += 256 * 4) {
            const int r = idx / NTT, cc = idx % NTT;
            float4 mv = make_float4(-1e10f, -1e10f, -1e10f, -1e10f);
            *reinterpret_cast<float4*>(C + (size_t)(m0 + r) * ldc + n0 + cc) = mv;
        }
        return;
    }

    const int wm = (wid >> 2) * 64;
    const int wn = (wid & 3) * 32;

    float acc[4][4][4];
#pragma unroll
    for (int i = 0; i < 4; i++)
#pragma unroll
        for (int j = 0; j < 4; j++)
#pragma unroll
            for (int r = 0; r < 4; r++) acc[i][j][r] = 0.f;

    // cp.async chunk assignment: 2048 16B-chunks/stage over 256 threads (8 each)
    const int lrow = tid >> 2;     // 0..63 (plus p*64)
    const int lcol = tid & 3;      // 16B column within 64B row

    const int NC = K / KC;

#define ISSUE_STAGE(stg, kc_) do {                                              \
        const int kc__ = (kc_);                                                 \
        _Pragma("unroll")                                                       \
        for (int p = 0; p < 2; p++) {                                           \
            const int row = lrow + p * 64;                                      \
            const uint32_t dsw = SWZ64((uint32_t)(row * 64 + lcol * 16));       \
            const uint32_t db = sbase + (uint32_t)(stg) * STAGE_B + dsw;        \
            CP16(db,          Ah + (size_t)(m0 + row) * lda + kc__ + lcol * 8); \
            CP16(db + 8192u,  Al + (size_t)(m0 + row) * lda + kc__ + lcol * 8); \
            CP16(db + 16384u, Bh + (size_t)(n0 + row) * ldb + kc__ + lcol * 8); \
            CP16(db + 24576u, Bl + (size_t)(n0 + row) * ldb + kc__ + lcol * 8); \
        }                                                                       \
        CPCOMMIT();                                                             \
    } while (0)

    ISSUE_STAGE(0, 0);
    ISSUE_STAGE(1, KC);

    const uint32_t aRawBase = (uint32_t)((wm + (lid & 15)) * 64 + (lid >> 4) * 16);
    const uint32_t bRawBase = (uint32_t)((wn + (lid & 7) + ((lid >> 4) << 3)) * 64
                                         + (((lid >> 3) & 1) << 4));

    for (int c = 0; c < NC; ++c) {
        if (c + 2 < NC) {
            ISSUE_STAGE((c + 2) % NSTAGE, (c + 2) * KC);
            CPWAIT2();
        } else {
            CPWAIT0();
        }
        __syncthreads();

        const uint32_t st = sbase + (uint32_t)(c % NSTAGE) * STAGE_B;

#pragma unroll
        for (int ks = 0; ks < 2; ks++) {
            const uint32_t kb = (uint32_t)ks * 32;
            uint32_t ah[4][4], al[4][4], bh[4][2], bl[4][2];
#pragma unroll
            for (int i = 0; i < 4; i++) {
                const uint32_t raw = aRawBase + (uint32_t)i * (16 * 64) + kb;
                ldm_x4(ah[i], st + SWZ64(raw));
                ldm_x4(al[i], st + 8192u + SWZ64(raw));
            }
#pragma unroll
            for (int j2 = 0; j2 < 2; j2++) {
                const uint32_t raw = bRawBase + (uint32_t)j2 * (16 * 64) + kb;
                uint32_t t4[4];
                ldm_x4(t4, st + 16384u + SWZ64(raw));
                bh[2 * j2][0] = t4[0]; bh[2 * j2][1] = t4[1];
                bh[2 * j2 + 1][0] = t4[2]; bh[2 * j2 + 1][1] = t4[3];
                ldm_x4(t4, st + 24576u + SWZ64(raw));
                bl[2 * j2][0] = t4[0]; bl[2 * j2][1] = t4[1];
                bl[2 * j2 + 1][0] = t4[2]; bl[2 * j2 + 1][1] = t4[3];
            }
#pragma unroll
            for (int i = 0; i < 4; i++)
#pragma unroll
                for (int j = 0; j < 4; j++) {
                    mma16816(acc[i][j], ah[i], bh[j]);
                    mma16816(acc[i][j], ah[i], bl[j]);
                    mma16816(acc[i][j], al[i], bh[j]);
                }
        }
        __syncthreads();
    }
#undef ISSUE_STAGE

    // ---------------- epilogue ----------------
    const int tr = lid >> 2, tc = (lid & 3) * 2;
#pragma unroll
    for (int i = 0; i < 4; i++) {
        const int m1 = m0 + wm + i * 16 + tr;
        const int m2 = m1 + 8;
#pragma unroll
        for (int j = 0; j < 4; j++) {
            const int n = n0 + wn + j * 8 + tc;
            float v0 = acc[i][j][0] * alpha;
            float v1 = acc[i][j][1] * alpha;
            float v2 = acc[i][j][2] * alpha;
            float v3 = acc[i][j][3] * alpha;
            if (epi == E_CAUSAL) {
                if (n     > m1) v0 = -1e10f;
                if (n + 1 > m1) v1 = -1e10f;
                if (n     > m2) v2 = -1e10f;
                if (n + 1 > m2) v3 = -1e10f;
            } else if (epi == E_GELU_SPLIT) {
                const float b0 = bias[n], b1 = bias[n + 1];
                v0 = gelu_f(v0 + b0); v1 = gelu_f(v1 + b1);
                v2 = gelu_f(v2 + b0); v3 = gelu_f(v3 + b1);
            } else if (epi == E_BIASRES) {
                const float b0 = bias[n], b1 = bias[n + 1];
                const float2 r1 = *reinterpret_cast<const float2*>(res + (size_t)m1 * ldres + n);
                const float2 r2 = *reinterpret_cast<const float2*>(res + (size_t)m2 * ldres + n);
                v0 += b0 + r1.x; v1 += b1 + r1.y;
                v2 += b0 + r2.x; v3 += b1 + r2.y;
            }
            if (epi == E_SPLIT || epi == E_GELU_SPLIT) {
                uint32_t hi, lo;
                split2(v0, v1, hi, lo);
                *reinterpret_cast<uint32_t*>(Chi + (size_t)m1 * ldc + n) = hi;
                *reinterpret_cast<uint32_t*>(Clo + (size_t)m1 * ldc + n) = lo;
                split2(v2, v3, hi, lo);
                *reinterpret_cast<uint32_t*>(Chi + (size_t)m2 * ldc + n) = hi;
                *reinterpret_cast<uint32_t*>(Clo + (size_t)m2 * ldc + n) = lo;
            } else {
                *reinterpret_cast<float2*>(C + (size_t)m1 * ldc + n) = make_float2(v0, v1);
                *reinterpret_cast<float2*>(C + (size_t)m2 * ldc + n) = make_float2(v2, v3);
            }
        }
    }
}

// ---------------- launch -----------------------------------------------------
extern "C" void kernel_launch(void* const* d_in, const int* in_sizes, int n_in,
                              void* d_out, int out_size)
{
    const float* x    = (const float*)d_in[0];
    const float* ln_s = (const float*)d_in[1];
    const float* ln_o = (const float*)d_in[2];
    const float* wq   = (const float*)d_in[3];
    const float* wk   = (const float*)d_in[4];
    const float* wv   = (const float*)d_in[5];
    const float* wo   = (const float*)d_in[6];
    const float* w1   = (const float*)d_in[7];
    const float* b1   = (const float*)d_in[8];
    const float* w2   = (const float*)d_in[9];
    const float* b2   = (const float*)d_in[10];
    float* out = (float*)d_out;

    float *q, *k, *v, *attn, *sc;
    bf16 *xnh, *xnl, *qh, *ql, *kh, *kl, *vth, *vtl, *sch, *scl;
    bf16 *cxh, *cxl, *hbh, *hbl;
    bf16 *wqh, *wql, *wkh, *wkl, *wvh, *wvl, *woh, *wol, *w1h, *w1l, *w2h, *w2l;

    cudaGetSymbolAddress((void**)&q,    g_q);
    cudaGetSymbolAddress((void**)&k,    g_k);
    cudaGetSymbolAddress((void**)&v,    g_v);
    cudaGetSymbolAddress((void**)&attn, g_attn);
    cudaGetSymbolAddress((void**)&sc,   g_sc);
    cudaGetSymbolAddress((void**)&xnh,  g_xnh);
    cudaGetSymbolAddress((void**)&xnl,  g_xnl);
    cudaGetSymbolAddress((void**)&qh,   g_qh);
    cudaGetSymbolAddress((void**)&ql,   g_ql);
    cudaGetSymbolAddress((void**)&kh,   g_kh);
    cudaGetSymbolAddress((void**)&kl,   g_kl);
    cudaGetSymbolAddress((void**)&vth,  g_vth);
    cudaGetSymbolAddress((void**)&vtl,  g_vtl);
    cudaGetSymbolAddress((void**)&sch,  g_sch);
    cudaGetSymbolAddress((void**)&scl,  g_scl);
    cudaGetSymbolAddress((void**)&cxh,  g_cxh);
    cudaGetSymbolAddress((void**)&cxl,  g_cxl);
    cudaGetSymbolAddress((void**)&hbh,  g_hbh);
    cudaGetSymbolAddress((void**)&hbl,  g_hbl);
    cudaGetSymbolAddress((void**)&wqh,  g_wqh);
    cudaGetSymbolAddress((void**)&wql,  g_wql);
    cudaGetSymbolAddress((void**)&wkh,  g_wkh);
    cudaGetSymbolAddress((void**)&wkl,  g_wkl);
    cudaGetSymbolAddress((void**)&wvh,  g_wvh);
    cudaGetSymbolAddress((void**)&wvl,  g_wvl);
    cudaGetSymbolAddress((void**)&woh,  g_woh);
    cudaGetSymbolAddress((void**)&wol,  g_wol);
    cudaGetSymbolAddress((void**)&w1h,  g_w1h);
    cudaGetSymbolAddress((void**)&w1l,  g_w1l);
    cudaGetSymbolAddress((void**)&w2h,  g_w2h);
    cudaGetSymbolAddress((void**)&w2l,  g_w2l);

    cudaFuncSetAttribute(mma_gemm, cudaFuncAttributeMaxDynamicSharedMemorySize,
                         GEMM_SMEM_BYTES);

    const dim3 tb32(32, 8);

    // 0) weight transpose+split: W[k][n] -> WT hi/lo [n][k]
    transpose_split_kernel<<<dim3(D_ / 32, D_ / 32), tb32>>>(wq, wqh, wql, D_, D_);
    transpose_split_kernel<<<dim3(D_ / 32, D_ / 32), tb32>>>(wk, wkh, wkl, D_, D_);
    transpose_split_kernel<<<dim3(D_ / 32, D_ / 32), tb32>>>(wv, wvh, wvl, D_, D_);
    transpose_split_kernel<<<dim3(D_ / 32, D_ / 32), tb32>>>(wo, woh, wol, D_, D_);
    transpose_split_kernel<<<dim3(FF_ / 32, D_ / 32), tb32>>>(w1, w1h, w1l, D_, FF_);
    transpose_split_kernel<<<dim3(D_ / 32, FF_ / 32), tb32>>>(w2, w2h, w2l, FF_, D_);

    // 1) LayerNorm -> xn hi/lo
    ln_split_kernel<<<T_, 256>>>(x, ln_s, ln_o, xnh, xnl);

    // 2) Q/K/V projections (fp32 out)
    {
        dim3 g(D_ / NTT, T_ / MT, 1);
        mma_gemm<<<g, 256, GEMM_SMEM_BYTES>>>(D_, xnh, xnl, D_, 0, wqh, wql, D_, 0,
            q, nullptr, nullptr, D_, 0, 1.f, E_F32, nullptr, nullptr, 0);
        mma_gemm<<<g, 256, GEMM_SMEM_BYTES>>>(D_, xnh, xnl, D_, 0, wkh, wkl, D_, 0,
            k, nullptr, nullptr, D_, 0, 1.f, E_F32, nullptr, nullptr, 0);
        mma_gemm<<<g, 256, GEMM_SMEM_BYTES>>>(D_, xnh, xnl, D_, 0, wvh, wvl, D_, 0,
            v, nullptr, nullptr, D_, 0, 1.f, E_F32, nullptr, nullptr, 0);
    }

    // 3) RoPE + split q,k
    rope_split_kernel<<<T_, 256>>>(q, k, qh, ql, kh, kl);

    // 4) V transpose + split
    transpose_v_split_kernel<<<dim3(DH_ / 32, T_ / 32, H_), tb32>>>(v, vth, vtl);

    // 5) scores = scale * Q_h @ K_h^T + causal (fp32)
    {
        dim3 g(T_ / NTT, T_ / MT, H_);
        mma_gemm<<<g, 256, GEMM_SMEM_BYTES>>>(DH_,
            qh, ql, D_, DH_,
            kh, kl, D_, DH_,
            sc, nullptr, nullptr, T_, (long long)T_ * T_,
            0.0625f, E_CAUSAL, nullptr, nullptr, 0);
    }

    // 6) softmax -> P hi/lo
    softmax_split_kernel<<<H_ * T_, 256>>>(sc, sch, scl);

    // 7) ctx = P_h @ V_h  (split out)
    {
        dim3 g(DH_ / NTT, T_ / MT, H_);
        mma_gemm<<<g, 256, GEMM_SMEM_BYTES>>>(T_,
            sch, scl, T_, (long long)T_ * T_,
            vth, vtl, T_, (long long)DH_ * T_,
            nullptr, cxh, cxl, D_, DH_,
            1.f, E_SPLIT, nullptr, nullptr, 0);
    }

    // 8) attn_out = ctx @ wo (fp32)
    {
        dim3 g(D_ / NTT, T_ / MT, 1);
        mma_gemm<<<g, 256, GEMM_SMEM_BYTES>>>(D_, cxh, cxl, D_, 0, woh, wol, D_, 0,
            attn, nullptr, nullptr, D_, 0, 1.f, E_F32, nullptr, nullptr, 0);
    }

    // 9) h = gelu(xn @ w1 + b1)  (split out)
    {
        dim3 g(FF_ / NTT, T_ / MT, 1);
        mma_gemm<<<g, 256, GEMM_SMEM_BYTES>>>(D_, xnh, xnl, D_, 0, w1h, w1l, D_, 0,
            nullptr, hbh, hbl, FF_, 0, 1.f, E_GELU_SPLIT, b1, nullptr, 0);
    }

    // 10) out = h @ w2 + b2 + attn_out
    {
        dim3 g(D_ / NTT, T_ / MT, 1);
        mma_gemm<<<g, 256, GEMM_SMEM_BYTES>>>(FF_, hbh, hbl, FF_, 0, w2h, w2l, FF_, 0,
            out, nullptr, nullptr, D_, 0, 1.f, E_BIASRES, b2, attn, D_);
    }
}

// round 9
// speedup vs baseline: 1.1777x; 1.1619x over previous
#include <cuda_runtime.h>
#include <cuda_bf16.h>
#include <math.h>
#include <stdint.h>

#define T_  2048
#define D_  4096
#define D3_ 12288
#define H_  16
#define DH_ 256
#define RR_ 64
#define FF_ 16384

// GEMM tiling (R5 proven config)
#define MT   128
#define NTT  128
#define KC   64
#define STAGE_B 65536            // Ah(16K)+Al(16K)+Bh(16K)+Bl(16K)
#define NSTAGE 3
#define GEMM_SMEM_BYTES (NSTAGE * STAGE_B)

typedef __nv_bfloat16 bf16;

// ---------------- scratch (static device arrays: allocation-free) -----------
__device__ float g_qkv [(size_t)T_ * D3_];       // fused q|k|v fp32
__device__ float g_attn[(size_t)T_ * D_];
__device__ float g_sc  [(size_t)H_ * T_ * T_];
__device__ float g_tcos[(size_t)T_ * 32];
__device__ float g_tsin[(size_t)T_ * 32];

__device__ bf16 g_xnh [(size_t)T_ * D_];
__device__ bf16 g_xnl [(size_t)T_ * D_];
__device__ bf16 g_qh  [(size_t)T_ * D_];
__device__ bf16 g_ql  [(size_t)T_ * D_];
__device__ bf16 g_kh  [(size_t)T_ * D_];
__device__ bf16 g_kl  [(size_t)T_ * D_];
__device__ bf16 g_vth [(size_t)H_ * DH_ * T_];
__device__ bf16 g_vtl [(size_t)H_ * DH_ * T_];
__device__ bf16 g_sch [(size_t)H_ * T_ * T_];
__device__ bf16 g_scl [(size_t)H_ * T_ * T_];
__device__ bf16 g_cxh [(size_t)T_ * D_];
__device__ bf16 g_cxl [(size_t)T_ * D_];
__device__ bf16 g_hbh [(size_t)T_ * FF_];
__device__ bf16 g_hbl [(size_t)T_ * FF_];
__device__ bf16 g_wqkvh[(size_t)D3_ * D_];       // fused wq|wk|wv transposed hi
__device__ bf16 g_wqkvl[(size_t)D3_ * D_];
__device__ bf16 g_woh [(size_t)D_ * D_];
__device__ bf16 g_wol [(size_t)D_ * D_];
__device__ bf16 g_w1h [(size_t)D_ * FF_];
__device__ bf16 g_w1l [(size_t)D_ * FF_];
__device__ bf16 g_w2h [(size_t)D_ * FF_];
__device__ bf16 g_w2l [(size_t)D_ * FF_];

// ---------------- helpers ----------------------------------------------------
__device__ __forceinline__ uint32_t smem_u32(const void* p) {
    uint32_t a;
    asm("{ .reg .u64 t; cvta.to.shared.u64 t, %1; cvt.u32.u64 %0, t; }"
        : "=r"(a) : "l"(p));
    return a;
}

#define SWZ(o) ((o) ^ (((o) >> 3) & 0x70))

#define CP16(dst, src) \
    asm volatile("cp.async.cg.shared.global [%0], [%1], 16;" \
                 :: "r"(dst), "l"(src))
#define CPCOMMIT() asm volatile("cp.async.commit_group;" ::: "memory")
#define CPWAIT2()  asm volatile("cp.async.wait_group 2;" ::: "memory")
#define CPWAIT0()  asm volatile("cp.async.wait_group 0;" ::: "memory")

__device__ __forceinline__ void ldm_x4(uint32_t* r, uint32_t a) {
    asm volatile("ldmatrix.sync.aligned.m8n8.x4.shared.b16 {%0,%1,%2,%3}, [%4];"
                 : "=r"(r[0]), "=r"(r[1]), "=r"(r[2]), "=r"(r[3]) : "r"(a));
}

__device__ __forceinline__ void mma16816(float* d, const uint32_t* a, const uint32_t* b) {
    asm volatile("mma.sync.aligned.m16n8k16.row.col.f32.bf16.bf16.f32 "
                 "{%0,%1,%2,%3}, {%4,%5,%6,%7}, {%8,%9}, {%0,%1,%2,%3};"
                 : "+f"(d[0]), "+f"(d[1]), "+f"(d[2]), "+f"(d[3])
                 : "r"(a[0]), "r"(a[1]), "r"(a[2]), "r"(a[3]),
                   "r"(b[0]), "r"(b[1]));
}

// split fp32 pair -> packed bf16x2 hi and lo
__device__ __forceinline__ void split2(float x, float y, uint32_t& hi, uint32_t& lo) {
    bf16 hx = __float2bfloat16_rn(x);
    bf16 hy = __float2bfloat16_rn(y);
    float rx = x - __bfloat162float(hx);
    float ry = y - __bfloat162float(hy);
    bf16 lx = __float2bfloat16_rn(rx);
    bf16 ly = __float2bfloat16_rn(ry);
    hi = ((uint32_t)__bfloat16_as_ushort(hy) << 16) | (uint32_t)__bfloat16_as_ushort(hx);
    lo = ((uint32_t)__bfloat16_as_ushort(ly) << 16) | (uint32_t)__bfloat16_as_ushort(lx);
}

__device__ __forceinline__ float gelu_f(float x)
{
    const float x3 = x * x * x;
    return 0.5f * x * (1.0f + tanhf(0.7978845608028654f * (x + 0.044715f * x3)));
}

// ---------------- RoPE table (double-precision, computed once per launch) ----
__global__ void rope_table_kernel(float* __restrict__ tc, float* __restrict__ ts)
{
    const int t = blockIdx.x;
    const int i = threadIdx.x;          // 0..31
    const double inv = pow(10000.0, -2.0 * (double)i / (double)RR_);
    const double ang = (double)t * inv;
    tc[t * 32 + i] = (float)cos(ang);
    ts[t * 32 + i] = (float)sin(ang);
}

// ---------------- LayerNorm -> split bf16 ------------------------------------
__global__ void ln_split_kernel(const float* __restrict__ x,
                                const float* __restrict__ scale,
                                const float* __restrict__ offset,
                                bf16* __restrict__ oh, bf16* __restrict__ ol)
{
    const int t = blockIdx.x;
    const float* xr = x + (size_t)t * D_;
    const int base = threadIdx.x * 16;
    __shared__ float red[256];

    float v[16];
#pragma unroll
    for (int i = 0; i < 16; i += 4)
        *reinterpret_cast<float4*>(v + i) =
            *reinterpret_cast<const float4*>(xr + base + i);

    float s = 0.f;
#pragma unroll
    for (int i = 0; i < 16; i++) s += v[i];
    red[threadIdx.x] = s; __syncthreads();
    for (int o = 128; o > 0; o >>= 1) {
        if (threadIdx.x < o) red[threadIdx.x] += red[threadIdx.x + o];
        __syncthreads();
    }
    const float mean = red[0] * (1.0f / D_);
    __syncthreads();

    float vv = 0.f;
#pragma unroll
    for (int i = 0; i < 16; i++) { float d = v[i] - mean; vv += d * d; }
    red[threadIdx.x] = vv; __syncthreads();
    for (int o = 128; o > 0; o >>= 1) {
        if (threadIdx.x < o) red[threadIdx.x] += red[threadIdx.x + o];
        __syncthreads();
    }
    const float rstd = rsqrtf(red[0] * (1.0f / D_) + 1e-5f);

    bf16* ohr = oh + (size_t)t * D_ + base;
    bf16* olr = ol + (size_t)t * D_ + base;
#pragma unroll
    for (int i = 0; i < 16; i += 2) {
        float y0 = (v[i]     - mean) * rstd * scale[base + i]     + offset[base + i];
        float y1 = (v[i + 1] - mean) * rstd * scale[base + i + 1] + offset[base + i + 1];
        uint32_t hi, lo;
        split2(y0, y1, hi, lo);
        *reinterpret_cast<uint32_t*>(ohr + i) = hi;
        *reinterpret_cast<uint32_t*>(olr + i) = lo;
    }
}

// ---------------- RoPE + split (q, k cols of fused qkv) ----------------------
__global__ void rope_split_kernel(const float* __restrict__ qkv,
                                  const float* __restrict__ tc,
                                  const float* __restrict__ ts,
                                  bf16* __restrict__ qh, bf16* __restrict__ ql,
                                  bf16* __restrict__ kh, bf16* __restrict__ kl)
{
    const int t = blockIdx.x;
    const int d0 = threadIdx.x * 16;
    const size_t src = (size_t)t * D3_ + d0;   // q at col 0, k at col D_
    const size_t dst = (size_t)t * D_ + d0;

#pragma unroll
    for (int j = 0; j < 8; j++) {
        const int d = d0 + 2 * j;
        float2 qv = *reinterpret_cast<const float2*>(qkv + src + 2 * j);
        float2 kv = *reinterpret_cast<const float2*>(qkv + src + D_ + 2 * j);
        const int dd = d & (DH_ - 1);
        if (dd < RR_) {
            const int i = dd >> 1;
            const float c = tc[t * 32 + i];
            const float s = ts[t * 32 + i];
            float q0 = qv.x, q1 = qv.y;
            qv.x = q0 * c - q1 * s; qv.y = q1 * c + q0 * s;
            float k0 = kv.x, k1 = kv.y;
            kv.x = k0 * c - k1 * s; kv.y = k1 * c + k0 * s;
        }
        uint32_t hi, lo;
        split2(qv.x, qv.y, hi, lo);
        *reinterpret_cast<uint32_t*>(qh + dst + 2 * j) = hi;
        *reinterpret_cast<uint32_t*>(ql + dst + 2 * j) = lo;
        split2(kv.x, kv.y, hi, lo);
        *reinterpret_cast<uint32_t*>(kh + dst + 2 * j) = hi;
        *reinterpret_cast<uint32_t*>(kl + dst + 2 * j) = lo;
    }
}

// ---------------- softmax -> split bf16 --------------------------------------
__global__ void softmax_split_kernel(const float* __restrict__ scores,
                                     bf16* __restrict__ ph, bf16* __restrict__ pl)
{
    const size_t row = blockIdx.x;
    const float* r = scores + row * (size_t)T_;
    const int base = threadIdx.x * 8;
    __shared__ float red[256];

    float v[8];
#pragma unroll
    for (int i = 0; i < 8; i += 4)
        *reinterpret_cast<float4*>(v + i) =
            *reinterpret_cast<const float4*>(r + base + i);

    float m = -1e30f;
#pragma unroll
    for (int i = 0; i < 8; i++) m = fmaxf(m, v[i]);
    red[threadIdx.x] = m; __syncthreads();
    for (int o = 128; o > 0; o >>= 1) {
        if (threadIdx.x < o) red[threadIdx.x] = fmaxf(red[threadIdx.x], red[threadIdx.x + o]);
        __syncthreads();
    }
    m = red[0]; __syncthreads();

    float s = 0.f;
#pragma unroll
    for (int i = 0; i < 8; i++) { v[i] = __expf(v[i] - m); s += v[i]; }
    red[threadIdx.x] = s; __syncthreads();
    for (int o = 128; o > 0; o >>= 1) {
        if (threadIdx.x < o) red[threadIdx.x] += red[threadIdx.x + o];
        __syncthreads();
    }
    const float invs = 1.0f / red[0];

    bf16* phr = ph + row * (size_t)T_ + base;
    bf16* plr = pl + row * (size_t)T_ + base;
#pragma unroll
    for (int i = 0; i < 8; i += 2) {
        uint32_t hi, lo;
        split2(v[i] * invs, v[i + 1] * invs, hi, lo);
        *reinterpret_cast<uint32_t*>(phr + i) = hi;
        *reinterpret_cast<uint32_t*>(plr + i) = lo;
    }
}

// ---------------- transpose + split: in[R][C] fp32 -> out[C][R] bf16 hi/lo ---
__global__ void transpose_split_kernel(const float* __restrict__ in,
                                       bf16* __restrict__ oh, bf16* __restrict__ ol,
                                       int R, int C)
{
    __shared__ float t[32][33];
    const int c0 = blockIdx.x * 32, r0 = blockIdx.y * 32;
    const int x = threadIdx.x, y = threadIdx.y;
#pragma unroll
    for (int i = 0; i < 32; i += 8)
        t[y + i][x] = in[(size_t)(r0 + y + i) * C + c0 + x];
    __syncthreads();
#pragma unroll
    for (int i = 0; i < 32; i += 8) {
        const float vv = t[x][y + i];
        bf16 h = __float2bfloat16_rn(vv);
        bf16 l = __float2bfloat16_rn(vv - __bfloat162float(h));
        const size_t o = (size_t)(c0 + y + i) * R + r0 + x;
        oh[o] = h; ol[o] = l;
    }
}

// per-head transpose+split of V (cols 2D.. of fused qkv): vt[h][d][t]
__global__ void transpose_v_split_kernel(const float* __restrict__ qkv,
                                         bf16* __restrict__ oh, bf16* __restrict__ ol)
{
    __shared__ float s[32][33];
    const int h = blockIdx.z;
    const int d0 = blockIdx.x * 32, t0 = blockIdx.y * 32;
    const int x = threadIdx.x, y = threadIdx.y;
#pragma unroll
    for (int i = 0; i < 32; i += 8)
        s[y + i][x] = qkv[(size_t)(t0 + y + i) * D3_ + 2 * D_ + (size_t)h * DH_ + d0 + x];
    __syncthreads();
#pragma unroll
    for (int i = 0; i < 32; i += 8) {
        const float vv = s[x][y + i];
        bf16 hh = __float2bfloat16_rn(vv);
        bf16 ll = __float2bfloat16_rn(vv - __bfloat162float(hh));
        const size_t o = ((size_t)h * DH_ + d0 + y + i) * T_ + t0 + x;
        oh[o] = hh; ol[o] = ll;
    }
}

// ---------------- split-bf16 mma.sync GEMM (cp.async pipelined) ---------------
// C[z][m][n] = alpha * sum_k (Ah+Al)[z][m][k] * (Bh+Bl)[z][n][k]  (3 products)
// climit != 0: effective K for row-block at m0 is (m0 + MT) (causal PV).
enum { E_F32 = 0, E_CAUSAL = 1, E_SPLIT = 2, E_GELU_SPLIT = 3, E_BIASRES = 4 };

__global__ void __launch_bounds__(256, 1)
mma_gemm(int K, int climit,
         const bf16* __restrict__ Ah, const bf16* __restrict__ Al,
         int lda, long long sA,
         const bf16* __restrict__ Bh, const bf16* __restrict__ Bl,
         int ldb, long long sB,
         float* __restrict__ C, bf16* __restrict__ Chi, bf16* __restrict__ Clo,
         int ldc, long long sC,
         float alpha, int epi,
         const float* __restrict__ bias,
         const float* __restrict__ res, int ldres)
{
    extern __shared__ char smem[];
    const uint32_t sbase = smem_u32(smem);
    const int tid = threadIdx.x;
    const int wid = tid >> 5, lid = tid & 31;
    const int m0 = blockIdx.y * MT, n0 = blockIdx.x * NTT;

    Ah += (size_t)blockIdx.z * sA;
    Al += (size_t)blockIdx.z * sA;
    Bh += (size_t)blockIdx.z * sB;
    Bl += (size_t)blockIdx.z * sB;
    if (C)   C   += (size_t)blockIdx.z * sC;
    if (Chi) { Chi += (size_t)blockIdx.z * sC; Clo += (size_t)blockIdx.z * sC; }

    // fully-masked causal tile: write mask, skip compute
    if (epi == E_CAUSAL && n0 > m0 + (MT - 1)) {
        for (int idx = tid * 4; idx < MT * NTT; idx += 256 * 4) {
            const int r = idx / NTT, cc = idx % NTT;
            float4 mv = make_float4(-1e10f, -1e10f, -1e10f, -1e10f);
            *reinterpret_cast<float4*>(C + (size_t)(m0 + r) * ldc + n0 + cc) = mv;
        }
        return;
    }

    const int Keff = climit ? (m0 + MT) : K;   // causal K-limit (multiple of KC)

    const int wm = (wid >> 2) * 64;
    const int wn = (wid & 3) * 32;

    float acc[4][4][4];
#pragma unroll
    for (int i = 0; i < 4; i++)
#pragma unroll
        for (int j = 0; j < 4; j++)
#pragma unroll
            for (int r = 0; r < 4; r++) acc[i][j][r] = 0.f;

    // cp.async chunk assignment: 4096 16B-chunks/stage over 256 threads
    const int lrow = tid >> 3;     // 0..31 (plus p*32)
    const int lcol = tid & 7;      // 16B column within 128B row

    const int NC = Keff / KC;

#define ISSUE_STAGE(stg, kc_) do {                                              \
        const int kc__ = (kc_);                                                 \
        _Pragma("unroll")                                                       \
        for (int p = 0; p < 4; p++) {                                           \
            const int row = lrow + p * 32;                                      \
            const uint32_t dsw = SWZ((uint32_t)(row * 128 + lcol * 16));        \
            const uint32_t db = sbase + (uint32_t)(stg) * STAGE_B + dsw;        \
            CP16(db,          Ah + (size_t)(m0 + row) * lda + kc__ + lcol * 8); \
            CP16(db + 16384u, Al + (size_t)(m0 + row) * lda + kc__ + lcol * 8); \
            CP16(db + 32768u, Bh + (size_t)(n0 + row) * ldb + kc__ + lcol * 8); \
            CP16(db + 49152u, Bl + (size_t)(n0 + row) * ldb + kc__ + lcol * 8); \
        }                                                                       \
        CPCOMMIT();                                                             \
    } while (0)

    ISSUE_STAGE(0, 0);
    ISSUE_STAGE(1, KC);

    const uint32_t aRawBase = (uint32_t)((wm + (lid & 15)) * 128 + (lid >> 4) * 16);
    const uint32_t bRawBase = (uint32_t)((wn + (lid & 7) + ((lid >> 4) << 3)) * 128
                                         + (((lid >> 3) & 1) << 4));

    for (int c = 0; c < NC; ++c) {
        if (c + 2 < NC) {
            ISSUE_STAGE((c + 2) % NSTAGE, (c + 2) * KC);
            CPWAIT2();
        } else {
            CPWAIT0();
        }
        __syncthreads();

        const uint32_t st = sbase + (uint32_t)(c % NSTAGE) * STAGE_B;

#pragma unroll
        for (int ks = 0; ks < 4; ks++) {
            const uint32_t kb = (uint32_t)ks * 32;
            uint32_t ah[4][4], al[4][4], bh[4][2], bl[4][2];
#pragma unroll
            for (int i = 0; i < 4; i++) {
                const uint32_t raw = aRawBase + (uint32_t)i * (16 * 128) + kb;
                ldm_x4(ah[i], st + SWZ(raw));
                ldm_x4(al[i], st + 16384u + SWZ(raw));
            }
#pragma unroll
            for (int j2 = 0; j2 < 2; j2++) {
                const uint32_t raw = bRawBase + (uint32_t)j2 * (16 * 128) + kb;
                uint32_t t4[4];
                ldm_x4(t4, st + 32768u + SWZ(raw));
                bh[2 * j2][0] = t4[0]; bh[2 * j2][1] = t4[1];
                bh[2 * j2 + 1][0] = t4[2]; bh[2 * j2 + 1][1] = t4[3];
                ldm_x4(t4, st + 49152u + SWZ(raw));
                bl[2 * j2][0] = t4[0]; bl[2 * j2][1] = t4[1];
                bl[2 * j2 + 1][0] = t4[2]; bl[2 * j2 + 1][1] = t4[3];
            }
#pragma unroll
            for (int i = 0; i < 4; i++)
#pragma unroll
                for (int j = 0; j < 4; j++) {
                    mma16816(acc[i][j], ah[i], bh[j]);
                    mma16816(acc[i][j], ah[i], bl[j]);
                    mma16816(acc[i][j], al[i], bh[j]);
                }
        }
        __syncthreads();
    }
#undef ISSUE_STAGE

    // ---------------- epilogue ----------------
    const int tr = lid >> 2, tc = (lid & 3) * 2;
#pragma unroll
    for (int i = 0; i < 4; i++) {
        const int m1 = m0 + wm + i * 16 + tr;
        const int m2 = m1 + 8;
#pragma unroll
        for (int j = 0; j < 4; j++) {
            const int n = n0 + wn + j * 8 + tc;
            float v0 = acc[i][j][0] * alpha;
            float v1 = acc[i][j][1] * alpha;
            float v2 = acc[i][j][2] * alpha;
            float v3 = acc[i][j][3] * alpha;
            if (epi == E_CAUSAL) {
                if (n     > m1) v0 = -1e10f;
                if (n + 1 > m1) v1 = -1e10f;
                if (n     > m2) v2 = -1e10f;
                if (n + 1 > m2) v3 = -1e10f;
            } else if (epi == E_GELU_SPLIT) {
                const float b0 = bias[n], b1 = bias[n + 1];
                v0 = gelu_f(v0 + b0); v1 = gelu_f(v1 + b1);
                v2 = gelu_f(v2 + b0); v3 = gelu_f(v3 + b1);
            } else if (epi == E_BIASRES) {
                const float b0 = bias[n], b1 = bias[n + 1];
                const float2 r1 = *reinterpret_cast<const float2*>(res + (size_t)m1 * ldres + n);
                const float2 r2 = *reinterpret_cast<const float2*>(res + (size_t)m2 * ldres + n);
                v0 += b0 + r1.x; v1 += b1 + r1.y;
                v2 += b0 + r2.x; v3 += b1 + r2.y;
            }
            if (epi == E_SPLIT || epi == E_GELU_SPLIT) {
                uint32_t hi, lo;
                split2(v0, v1, hi, lo);
                *reinterpret_cast<uint32_t*>(Chi + (size_t)m1 * ldc + n) = hi;
                *reinterpret_cast<uint32_t*>(Clo + (size_t)m1 * ldc + n) = lo;
                split2(v2, v3, hi, lo);
                *reinterpret_cast<uint32_t*>(Chi + (size_t)m2 * ldc + n) = hi;
                *reinterpret_cast<uint32_t*>(Clo + (size_t)m2 * ldc + n) = lo;
            } else {
                *reinterpret_cast<float2*>(C + (size_t)m1 * ldc + n) = make_float2(v0, v1);
                *reinterpret_cast<float2*>(C + (size_t)m2 * ldc + n) = make_float2(v2, v3);
            }
        }
    }
}

// ---------------- launch -----------------------------------------------------
extern "C" void kernel_launch(void* const* d_in, const int* in_sizes, int n_in,
                              void* d_out, int out_size)
{
    const float* x    = (const float*)d_in[0];
    const float* ln_s = (const float*)d_in[1];
    const float* ln_o = (const float*)d_in[2];
    const float* wq   = (const float*)d_in[3];
    const float* wk   = (const float*)d_in[4];
    const float* wv   = (const float*)d_in[5];
    const float* wo   = (const float*)d_in[6];
    const float* w1   = (const float*)d_in[7];
    const float* b1   = (const float*)d_in[8];
    const float* w2   = (const float*)d_in[9];
    const float* b2   = (const float*)d_in[10];
    float* out = (float*)d_out;

    float *qkv, *attn, *sc, *tcs, *tsn;
    bf16 *xnh, *xnl, *qh, *ql, *kh, *kl, *vth, *vtl, *sch, *scl;
    bf16 *cxh, *cxl, *hbh, *hbl;
    bf16 *wqkvh, *wqkvl, *woh, *wol, *w1h, *w1l, *w2h, *w2l;

    cudaGetSymbolAddress((void**)&qkv,  g_qkv);
    cudaGetSymbolAddress((void**)&attn, g_attn);
    cudaGetSymbolAddress((void**)&sc,   g_sc);
    cudaGetSymbolAddress((void**)&tcs,  g_tcos);
    cudaGetSymbolAddress((void**)&tsn,  g_tsin);
    cudaGetSymbolAddress((void**)&xnh,  g_xnh);
    cudaGetSymbolAddress((void**)&xnl,  g_xnl);
    cudaGetSymbolAddress((void**)&qh,   g_qh);
    cudaGetSymbolAddress((void**)&ql,   g_ql);
    cudaGetSymbolAddress((void**)&kh,   g_kh);
    cudaGetSymbolAddress((void**)&kl,   g_kl);
    cudaGetSymbolAddress((void**)&vth,  g_vth);
    cudaGetSymbolAddress((void**)&vtl,  g_vtl);
    cudaGetSymbolAddress((void**)&sch,  g_sch);
    cudaGetSymbolAddress((void**)&scl,  g_scl);
    cudaGetSymbolAddress((void**)&cxh,  g_cxh);
    cudaGetSymbolAddress((void**)&cxl,  g_cxl);
    cudaGetSymbolAddress((void**)&hbh,  g_hbh);
    cudaGetSymbolAddress((void**)&hbl,  g_hbl);
    cudaGetSymbolAddress((void**)&wqkvh, g_wqkvh);
    cudaGetSymbolAddress((void**)&wqkvl, g_wqkvl);
    cudaGetSymbolAddress((void**)&woh,  g_woh);
    cudaGetSymbolAddress((void**)&wol,  g_wol);
    cudaGetSymbolAddress((void**)&w1h,  g_w1h);
    cudaGetSymbolAddress((void**)&w1l,  g_w1l);
    cudaGetSymbolAddress((void**)&w2h,  g_w2h);
    cudaGetSymbolAddress((void**)&w2l,  g_w2l);

    cudaFuncSetAttribute(mma_gemm, cudaFuncAttributeMaxDynamicSharedMemorySize,
                         GEMM_SMEM_BYTES);

    const dim3 tb32(32, 8);

    // 0) RoPE table + weight transpose+split (wq|wk|wv fused rows)
    rope_table_kernel<<<T_, 32>>>(tcs, tsn);
    transpose_split_kernel<<<dim3(D_ / 32, D_ / 32), tb32>>>(wq, wqkvh,              wqkvl,              D_, D_);
    transpose_split_kernel<<<dim3(D_ / 32, D_ / 32), tb32>>>(wk, wqkvh + (size_t)D_ * D_, wqkvl + (size_t)D_ * D_, D_, D_);
    transpose_split_kernel<<<dim3(D_ / 32, D_ / 32), tb32>>>(wv, wqkvh + (size_t)2 * D_ * D_, wqkvl + (size_t)2 * D_ * D_, D_, D_);
    transpose_split_kernel<<<dim3(FF_ / 32, D_ / 32), tb32>>>(w1, w1h, w1l, D_, FF_);
    transpose_split_kernel<<<dim3(D_ / 32, FF_ / 32), tb32>>>(w2, w2h, w2l, FF_, D_);
    transpose_split_kernel<<<dim3(D_ / 32, D_ / 32), tb32>>>(wo, woh, wol, D_, D_);

    // 1) LayerNorm -> xn hi/lo
    ln_split_kernel<<<T_, 256>>>(x, ln_s, ln_o, xnh, xnl);

    // 2) fused QKV projection: [2048,4096] @ [4096,12288] -> g_qkv
    {
        dim3 g(D3_ / NTT, T_ / MT, 1);
        mma_gemm<<<g, 256, GEMM_SMEM_BYTES>>>(D_, 0, xnh, xnl, D_, 0, wqkvh, wqkvl, D_, 0,
            qkv, nullptr, nullptr, D3_, 0, 1.f, E_F32, nullptr, nullptr, 0);
    }

    // 3) RoPE + split q,k
    rope_split_kernel<<<T_, 256>>>(qkv, tcs, tsn, qh, ql, kh, kl);

    // 4) V transpose + split
    transpose_v_split_kernel<<<dim3(DH_ / 32, T_ / 32, H_), tb32>>>(qkv, vth, vtl);

    // 5) scores = scale * Q_h @ K_h^T + causal (fp32)
    {
        dim3 g(T_ / NTT, T_ / MT, H_);
        mma_gemm<<<g, 256, GEMM_SMEM_BYTES>>>(DH_, 0,
            qh, ql, D_, DH_,
            kh, kl, D_, DH_,
            sc, nullptr, nullptr, T_, (long long)T_ * T_,
            0.0625f, E_CAUSAL, nullptr, nullptr, 0);
    }

    // 6) softmax -> P hi/lo
    softmax_split_kernel<<<H_ * T_, 256>>>(sc, sch, scl);

    // 7) ctx = P_h @ V_h  (split out, causal K-limit)
    {
        dim3 g(DH_ / NTT, T_ / MT, H_);
        mma_gemm<<<g, 256, GEMM_SMEM_BYTES>>>(T_, 1,
            sch, scl, T_, (long long)T_ * T_,
            vth, vtl, T_, (long long)DH_ * T_,
            nullptr, cxh, cxl, D_, DH_,
            1.f, E_SPLIT, nullptr, nullptr, 0);
    }

    // 8) attn_out = ctx @ wo (fp32)
    {
        dim3 g(D_ / NTT, T_ / MT, 1);
        mma_gemm<<<g, 256, GEMM_SMEM_BYTES>>>(D_, 0, cxh, cxl, D_, 0, woh, wol, D_, 0,
            attn, nullptr, nullptr, D_, 0, 1.f, E_F32, nullptr, nullptr, 0);
    }

    // 9) h = gelu(xn @ w1 + b1)  (split out)
    {
        dim3 g(FF_ / NTT, T_ / MT, 1);
        mma_gemm<<<g, 256, GEMM_SMEM_BYTES>>>(D_, 0, xnh, xnl, D_, 0, w1h, w1l, D_, 0,
            nullptr, hbh, hbl, FF_, 0, 1.f, E_GELU_SPLIT, b1, nullptr, 0);
    }

    // 10) out = h @ w2 + b2 + attn_out
    {
        dim3 g(D_ / NTT, T_ / MT, 1);
        mma_gemm<<<g, 256, GEMM_SMEM_BYTES>>>(FF_, 0, hbh, hbl, FF_, 0, w2h, w2l, FF_, 0,
            out, nullptr, nullptr, D_, 0, 1.f, E_BIASRES, b2, attn, D_);
    }
}

// round 10
// speedup vs baseline: 1.5407x; 1.3083x over previous
#include <cuda_runtime.h>
#include <cuda_fp16.h>
#include <math.h>
#include <stdint.h>

#define T_  2048
#define D_  4096
#define D3_ 12288
#define H_  16
#define DH_ 256
#define RR_ 64
#define FF_ 16384

// GEMM tiling (R5 proven config)
#define MT   128
#define NTT  128
#define KC   64
#define STAGE_B 65536            // Ah(16K)+Al(16K)+Bh(16K)+Bl(16K)
#define NSTAGE 3
#define GEMM_SMEM_BYTES (NSTAGE * STAGE_B)

typedef __half f16;

// ---------------- scratch (static device arrays: allocation-free) -----------
__device__ float g_qkv [(size_t)T_ * D3_];       // fused q|k|v fp32
__device__ float g_attn[(size_t)T_ * D_];
__device__ float g_sc  [(size_t)H_ * T_ * T_];
__device__ float g_tcos[(size_t)T_ * 32];
__device__ float g_tsin[(size_t)T_ * 32];

__device__ f16 g_xnh [(size_t)T_ * D_];
__device__ f16 g_xnl [(size_t)T_ * D_];
__device__ f16 g_qh  [(size_t)T_ * D_];
__device__ f16 g_ql  [(size_t)T_ * D_];
__device__ f16 g_kh  [(size_t)T_ * D_];
__device__ f16 g_kl  [(size_t)T_ * D_];
__device__ f16 g_vth [(size_t)H_ * DH_ * T_];
__device__ f16 g_vtl [(size_t)H_ * DH_ * T_];
__device__ f16 g_sch [(size_t)H_ * T_ * T_];
__device__ f16 g_scl [(size_t)H_ * T_ * T_];
__device__ f16 g_cxh [(size_t)T_ * D_];
__device__ f16 g_cxl [(size_t)T_ * D_];
__device__ f16 g_hbh [(size_t)T_ * FF_];
__device__ f16 g_hbl [(size_t)T_ * FF_];
__device__ f16 g_wqkvh[(size_t)D3_ * D_];        // fused wq|wk|wv transposed hi
__device__ f16 g_wqkvl[(size_t)D3_ * D_];
__device__ f16 g_woh [(size_t)D_ * D_];
__device__ f16 g_wol [(size_t)D_ * D_];
__device__ f16 g_w1h [(size_t)D_ * FF_];
__device__ f16 g_w1l [(size_t)D_ * FF_];
__device__ f16 g_w2h [(size_t)D_ * FF_];
__device__ f16 g_w2l [(size_t)D_ * FF_];

// ---------------- helpers ----------------------------------------------------
__device__ __forceinline__ uint32_t smem_u32(const void* p) {
    uint32_t a;
    asm("{ .reg .u64 t; cvta.to.shared.u64 t, %1; cvt.u32.u64 %0, t; }"
        : "=r"(a) : "l"(p));
    return a;
}

#define SWZ(o) ((o) ^ (((o) >> 3) & 0x70))

#define CP16(dst, src) \
    asm volatile("cp.async.cg.shared.global [%0], [%1], 16;" \
                 :: "r"(dst), "l"(src))
#define CPCOMMIT() asm volatile("cp.async.commit_group;" ::: "memory")
#define CPWAIT2()  asm volatile("cp.async.wait_group 2;" ::: "memory")
#define CPWAIT0()  asm volatile("cp.async.wait_group 0;" ::: "memory")

__device__ __forceinline__ void ldm_x4(uint32_t* r, uint32_t a) {
    asm volatile("ldmatrix.sync.aligned.m8n8.x4.shared.b16 {%0,%1,%2,%3}, [%4];"
                 : "=r"(r[0]), "=r"(r[1]), "=r"(r[2]), "=r"(r[3]) : "r"(a));
}

__device__ __forceinline__ void mma16816(float* d, const uint32_t* a, const uint32_t* b) {
    asm volatile("mma.sync.aligned.m16n8k16.row.col.f32.f16.f16.f32 "
                 "{%0,%1,%2,%3}, {%4,%5,%6,%7}, {%8,%9}, {%0,%1,%2,%3};"
                 : "+f"(d[0]), "+f"(d[1]), "+f"(d[2]), "+f"(d[3])
                 : "r"(a[0]), "r"(a[1]), "r"(a[2]), "r"(a[3]),
                   "r"(b[0]), "r"(b[1]));
}

// split fp32 pair -> packed fp16x2 hi and lo
__device__ __forceinline__ void split2(float x, float y, uint32_t& hi, uint32_t& lo) {
    f16 hx = __float2half_rn(x);
    f16 hy = __float2half_rn(y);
    float rx = x - __half2float(hx);
    float ry = y - __half2float(hy);
    f16 lx = __float2half_rn(rx);
    f16 ly = __float2half_rn(ry);
    hi = ((uint32_t)__half_as_ushort(hy) << 16) | (uint32_t)__half_as_ushort(hx);
    lo = ((uint32_t)__half_as_ushort(ly) << 16) | (uint32_t)__half_as_ushort(lx);
}

__device__ __forceinline__ float gelu_f(float x)
{
    const float x3 = x * x * x;
    return 0.5f * x * (1.0f + tanhf(0.7978845608028654f * (x + 0.044715f * x3)));
}

// ---------------- RoPE table (double-precision, computed once per launch) ----
__global__ void rope_table_kernel(float* __restrict__ tc, float* __restrict__ ts)
{
    const int t = blockIdx.x;
    const int i = threadIdx.x;          // 0..31
    const double inv = pow(10000.0, -2.0 * (double)i / (double)RR_);
    const double ang = (double)t * inv;
    tc[t * 32 + i] = (float)cos(ang);
    ts[t * 32 + i] = (float)sin(ang);
}

// ---------------- LayerNorm -> split fp16 ------------------------------------
__global__ void ln_split_kernel(const float* __restrict__ x,
                                const float* __restrict__ scale,
                                const float* __restrict__ offset,
                                f16* __restrict__ oh, f16* __restrict__ ol)
{
    const int t = blockIdx.x;
    const float* xr = x + (size_t)t * D_;
    const int base = threadIdx.x * 16;
    __shared__ float red[256];

    float v[16];
#pragma unroll
    for (int i = 0; i < 16; i += 4)
        *reinterpret_cast<float4*>(v + i) =
            *reinterpret_cast<const float4*>(xr + base + i);

    float s = 0.f;
#pragma unroll
    for (int i = 0; i < 16; i++) s += v[i];
    red[threadIdx.x] = s; __syncthreads();
    for (int o = 128; o > 0; o >>= 1) {
        if (threadIdx.x < o) red[threadIdx.x] += red[threadIdx.x + o];
        __syncthreads();
    }
    const float mean = red[0] * (1.0f / D_);
    __syncthreads();

    float vv = 0.f;
#pragma unroll
    for (int i = 0; i < 16; i++) { float d = v[i] - mean; vv += d * d; }
    red[threadIdx.x] = vv; __syncthreads();
    for (int o = 128; o > 0; o >>= 1) {
        if (threadIdx.x < o) red[threadIdx.x] += red[threadIdx.x + o];
        __syncthreads();
    }
    const float rstd = rsqrtf(red[0] * (1.0f / D_) + 1e-5f);

    f16* ohr = oh + (size_t)t * D_ + base;
    f16* olr = ol + (size_t)t * D_ + base;
#pragma unroll
    for (int i = 0; i < 16; i += 2) {
        float y0 = (v[i]     - mean) * rstd * scale[base + i]     + offset[base + i];
        float y1 = (v[i + 1] - mean) * rstd * scale[base + i + 1] + offset[base + i + 1];
        uint32_t hi, lo;
        split2(y0, y1, hi, lo);
        *reinterpret_cast<uint32_t*>(ohr + i) = hi;
        *reinterpret_cast<uint32_t*>(olr + i) = lo;
    }
}

// ---------------- RoPE + split (q, k cols of fused qkv) ----------------------
__global__ void rope_split_kernel(const float* __restrict__ qkv,
                                  const float* __restrict__ tc,
                                  const float* __restrict__ ts,
                                  f16* __restrict__ qh, f16* __restrict__ ql,
                                  f16* __restrict__ kh, f16* __restrict__ kl)
{
    const int t = blockIdx.x;
    const int d0 = threadIdx.x * 16;
    const size_t src = (size_t)t * D3_ + d0;   // q at col 0, k at col D_
    const size_t dst = (size_t)t * D_ + d0;

#pragma unroll
    for (int j = 0; j < 8; j++) {
        const int d = d0 + 2 * j;
        float2 qv = *reinterpret_cast<const float2*>(qkv + src + 2 * j);
        float2 kv = *reinterpret_cast<const float2*>(qkv + src + D_ + 2 * j);
        const int dd = d & (DH_ - 1);
        if (dd < RR_) {
            const int i = dd >> 1;
            const float c = tc[t * 32 + i];
            const float s = ts[t * 32 + i];
            float q0 = qv.x, q1 = qv.y;
            qv.x = q0 * c - q1 * s; qv.y = q1 * c + q0 * s;
            float k0 = kv.x, k1 = kv.y;
            kv.x = k0 * c - k1 * s; kv.y = k1 * c + k0 * s;
        }
        uint32_t hi, lo;
        split2(qv.x, qv.y, hi, lo);
        *reinterpret_cast<uint32_t*>(qh + dst + 2 * j) = hi;
        *reinterpret_cast<uint32_t*>(ql + dst + 2 * j) = lo;
        split2(kv.x, kv.y, hi, lo);
        *reinterpret_cast<uint32_t*>(kh + dst + 2 * j) = hi;
        *reinterpret_cast<uint32_t*>(kl + dst + 2 * j) = lo;
    }
}

// ---------------- softmax (causal-limited) -> split fp16 ---------------------
__global__ void softmax_split_kernel(const float* __restrict__ scores,
                                     f16* __restrict__ ph, f16* __restrict__ pl)
{
    const size_t row = blockIdx.x;
    const int t = (int)(row & (T_ - 1));
    const int L = ((t >> 7) + 1) << 7;          // causal row length, mult of 128
    const float* r = scores + row * (size_t)T_;
    const int base = threadIdx.x * 8;
    const bool act = base < L;                  // 8-blocks fully in or out
    __shared__ float red[256];

    float v[8];
    if (act) {
#pragma unroll
        for (int i = 0; i < 8; i += 4)
            *reinterpret_cast<float4*>(v + i) =
                *reinterpret_cast<const float4*>(r + base + i);
    } else {
#pragma unroll
        for (int i = 0; i < 8; i++) v[i] = -1e30f;
    }

    float m = -1e30f;
#pragma unroll
    for (int i = 0; i < 8; i++) m = fmaxf(m, v[i]);
    red[threadIdx.x] = m; __syncthreads();
    for (int o = 128; o > 0; o >>= 1) {
        if (threadIdx.x < o) red[threadIdx.x] = fmaxf(red[threadIdx.x], red[threadIdx.x + o]);
        __syncthreads();
    }
    m = red[0]; __syncthreads();

    float s = 0.f;
    if (act) {
#pragma unroll
        for (int i = 0; i < 8; i++) { v[i] = __expf(v[i] - m); s += v[i]; }
    }
    red[threadIdx.x] = s; __syncthreads();
    for (int o = 128; o > 0; o >>= 1) {
        if (threadIdx.x < o) red[threadIdx.x] += red[threadIdx.x + o];
        __syncthreads();
    }
    const float invs = 1.0f / red[0];

    if (act) {
        f16* phr = ph + row * (size_t)T_ + base;
        f16* plr = pl + row * (size_t)T_ + base;
#pragma unroll
        for (int i = 0; i < 8; i += 2) {
            uint32_t hi, lo;
            split2(v[i] * invs, v[i + 1] * invs, hi, lo);
            *reinterpret_cast<uint32_t*>(phr + i) = hi;
            *reinterpret_cast<uint32_t*>(plr + i) = lo;
        }
    }
}

// ---------------- transpose + split: in[R][C] fp32 -> out[C][R] fp16 hi/lo ---
__global__ void transpose_split_kernel(const float* __restrict__ in,
                                       f16* __restrict__ oh, f16* __restrict__ ol,
                                       int R, int C)
{
    __shared__ float t[32][33];
    const int c0 = blockIdx.x * 32, r0 = blockIdx.y * 32;
    const int x = threadIdx.x, y = threadIdx.y;
#pragma unroll
    for (int i = 0; i < 32; i += 8)
        t[y + i][x] = in[(size_t)(r0 + y + i) * C + c0 + x];
    __syncthreads();
#pragma unroll
    for (int i = 0; i < 32; i += 8) {
        const float vv = t[x][y + i];
        f16 h = __float2half_rn(vv);
        f16 l = __float2half_rn(vv - __half2float(h));
        const size_t o = (size_t)(c0 + y + i) * R + r0 + x;
        oh[o] = h; ol[o] = l;
    }
}

// per-head transpose+split of V (cols 2D.. of fused qkv): vt[h][d][t]
__global__ void transpose_v_split_kernel(const float* __restrict__ qkv,
                                         f16* __restrict__ oh, f16* __restrict__ ol)
{
    __shared__ float s[32][33];
    const int h = blockIdx.z;
    const int d0 = blockIdx.x * 32, t0 = blockIdx.y * 32;
    const int x = threadIdx.x, y = threadIdx.y;
#pragma unroll
    for (int i = 0; i < 32; i += 8)
        s[y + i][x] = qkv[(size_t)(t0 + y + i) * D3_ + 2 * D_ + (size_t)h * DH_ + d0 + x];
    __syncthreads();
#pragma unroll
    for (int i = 0; i < 32; i += 8) {
        const float vv = s[x][y + i];
        f16 hh = __float2half_rn(vv);
        f16 ll = __float2half_rn(vv - __half2float(hh));
        const size_t o = ((size_t)h * DH_ + d0 + y + i) * T_ + t0 + x;
        oh[o] = hh; ol[o] = ll;
    }
}

// ---------------- split-fp16 mma.sync GEMM (cp.async pipelined) ---------------
// NPROD=3: C = AhBh + AhBl + AlBh.  NPROD=2: C = AhBh + AlBh (Bl never loaded).
// climit != 0: effective K for row-block at m0 is (m0 + MT) (causal PV).
enum { E_F32 = 0, E_CAUSAL = 1, E_SPLIT = 2, E_GELU_SPLIT = 3, E_BIASRES = 4 };

template <int NPROD>
__global__ void __launch_bounds__(256, 1)
mma_gemm(int K, int climit,
         const f16* __restrict__ Ah, const f16* __restrict__ Al,
         int lda, long long sA,
         const f16* __restrict__ Bh, const f16* __restrict__ Bl,
         int ldb, long long sB,
         float* __restrict__ C, f16* __restrict__ Chi, f16* __restrict__ Clo,
         int ldc, long long sC,
         float alpha, int epi,
         const float* __restrict__ bias,
         const float* __restrict__ res, int ldres)
{
    extern __shared__ char smem[];
    const uint32_t sbase = smem_u32(smem);
    const int tid = threadIdx.x;
    const int wid = tid >> 5, lid = tid & 31;
    const int m0 = blockIdx.y * MT, n0 = blockIdx.x * NTT;

    Ah += (size_t)blockIdx.z * sA;
    Al += (size_t)blockIdx.z * sA;
    Bh += (size_t)blockIdx.z * sB;
    if (NPROD == 3) Bl += (size_t)blockIdx.z * sB;
    if (C)   C   += (size_t)blockIdx.z * sC;
    if (Chi) { Chi += (size_t)blockIdx.z * sC; Clo += (size_t)blockIdx.z * sC; }

    // fully-masked causal tile: nothing downstream reads it -> skip entirely
    if (epi == E_CAUSAL && n0 > m0 + (MT - 1)) return;

    const int Keff = climit ? (m0 + MT) : K;   // causal K-limit (multiple of KC)

    const int wm = (wid >> 2) * 64;
    const int wn = (wid & 3) * 32;

    float acc[4][4][4];
#pragma unroll
    for (int i = 0; i < 4; i++)
#pragma unroll
        for (int j = 0; j < 4; j++)
#pragma unroll
            for (int r = 0; r < 4; r++) acc[i][j][r] = 0.f;

    // cp.async chunk assignment: 16B chunks over 256 threads
    const int lrow = tid >> 3;     // 0..31 (plus p*32)
    const int lcol = tid & 7;      // 16B column within 128B row

    const int NC = Keff / KC;

#define ISSUE_STAGE(stg, kc_) do {                                              \
        const int kc__ = (kc_);                                                 \
        _Pragma("unroll")                                                       \
        for (int p = 0; p < 4; p++) {                                           \
            const int row = lrow + p * 32;                                      \
            const uint32_t dsw = SWZ((uint32_t)(row * 128 + lcol * 16));        \
            const uint32_t db = sbase + (uint32_t)(stg) * STAGE_B + dsw;        \
            CP16(db,          Ah + (size_t)(m0 + row) * lda + kc__ + lcol * 8); \
            CP16(db + 16384u, Al + (size_t)(m0 + row) * lda + kc__ + lcol * 8); \
            CP16(db + 32768u, Bh + (size_t)(n0 + row) * ldb + kc__ + lcol * 8); \
            if (NPROD == 3)                                                     \
                CP16(db + 49152u, Bl + (size_t)(n0 + row) * ldb + kc__ + lcol * 8); \
        }                                                                       \
        CPCOMMIT();                                                             \
    } while (0)

    ISSUE_STAGE(0, 0);
    ISSUE_STAGE(1, KC);

    const uint32_t aRawBase = (uint32_t)((wm + (lid & 15)) * 128 + (lid >> 4) * 16);
    const uint32_t bRawBase = (uint32_t)((wn + (lid & 7) + ((lid >> 4) << 3)) * 128
                                         + (((lid >> 3) & 1) << 4));

    for (int c = 0; c < NC; ++c) {
        if (c + 2 < NC) {
            ISSUE_STAGE((c + 2) % NSTAGE, (c + 2) * KC);
            CPWAIT2();
        } else {
            CPWAIT0();
        }
        __syncthreads();

        const uint32_t st = sbase + (uint32_t)(c % NSTAGE) * STAGE_B;

#pragma unroll
        for (int ks = 0; ks < 4; ks++) {
            const uint32_t kb = (uint32_t)ks * 32;
            uint32_t ah[4][4], al[4][4], bh[4][2], bl[4][2];
#pragma unroll
            for (int i = 0; i < 4; i++) {
                const uint32_t raw = aRawBase + (uint32_t)i * (16 * 128) + kb;
                ldm_x4(ah[i], st + SWZ(raw));
                ldm_x4(al[i], st + 16384u + SWZ(raw));
            }
#pragma unroll
            for (int j2 = 0; j2 < 2; j2++) {
                const uint32_t raw = bRawBase + (uint32_t)j2 * (16 * 128) + kb;
                uint32_t t4[4];
                ldm_x4(t4, st + 32768u + SWZ(raw));
                bh[2 * j2][0] = t4[0]; bh[2 * j2][1] = t4[1];
                bh[2 * j2 + 1][0] = t4[2]; bh[2 * j2 + 1][1] = t4[3];
                if (NPROD == 3) {
                    ldm_x4(t4, st + 49152u + SWZ(raw));
                    bl[2 * j2][0] = t4[0]; bl[2 * j2][1] = t4[1];
                    bl[2 * j2 + 1][0] = t4[2]; bl[2 * j2 + 1][1] = t4[3];
                }
            }
#pragma unroll
            for (int i = 0; i < 4; i++)
#pragma unroll
                for (int j = 0; j < 4; j++) {
                    mma16816(acc[i][j], ah[i], bh[j]);
                    mma16816(acc[i][j], al[i], bh[j]);
                    if (NPROD == 3) mma16816(acc[i][j], ah[i], bl[j]);
                }
        }
        __syncthreads();
    }
#undef ISSUE_STAGE

    // ---------------- epilogue ----------------
    const int tr = lid >> 2, tc = (lid & 3) * 2;
#pragma unroll
    for (int i = 0; i < 4; i++) {
        const int m1 = m0 + wm + i * 16 + tr;
        const int m2 = m1 + 8;
#pragma unroll
        for (int j = 0; j < 4; j++) {
            const int n = n0 + wn + j * 8 + tc;
            float v0 = acc[i][j][0] * alpha;
            float v1 = acc[i][j][1] * alpha;
            float v2 = acc[i][j][2] * alpha;
            float v3 = acc[i][j][3] * alpha;
            if (epi == E_CAUSAL) {
                if (n     > m1) v0 = -1e10f;
                if (n + 1 > m1) v1 = -1e10f;
                if (n     > m2) v2 = -1e10f;
                if (n + 1 > m2) v3 = -1e10f;
            } else if (epi == E_GELU_SPLIT) {
                const float b0 = bias[n], b1 = bias[n + 1];
                v0 = gelu_f(v0 + b0); v1 = gelu_f(v1 + b1);
                v2 = gelu_f(v2 + b0); v3 = gelu_f(v3 + b1);
            } else if (epi == E_BIASRES) {
                const float b0 = bias[n], b1 = bias[n + 1];
                const float2 r1 = *reinterpret_cast<const float2*>(res + (size_t)m1 * ldres + n);
                const float2 r2 = *reinterpret_cast<const float2*>(res + (size_t)m2 * ldres + n);
                v0 += b0 + r1.x; v1 += b1 + r1.y;
                v2 += b0 + r2.x; v3 += b1 + r2.y;
            }
            if (epi == E_SPLIT || epi == E_GELU_SPLIT) {
                uint32_t hi, lo;
                split2(v0, v1, hi, lo);
                *reinterpret_cast<uint32_t*>(Chi + (size_t)m1 * ldc + n) = hi;
                *reinterpret_cast<uint32_t*>(Clo + (size_t)m1 * ldc + n) = lo;
                split2(v2, v3, hi, lo);
                *reinterpret_cast<uint32_t*>(Chi + (size_t)m2 * ldc + n) = hi;
                *reinterpret_cast<uint32_t*>(Clo + (size_t)m2 * ldc + n) = lo;
            } else {
                *reinterpret_cast<float2*>(C + (size_t)m1 * ldc + n) = make_float2(v0, v1);
                *reinterpret_cast<float2*>(C + (size_t)m2 * ldc + n) = make_float2(v2, v3);
            }
        }
    }
}

// ---------------- launch -----------------------------------------------------
extern "C" void kernel_launch(void* const* d_in, const int* in_sizes, int n_in,
                              void* d_out, int out_size)
{
    const float* x    = (const float*)d_in[0];
    const float* ln_s = (const float*)d_in[1];
    const float* ln_o = (const float*)d_in[2];
    const float* wq   = (const float*)d_in[3];
    const float* wk   = (const float*)d_in[4];
    const float* wv   = (const float*)d_in[5];
    const float* wo   = (const float*)d_in[6];
    const float* w1   = (const float*)d_in[7];
    const float* b1   = (const float*)d_in[8];
    const float* w2   = (const float*)d_in[9];
    const float* b2   = (const float*)d_in[10];
    float* out = (float*)d_out;

    float *qkv, *attn, *sc, *tcs, *tsn;
    f16 *xnh, *xnl, *qh, *ql, *kh, *kl, *vth, *vtl, *sch, *scl;
    f16 *cxh, *cxl, *hbh, *hbl;
    f16 *wqkvh, *wqkvl, *woh, *wol, *w1h, *w1l, *w2h, *w2l;

    cudaGetSymbolAddress((void**)&qkv,  g_qkv);
    cudaGetSymbolAddress((void**)&attn, g_attn);
    cudaGetSymbolAddress((void**)&sc,   g_sc);
    cudaGetSymbolAddress((void**)&tcs,  g_tcos);
    cudaGetSymbolAddress((void**)&tsn,  g_tsin);
    cudaGetSymbolAddress((void**)&xnh,  g_xnh);
    cudaGetSymbolAddress((void**)&xnl,  g_xnl);
    cudaGetSymbolAddress((void**)&qh,   g_qh);
    cudaGetSymbolAddress((void**)&ql,   g_ql);
    cudaGetSymbolAddress((void**)&kh,   g_kh);
    cudaGetSymbolAddress((void**)&kl,   g_kl);
    cudaGetSymbolAddress((void**)&vth,  g_vth);
    cudaGetSymbolAddress((void**)&vtl,  g_vtl);
    cudaGetSymbolAddress((void**)&sch,  g_sch);
    cudaGetSymbolAddress((void**)&scl,  g_scl);
    cudaGetSymbolAddress((void**)&cxh,  g_cxh);
    cudaGetSymbolAddress((void**)&cxl,  g_cxl);
    cudaGetSymbolAddress((void**)&hbh,  g_hbh);
    cudaGetSymbolAddress((void**)&hbl,  g_hbl);
    cudaGetSymbolAddress((void**)&wqkvh, g_wqkvh);
    cudaGetSymbolAddress((void**)&wqkvl, g_wqkvl);
    cudaGetSymbolAddress((void**)&woh,  g_woh);
    cudaGetSymbolAddress((void**)&wol,  g_wol);
    cudaGetSymbolAddress((void**)&w1h,  g_w1h);
    cudaGetSymbolAddress((void**)&w1l,  g_w1l);
    cudaGetSymbolAddress((void**)&w2h,  g_w2h);
    cudaGetSymbolAddress((void**)&w2l,  g_w2l);

    cudaFuncSetAttribute(mma_gemm<3>, cudaFuncAttributeMaxDynamicSharedMemorySize,
                         GEMM_SMEM_BYTES);
    cudaFuncSetAttribute(mma_gemm<2>, cudaFuncAttributeMaxDynamicSharedMemorySize,
                         GEMM_SMEM_BYTES);

    const dim3 tb32(32, 8);

    // 0) RoPE table + weight transpose+split (wq|wk|wv fused rows)
    rope_table_kernel<<<T_, 32>>>(tcs, tsn);
    transpose_split_kernel<<<dim3(D_ / 32, D_ / 32), tb32>>>(wq, wqkvh,              wqkvl,              D_, D_);
    transpose_split_kernel<<<dim3(D_ / 32, D_ / 32), tb32>>>(wk, wqkvh + (size_t)D_ * D_, wqkvl + (size_t)D_ * D_, D_, D_);
    transpose_split_kernel<<<dim3(D_ / 32, D_ / 32), tb32>>>(wv, wqkvh + (size_t)2 * D_ * D_, wqkvl + (size_t)2 * D_ * D_, D_, D_);
    transpose_split_kernel<<<dim3(FF_ / 32, D_ / 32), tb32>>>(w1, w1h, w1l, D_, FF_);
    transpose_split_kernel<<<dim3(D_ / 32, FF_ / 32), tb32>>>(w2, w2h, w2l, FF_, D_);
    transpose_split_kernel<<<dim3(D_ / 32, D_ / 32), tb32>>>(wo, woh, wol, D_, D_);

    // 1) LayerNorm -> xn hi/lo
    ln_split_kernel<<<T_, 256>>>(x, ln_s, ln_o, xnh, xnl);

    // 2) fused QKV projection (3-product): [2048,4096]@[4096,12288]
    {
        dim3 g(D3_ / NTT, T_ / MT, 1);
        mma_gemm<3><<<g, 256, GEMM_SMEM_BYTES>>>(D_, 0, xnh, xnl, D_, 0, wqkvh, wqkvl, D_, 0,
            qkv, nullptr, nullptr, D3_, 0, 1.f, E_F32, nullptr, nullptr, 0);
    }

    // 3) RoPE + split q,k
    rope_split_kernel<<<T_, 256>>>(qkv, tcs, tsn, qh, ql, kh, kl);

    // 4) V transpose + split
    transpose_v_split_kernel<<<dim3(DH_ / 32, T_ / 32, H_), tb32>>>(qkv, vth, vtl);

    // 5) scores = scale * Q_h @ K_h^T + causal (3-product, masked tiles skipped)
    {
        dim3 g(T_ / NTT, T_ / MT, H_);
        mma_gemm<3><<<g, 256, GEMM_SMEM_BYTES>>>(DH_, 0,
            qh, ql, D_, DH_,
            kh, kl, D_, DH_,
            sc, nullptr, nullptr, T_, (long long)T_ * T_,
            0.0625f, E_CAUSAL, nullptr, nullptr, 0);
    }

    // 6) softmax (causal length) -> P hi/lo
    softmax_split_kernel<<<H_ * T_, 256>>>(sc, sch, scl);

    // 7) ctx = P_h @ V_h  (2-product, causal K-limit)
    {
        dim3 g(DH_ / NTT, T_ / MT, H_);
        mma_gemm<2><<<g, 256, GEMM_SMEM_BYTES>>>(T_, 1,
            sch, scl, T_, (long long)T_ * T_,
            vth, vtl, T_, (long long)DH_ * T_,
            nullptr, cxh, cxl, D_, DH_,
            1.f, E_SPLIT, nullptr, nullptr, 0);
    }

    // 8) attn_out = ctx @ wo (2-product)
    {
        dim3 g(D_ / NTT, T_ / MT, 1);
        mma_gemm<2><<<g, 256, GEMM_SMEM_BYTES>>>(D_, 0, cxh, cxl, D_, 0, woh, wol, D_, 0,
            attn, nullptr, nullptr, D_, 0, 1.f, E_F32, nullptr, nullptr, 0);
    }

    // 9) h = gelu(xn @ w1 + b1)  (2-product, split out)
    {
        dim3 g(FF_ / NTT, T_ / MT, 1);
        mma_gemm<2><<<g, 256, GEMM_SMEM_BYTES>>>(D_, 0, xnh, xnl, D_, 0, w1h, w1l, D_, 0,
            nullptr, hbh, hbl, FF_, 0, 1.f, E_GELU_SPLIT, b1, nullptr, 0);
    }

    // 10) out = h @ w2 + b2 + attn_out (2-product)
    {
        dim3 g(D_ / NTT, T_ / MT, 1);
        mma_gemm<2><<<g, 256, GEMM_SMEM_BYTES>>>(FF_, 0, hbh, hbl, FF_, 0, w2h, w2l, FF_, 0,
            out, nullptr, nullptr, D_, 0, 1.f, E_BIASRES, b2, attn, D_);
    }
}

// round 12
// speedup vs baseline: 1.7479x; 1.1345x over previous
#include <cuda_runtime.h>
#include <cuda_fp16.h>
#include <math.h>
#include <stdint.h>

#define T_  2048
#define D_  4096
#define D3_ 12288
#define H_  16
#define DH_ 256
#define RR_ 64
#define FF_ 16384

// GEMM tiling — 2-product stages: Ah(16K)+Al(16K)+Bh(16K)
#define MT   128
#define NTT  128
#define KC   64
#define STAGE_B 49152
#define NSTAGE 3
#define GEMM_SMEM_BYTES (NSTAGE * STAGE_B)   // 144KB

typedef __half f16;

// ---------------- scratch (static device arrays: allocation-free) -----------
__device__ float g_qkv [(size_t)T_ * D3_];       // fused q|k|v fp32
__device__ float g_attn[(size_t)T_ * D_];
__device__ float g_sc  [(size_t)H_ * T_ * T_];
__device__ float g_tcos[(size_t)T_ * 32];
__device__ float g_tsin[(size_t)T_ * 32];

__device__ f16 g_xnh [(size_t)T_ * D_];
__device__ f16 g_xnl [(size_t)T_ * D_];
__device__ f16 g_qh  [(size_t)T_ * D_];
__device__ f16 g_ql  [(size_t)T_ * D_];
__device__ f16 g_kh  [(size_t)T_ * D_];
__device__ f16 g_vth [(size_t)H_ * DH_ * T_];
__device__ f16 g_sch [(size_t)H_ * T_ * T_];
__device__ f16 g_scl [(size_t)H_ * T_ * T_];
__device__ f16 g_cxh [(size_t)T_ * D_];
__device__ f16 g_cxl [(size_t)T_ * D_];
__device__ f16 g_hbh [(size_t)T_ * FF_];
__device__ f16 g_hbl [(size_t)T_ * FF_];
__device__ f16 g_wqkvh[(size_t)D3_ * D_];        // fused wq|wk|wv transposed hi
__device__ f16 g_woh [(size_t)D_ * D_];
__device__ f16 g_w1h [(size_t)FF_ * D_];         // [FF][D], row stride D
__device__ f16 g_w2h [(size_t)D_ * FF_];         // [D][FF], row stride FF
// ---------------- helpers ----------------------------------------------------
__device__ __forceinline__ uint32_t smem_u32(const void* p) {
    uint32_t a;
    asm("{ .reg .u64 t; cvta.to.shared.u64 t, %1; cvt.u32.u64 %0, t; }"
        : "=r"(a) : "l"(p));
    return a;
}

#define SWZ(o) ((o) ^ (((o) >> 3) & 0x70))

#define CP16(dst, src) \
    asm volatile("cp.async.cg.shared.global [%0], [%1], 16;" \
                 :: "r"(dst), "l"(src))
#define CPCOMMIT() asm volatile("cp.async.commit_group;" ::: "memory")
#define CPWAIT2()  asm volatile("cp.async.wait_group 2;" ::: "memory")
#define CPWAIT0()  asm volatile("cp.async.wait_group 0;" ::: "memory")

__device__ __forceinline__ void ldm_x4(uint32_t* r, uint32_t a) {
    asm volatile("ldmatrix.sync.aligned.m8n8.x4.shared.b16 {%0,%1,%2,%3}, [%4];"
                 : "=r"(r[0]), "=r"(r[1]), "=r"(r[2]), "=r"(r[3]) : "r"(a));
}

__device__ __forceinline__ void mma16816(float* d, const uint32_t* a, const uint32_t* b) {
    asm volatile("mma.sync.aligned.m16n8k16.row.col.f32.f16.f16.f32 "
                 "{%0,%1,%2,%3}, {%4,%5,%6,%7}, {%8,%9}, {%0,%1,%2,%3};"
                 : "+f"(d[0]), "+f"(d[1]), "+f"(d[2]), "+f"(d[3])
                 : "r"(a[0]), "r"(a[1]), "r"(a[2]), "r"(a[3]),
                   "r"(b[0]), "r"(b[1]));
}

// split fp32 pair -> packed fp16x2 hi and lo
__device__ __forceinline__ void split2(float x, float y, uint32_t& hi, uint32_t& lo) {
    f16 hx = __float2half_rn(x);
    f16 hy = __float2half_rn(y);
    float rx = x - __half2float(hx);
    float ry = y - __half2float(hy);
    f16 lx = __float2half_rn(rx);
    f16 ly = __float2half_rn(ry);
    hi = ((uint32_t)__half_as_ushort(hy) << 16) | (uint32_t)__half_as_ushort(hx);
    lo = ((uint32_t)__half_as_ushort(ly) << 16) | (uint32_t)__half_as_ushort(lx);
}

__device__ __forceinline__ uint32_t pack_hi2(float x, float y) {
    f16 hx = __float2half_rn(x);
    f16 hy = __float2half_rn(y);
    return ((uint32_t)__half_as_ushort(hy) << 16) | (uint32_t)__half_as_ushort(hx);
}

__device__ __forceinline__ float gelu_f(float x)
{
    const float x3 = x * x * x;
    return 0.5f * x * (1.0f + tanhf(0.7978845608028654f * (x + 0.044715f * x3)));
}

// ---------------- RoPE table (double-precision, computed once per launch) ----
__global__ void rope_table_kernel(float* __restrict__ tc, float* __restrict__ ts)
{
    const int t = blockIdx.x;
    const int i = threadIdx.x;          // 0..31
    const double inv = pow(10000.0, -2.0 * (double)i / (double)RR_);
    const double ang = (double)t * inv;
    tc[t * 32 + i] = (float)cos(ang);
    ts[t * 32 + i] = (float)sin(ang);
}

// ---------------- LayerNorm -> split fp16 ------------------------------------
__global__ void ln_split_kernel(const float* __restrict__ x,
                                const float* __restrict__ scale,
                                const float* __restrict__ offset,
                                f16* __restrict__ oh, f16* __restrict__ ol)
{
    const int t = blockIdx.x;
    const float* xr = x + (size_t)t * D_;
    const int base = threadIdx.x * 16;
    __shared__ float red[256];

    float v[16];
#pragma unroll
    for (int i = 0; i < 16; i += 4)
        *reinterpret_cast<float4*>(v + i) =
            *reinterpret_cast<const float4*>(xr + base + i);

    float s = 0.f;
#pragma unroll
    for (int i = 0; i < 16; i++) s += v[i];
    red[threadIdx.x] = s; __syncthreads();
    for (int o = 128; o > 0; o >>= 1) {
        if (threadIdx.x < o) red[threadIdx.x] += red[threadIdx.x + o];
        __syncthreads();
    }
    const float mean = red[0] * (1.0f / D_);
    __syncthreads();

    float vv = 0.f;
#pragma unroll
    for (int i = 0; i < 16; i++) { float d = v[i] - mean; vv += d * d; }
    red[threadIdx.x] = vv; __syncthreads();
    for (int o = 128; o > 0; o >>= 1) {
        if (threadIdx.x < o) red[threadIdx.x] += red[threadIdx.x + o];
        __syncthreads();
    }
    const float rstd = rsqrtf(red[0] * (1.0f / D_) + 1e-5f);

    f16* ohr = oh + (size_t)t * D_ + base;
    f16* olr = ol + (size_t)t * D_ + base;
#pragma unroll
    for (int i = 0; i < 16; i += 2) {
        float y0 = (v[i]     - mean) * rstd * scale[base + i]     + offset[base + i];
        float y1 = (v[i + 1] - mean) * rstd * scale[base + i + 1] + offset[base + i + 1];
        uint32_t hi, lo;
        split2(y0, y1, hi, lo);
        *reinterpret_cast<uint32_t*>(ohr + i) = hi;
        *reinterpret_cast<uint32_t*>(olr + i) = lo;
    }
}

// ---------------- RoPE + split q (hi/lo), k (hi only) ------------------------
__global__ void rope_split_kernel(const float* __restrict__ qkv,
                                  const float* __restrict__ tc,
                                  const float* __restrict__ ts,
                                  f16* __restrict__ qh, f16* __restrict__ ql,
                                  f16* __restrict__ kh)
{
    const int t = blockIdx.x;
    const int d0 = threadIdx.x * 16;
    const size_t src = (size_t)t * D3_ + d0;   // q at col 0, k at col D_
    const size_t dst = (size_t)t * D_ + d0;

#pragma unroll
    for (int j = 0; j < 8; j++) {
        const int d = d0 + 2 * j;
        float2 qv = *reinterpret_cast<const float2*>(qkv + src + 2 * j);
        float2 kv = *reinterpret_cast<const float2*>(qkv + src + D_ + 2 * j);
        const int dd = d & (DH_ - 1);
        if (dd < RR_) {
            const int i = dd >> 1;
            const float c = tc[t * 32 + i];
            const float s = ts[t * 32 + i];
            float q0 = qv.x, q1 = qv.y;
            qv.x = q0 * c - q1 * s; qv.y = q1 * c + q0 * s;
            float k0 = kv.x, k1 = kv.y;
            kv.x = k0 * c - k1 * s; kv.y = k1 * c + k0 * s;
        }
        uint32_t hi, lo;
        split2(qv.x, qv.y, hi, lo);
        *reinterpret_cast<uint32_t*>(qh + dst + 2 * j) = hi;
        *reinterpret_cast<uint32_t*>(ql + dst + 2 * j) = lo;
        *reinterpret_cast<uint32_t*>(kh + dst + 2 * j) = pack_hi2(kv.x, kv.y);
    }
}

// ---------------- softmax (causal-limited) -> split fp16 ---------------------
__global__ void softmax_split_kernel(const float* __restrict__ scores,
                                     f16* __restrict__ ph, f16* __restrict__ pl)
{
    const size_t row = blockIdx.x;
    const int t = (int)(row & (T_ - 1));
    const int L = ((t >> 7) + 1) << 7;          // causal row length, mult of 128
    const float* r = scores + row * (size_t)T_;
    const int base = threadIdx.x * 8;
    const bool act = base < L;                  // 8-blocks fully in or out
    __shared__ float red[256];

    float v[8];
    if (act) {
#pragma unroll
        for (int i = 0; i < 8; i += 4)
            *reinterpret_cast<float4*>(v + i) =
                *reinterpret_cast<const float4*>(r + base + i);
    } else {
#pragma unroll
        for (int i = 0; i < 8; i++) v[i] = -1e30f;
    }

    float m = -1e30f;
#pragma unroll
    for (int i = 0; i < 8; i++) m = fmaxf(m, v[i]);
    red[threadIdx.x] = m; __syncthreads();
    for (int o = 128; o > 0; o >>= 1) {
        if (threadIdx.x < o) red[threadIdx.x] = fmaxf(red[threadIdx.x], red[threadIdx.x + o]);
        __syncthreads();
    }
    m = red[0]; __syncthreads();

    float s = 0.f;
    if (act) {
#pragma unroll
        for (int i = 0; i < 8; i++) { v[i] = __expf(v[i] - m); s += v[i]; }
    }
    red[threadIdx.x] = s; __syncthreads();
    for (int o = 128; o > 0; o >>= 1) {
        if (threadIdx.x < o) red[threadIdx.x] += red[threadIdx.x + o];
        __syncthreads();
    }
    const float invs = 1.0f / red[0];

    if (act) {
        f16* phr = ph + row * (size_t)T_ + base;
        f16* plr = pl + row * (size_t)T_ + base;
#pragma unroll
        for (int i = 0; i < 8; i += 2) {
            uint32_t hi, lo;
            split2(v[i] * invs, v[i + 1] * invs, hi, lo);
            *reinterpret_cast<uint32_t*>(phr + i) = hi;
            *reinterpret_cast<uint32_t*>(plr + i) = lo;
        }
    }
}

// ---------------- transpose: in[R][C] fp32 -> out[C][R] fp16 hi only ---------
__global__ void transpose_hi_kernel(const float* __restrict__ in,
                                    f16* __restrict__ oh, int R, int C)
{
    __shared__ float t[32][33];
    const int c0 = blockIdx.x * 32, r0 = blockIdx.y * 32;
    const int x = threadIdx.x, y = threadIdx.y;
#pragma unroll
    for (int i = 0; i < 32; i += 8)
        t[y + i][x] = in[(size_t)(r0 + y + i) * C + c0 + x];
    __syncthreads();
#pragma unroll
    for (int i = 0; i < 32; i += 8) {
        const size_t o = (size_t)(c0 + y + i) * R + r0 + x;
        oh[o] = __float2half_rn(t[x][y + i]);
    }
}

// per-head transpose of V (cols 2D.. of fused qkv): vt[h][d][t], hi only
__global__ void transpose_v_hi_kernel(const float* __restrict__ qkv,
                                      f16* __restrict__ oh)
{
    __shared__ float s[32][33];
    const int h = blockIdx.z;
    const int d0 = blockIdx.x * 32, t0 = blockIdx.y * 32;
    const int x = threadIdx.x, y = threadIdx.y;
#pragma unroll
    for (int i = 0; i < 32; i += 8)
        s[y + i][x] = qkv[(size_t)(t0 + y + i) * D3_ + 2 * D_ + (size_t)h * DH_ + d0 + x];
    __syncthreads();
#pragma unroll
    for (int i = 0; i < 32; i += 8) {
        const size_t o = ((size_t)h * DH_ + d0 + y + i) * T_ + t0 + x;
        oh[o] = __float2half_rn(s[x][y + i]);
    }
}

// ---------------- 2-product split-fp16 GEMM: C = (Ah + Al) @ Bh^T ------------
// climit != 0: effective K for row-block at m0 is (m0 + MT) (causal PV).
enum { E_F32 = 0, E_CAUSAL = 1, E_SPLIT = 2, E_GELU_SPLIT = 3, E_BIASRES = 4 };

__global__ void __launch_bounds__(256, 1)
mma_gemm(int K, int climit,
         const f16* __restrict__ Ah, const f16* __restrict__ Al,
         int lda, long long sA,
         const f16* __restrict__ Bh, int ldb, long long sB,
         float* __restrict__ C, f16* __restrict__ Chi, f16* __restrict__ Clo,
         int ldc, long long sC,
         float alpha, int epi,
         const float* __restrict__ bias,
         const float* __restrict__ res, int ldres)
{
    extern __shared__ char smem[];
    const uint32_t sbase = smem_u32(smem);
    const int tid = threadIdx.x;
    const int wid = tid >> 5, lid = tid & 31;
    const int m0 = blockIdx.y * MT, n0 = blockIdx.x * NTT;

    Ah += (size_t)blockIdx.z * sA;
    Al += (size_t)blockIdx.z * sA;
    Bh += (size_t)blockIdx.z * sB;
    if (C)   C   += (size_t)blockIdx.z * sC;
    if (Chi) { Chi += (size_t)blockIdx.z * sC; Clo += (size_t)blockIdx.z * sC; }

    // fully-masked causal tile: nothing downstream reads it -> skip entirely
    if (epi == E_CAUSAL && n0 > m0 + (MT - 1)) return;

    const int Keff = climit ? (m0 + MT) : K;   // causal K-limit (multiple of KC)

    const int wm = (wid >> 2) * 64;
    const int wn = (wid & 3) * 32;

    float acc[4][4][4];
#pragma unroll
    for (int i = 0; i < 4; i++)
#pragma unroll
        for (int j = 0; j < 4; j++)
#pragma unroll
            for (int r = 0; r < 4; r++) acc[i][j][r] = 0.f;

    const int lrow = tid >> 3;     // 0..31 (plus p*32)
    const int lcol = tid & 7;      // 16B column within 128B row

    const int NC = Keff / KC;

#define ISSUE_STAGE(stg, kc_) do {                                              \
        const int kc__ = (kc_);                                                 \
        _Pragma("unroll")                                                       \
        for (int p = 0; p < 4; p++) {                                           \
            const int row = lrow + p * 32;                                      \
            const uint32_t dsw = SWZ((uint32_t)(row * 128 + lcol * 16));        \
            const uint32_t db = sbase + (uint32_t)(stg) * STAGE_B + dsw;        \
            CP16(db,          Ah + (size_t)(m0 + row) * lda + kc__ + lcol * 8); \
            CP16(db + 16384u, Al + (size_t)(m0 + row) * lda + kc__ + lcol * 8); \
            CP16(db + 32768u, Bh + (size_t)(n0 + row) * ldb + kc__ + lcol * 8); \
        }                                                                       \
        CPCOMMIT();                                                             \
    } while (0)

    ISSUE_STAGE(0, 0);
    ISSUE_STAGE(1, KC);

    const uint32_t aRawBase = (uint32_t)((wm + (lid & 15)) * 128 + (lid >> 4) * 16);
    const uint32_t bRawBase = (uint32_t)((wn + (lid & 7) + ((lid >> 4) << 3)) * 128
                                         + (((lid >> 3) & 1) << 4));

    for (int c = 0; c < NC; ++c) {
        if (c + 2 < NC) {
            ISSUE_STAGE((c + 2) % NSTAGE, (c + 2) * KC);
            CPWAIT2();
        } else {
            CPWAIT0();
        }
        __syncthreads();

        const uint32_t st = sbase + (uint32_t)(c % NSTAGE) * STAGE_B;

#pragma unroll
        for (int ks = 0; ks < 4; ks++) {
            const uint32_t kb = (uint32_t)ks * 32;
            uint32_t ah[4][4], al[4][4], bh[4][2];
#pragma unroll
            for (int i = 0; i < 4; i++) {
                const uint32_t raw = aRawBase + (uint32_t)i * (16 * 128) + kb;
                ldm_x4(ah[i], st + SWZ(raw));
                ldm_x4(al[i], st + 16384u + SWZ(raw));
            }
#pragma unroll
            for (int j2 = 0; j2 < 2; j2++) {
                const uint32_t raw = bRawBase + (uint32_t)j2 * (16 * 128) + kb;
                uint32_t t4[4];
                ldm_x4(t4, st + 32768u + SWZ(raw));
                bh[2 * j2][0] = t4[0]; bh[2 * j2][1] = t4[1];
                bh[2 * j2 + 1][0] = t4[2]; bh[2 * j2 + 1][1] = t4[3];
            }
#pragma unroll
            for (int i = 0; i < 4; i++)
#pragma unroll
                for (int j = 0; j < 4; j++) {
                    mma16816(acc[i][j], ah[i], bh[j]);
                    mma16816(acc[i][j], al[i], bh[j]);
                }
        }
        __syncthreads();
    }
#undef ISSUE_STAGE

    // ---------------- epilogue ----------------
    const int tr = lid >> 2, tc = (lid & 3) * 2;
#pragma unroll
    for (int i = 0; i < 4; i++) {
        const int m1 = m0 + wm + i * 16 + tr;
        const int m2 = m1 + 8;
#pragma unroll
        for (int j = 0; j < 4; j++) {
            const int n = n0 + wn + j * 8 + tc;
            float v0 = acc[i][j][0] * alpha;
            float v1 = acc[i][j][1] * alpha;
            float v2 = acc[i][j][2] * alpha;
            float v3 = acc[i][j][3] * alpha;
            if (epi == E_CAUSAL) {
                if (n     > m1) v0 = -1e10f;
                if (n + 1 > m1) v1 = -1e10f;
                if (n     > m2) v2 = -1e10f;
                if (n + 1 > m2) v3 = -1e10f;
            } else if (epi == E_GELU_SPLIT) {
                const float b0 = bias[n], b1 = bias[n + 1];
                v0 = gelu_f(v0 + b0); v1 = gelu_f(v1 + b1);
                v2 = gelu_f(v2 + b0); v3 = gelu_f(v3 + b1);
            } else if (epi == E_BIASRES) {
                const float b0 = bias[n], b1 = bias[n + 1];
                const float2 r1 = *reinterpret_cast<const float2*>(res + (size_t)m1 * ldres + n);
                const float2 r2 = *reinterpret_cast<const float2*>(res + (size_t)m2 * ldres + n);
                v0 += b0 + r1.x; v1 += b1 + r1.y;
                v2 += b0 + r2.x; v3 += b1 + r2.y;
            }
            if (epi == E_SPLIT || epi == E_GELU_SPLIT) {
                uint32_t hi, lo;
                split2(v0, v1, hi, lo);
                *reinterpret_cast<uint32_t*>(Chi + (size_t)m1 * ldc + n) = hi;
                *reinterpret_cast<uint32_t*>(Clo + (size_t)m1 * ldc + n) = lo;
                split2(v2, v3, hi, lo);
                *reinterpret_cast<uint32_t*>(Chi + (size_t)m2 * ldc + n) = hi;
                *reinterpret_cast<uint32_t*>(Clo + (size_t)m2 * ldc + n) = lo;
            } else {
                *reinterpret_cast<float2*>(C + (size_t)m1 * ldc + n) = make_float2(v0, v1);
                *reinterpret_cast<float2*>(C + (size_t)m2 * ldc + n) = make_float2(v2, v3);
            }
        }
    }
}

// ---------------- launch -----------------------------------------------------
extern "C" void kernel_launch(void* const* d_in, const int* in_sizes, int n_in,
                              void* d_out, int out_size)
{
    const float* x    = (const float*)d_in[0];
    const float* ln_s = (const float*)d_in[1];
    const float* ln_o = (const float*)d_in[2];
    const float* wq   = (const float*)d_in[3];
    const float* wk   = (const float*)d_in[4];
    const float* wv   = (const float*)d_in[5];
    const float* wo   = (const float*)d_in[6];
    const float* w1   = (const float*)d_in[7];
    const float* b1   = (const float*)d_in[8];
    const float* w2   = (const float*)d_in[9];
    const float* b2   = (const float*)d_in[10];
    float* out = (float*)d_out;

    float *qkv, *attn, *sc, *tcs, *tsn;
    f16 *xnh, *xnl, *qh, *ql, *kh, *vth, *sch, *scl;
    f16 *cxh, *cxl, *hbh, *hbl;
    f16 *wqkvh, *woh, *w1h, *w2h;

    cudaGetSymbolAddress((void**)&qkv,  g_qkv);
    cudaGetSymbolAddress((void**)&attn, g_attn);
    cudaGetSymbolAddress((void**)&sc,   g_sc);
    cudaGetSymbolAddress((void**)&tcs,  g_tcos);
    cudaGetSymbolAddress((void**)&tsn,  g_tsin);
    cudaGetSymbolAddress((void**)&xnh,  g_xnh);
    cudaGetSymbolAddress((void**)&xnl,  g_xnl);
    cudaGetSymbolAddress((void**)&qh,   g_qh);
    cudaGetSymbolAddress((void**)&ql,   g_ql);
    cudaGetSymbolAddress((void**)&kh,   g_kh);
    cudaGetSymbolAddress((void**)&vth,  g_vth);
    cudaGetSymbolAddress((void**)&sch,  g_sch);
    cudaGetSymbolAddress((void**)&scl,  g_scl);
    cudaGetSymbolAddress((void**)&cxh,  g_cxh);
    cudaGetSymbolAddress((void**)&cxl,  g_cxl);
    cudaGetSymbolAddress((void**)&hbh,  g_hbh);
    cudaGetSymbolAddress((void**)&hbl,  g_hbl);
    cudaGetSymbolAddress((void**)&wqkvh, g_wqkvh);
    cudaGetSymbolAddress((void**)&woh,  g_woh);
    cudaGetSymbolAddress((void**)&w1h,  g_w1h);
    cudaGetSymbolAddress((void**)&w2h,  g_w2h);

    cudaFuncSetAttribute(mma_gemm, cudaFuncAttributeMaxDynamicSharedMemorySize,
                         GEMM_SMEM_BYTES);

    const dim3 tb32(32, 8);

    // 0) RoPE table + weight transposes (hi only; lo planes never read)
    rope_table_kernel<<<T_, 32>>>(tcs, tsn);
    transpose_hi_kernel<<<dim3(D_ / 32, D_ / 32), tb32>>>(wq, wqkvh, D_, D_);
    transpose_hi_kernel<<<dim3(D_ / 32, D_ / 32), tb32>>>(wk, wqkvh + (size_t)D_ * D_, D_, D_);
    transpose_hi_kernel<<<dim3(D_ / 32, D_ / 32), tb32>>>(wv, wqkvh + (size_t)2 * D_ * D_, D_, D_);
    transpose_hi_kernel<<<dim3(FF_ / 32, D_ / 32), tb32>>>(w1, w1h, D_, FF_);   // w1h: [FF][D]
    transpose_hi_kernel<<<dim3(D_ / 32, FF_ / 32), tb32>>>(w2, w2h, FF_, D_);   // w2h: [D][FF]
    transpose_hi_kernel<<<dim3(D_ / 32, D_ / 32), tb32>>>(wo, woh, D_, D_);

    // 1) LayerNorm -> xn hi/lo
    ln_split_kernel<<<T_, 256>>>(x, ln_s, ln_o, xnh, xnl);

    // 2) fused QKV projection: [2048,4096]@[4096,12288]
    {
        dim3 g(D3_ / NTT, T_ / MT, 1);
        mma_gemm<<<g, 256, GEMM_SMEM_BYTES>>>(D_, 0, xnh, xnl, D_, 0, wqkvh, D_, 0,
            qkv, nullptr, nullptr, D3_, 0, 1.f, E_F32, nullptr, nullptr, 0);
    }

    // 3) RoPE + split q (hi/lo), k (hi)
    rope_split_kernel<<<T_, 256>>>(qkv, tcs, tsn, qh, ql, kh);

    // 4) V transpose (hi)
    transpose_v_hi_kernel<<<dim3(DH_ / 32, T_ / 32, H_), tb32>>>(qkv, vth);

    // 5) scores = scale * Q_h @ K_h^T + causal (masked tiles skipped)
    {
        dim3 g(T_ / NTT, T_ / MT, H_);
        mma_gemm<<<g, 256, GEMM_SMEM_BYTES>>>(DH_, 0,
            qh, ql, D_, DH_,
            kh, D_, DH_,
            sc, nullptr, nullptr, T_, (long long)T_ * T_,
            0.0625f, E_CAUSAL, nullptr, nullptr, 0);
    }

    // 6) softmax (causal length) -> P hi/lo
    softmax_split_kernel<<<H_ * T_, 256>>>(sc, sch, scl);

    // 7) ctx = P_h @ V_h  (causal K-limit, split out)
    {
        dim3 g(DH_ / NTT, T_ / MT, H_);
        mma_gemm<<<g, 256, GEMM_SMEM_BYTES>>>(T_, 1,
            sch, scl, T_, (long long)T_ * T_,
            vth, T_, (long long)DH_ * T_,
            nullptr, cxh, cxl, D_, DH_,
            1.f, E_SPLIT, nullptr, nullptr, 0);
    }

    // 8) attn_out = ctx @ wo
    {
        dim3 g(D_ / NTT, T_ / MT, 1);
        mma_gemm<<<g, 256, GEMM_SMEM_BYTES>>>(D_, 0, cxh, cxl, D_, 0, woh, D_, 0,
            attn, nullptr, nullptr, D_, 0, 1.f, E_F32, nullptr, nullptr, 0);
    }

    // 9) h = gelu(xn @ w1 + b1)  (split out) — w1h rows have stride D_
    {
        dim3 g(FF_ / NTT, T_ / MT, 1);
        mma_gemm<<<g, 256, GEMM_SMEM_BYTES>>>(D_, 0, xnh, xnl, D_, 0, w1h, D_, 0,
            nullptr, hbh, hbl, FF_, 0, 1.f, E_GELU_SPLIT, b1, nullptr, 0);
    }

    // 10) out = h @ w2 + b2 + attn_out — w2h rows have stride FF_
    {
        dim3 g(D_ / NTT, T_ / MT, 1);
        mma_gemm<<<g, 256, GEMM_SMEM_BYTES>>>(FF_, 0, hbh, hbl, FF_, 0, w2h, FF_, 0,
            out, nullptr, nullptr, D_, 0, 1.f, E_BIASRES, b2, attn, D_);
    }
}

// round 13
// speedup vs baseline: 1.9426x; 1.1114x over previous
#include <cuda_runtime.h>
#include <cuda_fp16.h>
#include <math.h>
#include <stdint.h>

#define T_  2048
#define D_  4096
#define D3_ 12288
#define H_  16
#define DH_ 256
#define RR_ 64
#define FF_ 16384

// GEMM tiling — stages: Ah(16K)+Al(16K)+Bh(16K)
#define MT   128
#define NTT  128
#define KC   64
#define STAGE_B 49152
#define NSTAGE 3
#define GEMM_SMEM_BYTES (NSTAGE * STAGE_B)   // 144KB

typedef __half f16;

// ---------------- scratch (static device arrays: allocation-free) -----------
__device__ float g_qkv [(size_t)T_ * D3_];       // fused q|k|v fp32
__device__ float g_attn[(size_t)T_ * D_];
__device__ float g_sc  [(size_t)H_ * T_ * T_];
__device__ float g_tcos[(size_t)T_ * 32];
__device__ float g_tsin[(size_t)T_ * 32];

__device__ f16 g_xnh [(size_t)T_ * D_];
__device__ f16 g_xnl [(size_t)T_ * D_];
__device__ f16 g_qh  [(size_t)T_ * D_];
__device__ f16 g_ql  [(size_t)T_ * D_];
__device__ f16 g_kh  [(size_t)T_ * D_];
__device__ f16 g_vth [(size_t)H_ * DH_ * T_];
__device__ f16 g_sch [(size_t)H_ * T_ * T_];
__device__ f16 g_scl [(size_t)H_ * T_ * T_];
__device__ f16 g_cxh [(size_t)T_ * D_];
__device__ f16 g_cxl [(size_t)T_ * D_];
__device__ f16 g_hbh [(size_t)T_ * FF_];
__device__ f16 g_hbl [(size_t)T_ * FF_];
__device__ f16 g_wqkvh[(size_t)D3_ * D_];        // fused wq|wk|wv transposed hi
__device__ f16 g_woh [(size_t)D_ * D_];
__device__ f16 g_w1h [(size_t)FF_ * D_];         // [FF][D], row stride D
__device__ f16 g_w2h [(size_t)D_ * FF_];         // [D][FF], row stride FF

// ---------------- helpers ----------------------------------------------------
__device__ __forceinline__ uint32_t smem_u32(const void* p) {
    uint32_t a;
    asm("{ .reg .u64 t; cvta.to.shared.u64 t, %1; cvt.u32.u64 %0, t; }"
        : "=r"(a) : "l"(p));
    return a;
}

#define SWZ(o) ((o) ^ (((o) >> 3) & 0x70))

#define CP16(dst, src) \
    asm volatile("cp.async.cg.shared.global [%0], [%1], 16;" \
                 :: "r"(dst), "l"(src))
#define CPCOMMIT() asm volatile("cp.async.commit_group;" ::: "memory")
#define CPWAIT2()  asm volatile("cp.async.wait_group 2;" ::: "memory")
#define CPWAIT0()  asm volatile("cp.async.wait_group 0;" ::: "memory")

__device__ __forceinline__ void ldm_x4(uint32_t* r, uint32_t a) {
    asm volatile("ldmatrix.sync.aligned.m8n8.x4.shared.b16 {%0,%1,%2,%3}, [%4];"
                 : "=r"(r[0]), "=r"(r[1]), "=r"(r[2]), "=r"(r[3]) : "r"(a));
}

__device__ __forceinline__ void mma16816(float* d, const uint32_t* a, const uint32_t* b) {
    asm volatile("mma.sync.aligned.m16n8k16.row.col.f32.f16.f16.f32 "
                 "{%0,%1,%2,%3}, {%4,%5,%6,%7}, {%8,%9}, {%0,%1,%2,%3};"
                 : "+f"(d[0]), "+f"(d[1]), "+f"(d[2]), "+f"(d[3])
                 : "r"(a[0]), "r"(a[1]), "r"(a[2]), "r"(a[3]),
                   "r"(b[0]), "r"(b[1]));
}

// split fp32 pair -> packed fp16x2 hi and lo
__device__ __forceinline__ void split2(float x, float y, uint32_t& hi, uint32_t& lo) {
    f16 hx = __float2half_rn(x);
    f16 hy = __float2half_rn(y);
    float rx = x - __half2float(hx);
    float ry = y - __half2float(hy);
    f16 lx = __float2half_rn(rx);
    f16 ly = __float2half_rn(ry);
    hi = ((uint32_t)__half_as_ushort(hy) << 16) | (uint32_t)__half_as_ushort(hx);
    lo = ((uint32_t)__half_as_ushort(ly) << 16) | (uint32_t)__half_as_ushort(lx);
}

__device__ __forceinline__ uint32_t pack_hi2(float x, float y) {
    f16 hx = __float2half_rn(x);
    f16 hy = __float2half_rn(y);
    return ((uint32_t)__half_as_ushort(hy) << 16) | (uint32_t)__half_as_ushort(hx);
}

__device__ __forceinline__ float gelu_f(float x)
{
    const float x3 = x * x * x;
    return 0.5f * x * (1.0f + tanhf(0.7978845608028654f * (x + 0.044715f * x3)));
}

// ---------------- RoPE table (double-precision, computed once per launch) ----
__global__ void rope_table_kernel(float* __restrict__ tc, float* __restrict__ ts)
{
    const int t = blockIdx.x;
    const int i = threadIdx.x;          // 0..31
    const double inv = pow(10000.0, -2.0 * (double)i / (double)RR_);
    const double ang = (double)t * inv;
    tc[t * 32 + i] = (float)cos(ang);
    ts[t * 32 + i] = (float)sin(ang);
}

// ---------------- LayerNorm -> split fp16 ------------------------------------
__global__ void ln_split_kernel(const float* __restrict__ x,
                                const float* __restrict__ scale,
                                const float* __restrict__ offset,
                                f16* __restrict__ oh, f16* __restrict__ ol)
{
    const int t = blockIdx.x;
    const float* xr = x + (size_t)t * D_;
    const int base = threadIdx.x * 16;
    __shared__ float red[256];

    float v[16];
#pragma unroll
    for (int i = 0; i < 16; i += 4)
        *reinterpret_cast<float4*>(v + i) =
            *reinterpret_cast<const float4*>(xr + base + i);

    float s = 0.f;
#pragma unroll
    for (int i = 0; i < 16; i++) s += v[i];
    red[threadIdx.x] = s; __syncthreads();
    for (int o = 128; o > 0; o >>= 1) {
        if (threadIdx.x < o) red[threadIdx.x] += red[threadIdx.x + o];
        __syncthreads();
    }
    const float mean = red[0] * (1.0f / D_);
    __syncthreads();

    float vv = 0.f;
#pragma unroll
    for (int i = 0; i < 16; i++) { float d = v[i] - mean; vv += d * d; }
    red[threadIdx.x] = vv; __syncthreads();
    for (int o = 128; o > 0; o >>= 1) {
        if (threadIdx.x < o) red[threadIdx.x] += red[threadIdx.x + o];
        __syncthreads();
    }
    const float rstd = rsqrtf(red[0] * (1.0f / D_) + 1e-5f);

    f16* ohr = oh + (size_t)t * D_ + base;
    f16* olr = ol + (size_t)t * D_ + base;
#pragma unroll
    for (int i = 0; i < 16; i += 2) {
        float y0 = (v[i]     - mean) * rstd * scale[base + i]     + offset[base + i];
        float y1 = (v[i + 1] - mean) * rstd * scale[base + i + 1] + offset[base + i + 1];
        uint32_t hi, lo;
        split2(y0, y1, hi, lo);
        *reinterpret_cast<uint32_t*>(ohr + i) = hi;
        *reinterpret_cast<uint32_t*>(olr + i) = lo;
    }
}

// ---------------- RoPE + split q (hi/lo), k (hi only) ------------------------
__global__ void rope_split_kernel(const float* __restrict__ qkv,
                                  const float* __restrict__ tc,
                                  const float* __restrict__ ts,
                                  f16* __restrict__ qh, f16* __restrict__ ql,
                                  f16* __restrict__ kh)
{
    const int t = blockIdx.x;
    const int d0 = threadIdx.x * 16;
    const size_t src = (size_t)t * D3_ + d0;   // q at col 0, k at col D_
    const size_t dst = (size_t)t * D_ + d0;

#pragma unroll
    for (int j = 0; j < 8; j++) {
        const int d = d0 + 2 * j;
        float2 qv = *reinterpret_cast<const float2*>(qkv + src + 2 * j);
        float2 kv = *reinterpret_cast<const float2*>(qkv + src + D_ + 2 * j);
        const int dd = d & (DH_ - 1);
        if (dd < RR_) {
            const int i = dd >> 1;
            const float c = tc[t * 32 + i];
            const float s = ts[t * 32 + i];
            float q0 = qv.x, q1 = qv.y;
            qv.x = q0 * c - q1 * s; qv.y = q1 * c + q0 * s;
            float k0 = kv.x, k1 = kv.y;
            kv.x = k0 * c - k1 * s; kv.y = k1 * c + k0 * s;
        }
        uint32_t hi, lo;
        split2(qv.x, qv.y, hi, lo);
        *reinterpret_cast<uint32_t*>(qh + dst + 2 * j) = hi;
        *reinterpret_cast<uint32_t*>(ql + dst + 2 * j) = lo;
        *reinterpret_cast<uint32_t*>(kh + dst + 2 * j) = pack_hi2(kv.x, kv.y);
    }
}

// ---------------- softmax (causal-limited) -> split fp16 ---------------------
__global__ void softmax_split_kernel(const float* __restrict__ scores,
                                     f16* __restrict__ ph, f16* __restrict__ pl)
{
    const size_t row = blockIdx.x;
    const int t = (int)(row & (T_ - 1));
    const int L = ((t >> 7) + 1) << 7;          // causal row length, mult of 128
    const float* r = scores + row * (size_t)T_;
    const int base = threadIdx.x * 8;
    const bool act = base < L;                  // 8-blocks fully in or out
    __shared__ float red[256];

    float v[8];
    if (act) {
#pragma unroll
        for (int i = 0; i < 8; i += 4)
            *reinterpret_cast<float4*>(v + i) =
                *reinterpret_cast<const float4*>(r + base + i);
    } else {
#pragma unroll
        for (int i = 0; i < 8; i++) v[i] = -1e30f;
    }

    float m = -1e30f;
#pragma unroll
    for (int i = 0; i < 8; i++) m = fmaxf(m, v[i]);
    red[threadIdx.x] = m; __syncthreads();
    for (int o = 128; o > 0; o >>= 1) {
        if (threadIdx.x < o) red[threadIdx.x] = fmaxf(red[threadIdx.x], red[threadIdx.x + o]);
        __syncthreads();
    }
    m = red[0]; __syncthreads();

    float s = 0.f;
    if (act) {
#pragma unroll
        for (int i = 0; i < 8; i++) { v[i] = __expf(v[i] - m); s += v[i]; }
    }
    red[threadIdx.x] = s; __syncthreads();
    for (int o = 128; o > 0; o >>= 1) {
        if (threadIdx.x < o) red[threadIdx.x] += red[threadIdx.x + o];
        __syncthreads();
    }
    const float invs = 1.0f / red[0];

    if (act) {
        f16* phr = ph + row * (size_t)T_ + base;
        f16* plr = pl + row * (size_t)T_ + base;
#pragma unroll
        for (int i = 0; i < 8; i += 2) {
            uint32_t hi, lo;
            split2(v[i] * invs, v[i + 1] * invs, hi, lo);
            *reinterpret_cast<uint32_t*>(phr + i) = hi;
            *reinterpret_cast<uint32_t*>(plr + i) = lo;
        }
    }
}

// ---------------- transpose: in[R][C] fp32 -> out[C][R] fp16 hi only ---------
__global__ void transpose_hi_kernel(const float* __restrict__ in,
                                    f16* __restrict__ oh, int R, int C)
{
    __shared__ float t[32][33];
    const int c0 = blockIdx.x * 32, r0 = blockIdx.y * 32;
    const int x = threadIdx.x, y = threadIdx.y;
#pragma unroll
    for (int i = 0; i < 32; i += 8)
        t[y + i][x] = in[(size_t)(r0 + y + i) * C + c0 + x];
    __syncthreads();
#pragma unroll
    for (int i = 0; i < 32; i += 8) {
        const size_t o = (size_t)(c0 + y + i) * R + r0 + x;
        oh[o] = __float2half_rn(t[x][y + i]);
    }
}

// per-head transpose of V (cols 2D.. of fused qkv): vt[h][d][t], hi only
__global__ void transpose_v_hi_kernel(const float* __restrict__ qkv,
                                      f16* __restrict__ oh)
{
    __shared__ float s[32][33];
    const int h = blockIdx.z;
    const int d0 = blockIdx.x * 32, t0 = blockIdx.y * 32;
    const int x = threadIdx.x, y = threadIdx.y;
#pragma unroll
    for (int i = 0; i < 32; i += 8)
        s[y + i][x] = qkv[(size_t)(t0 + y + i) * D3_ + 2 * D_ + (size_t)h * DH_ + d0 + x];
    __syncthreads();
#pragma unroll
    for (int i = 0; i < 32; i += 8) {
        const size_t o = ((size_t)h * DH_ + d0 + y + i) * T_ + t0 + x;
        oh[o] = __float2half_rn(s[x][y + i]);
    }
}

// ---------------- split-fp16 GEMM: C = (Ah [+ Al]) @ Bh^T --------------------
// NPROD=2: A = Ah + Al.  NPROD=1: A = Ah only (Al never loaded).
// climit != 0: effective K for row-block at m0 is (m0 + MT) (causal PV).
enum { E_F32 = 0, E_CAUSAL = 1, E_SPLIT = 2, E_GELU_SPLIT = 3, E_BIASRES = 4 };

template <int NPROD>
__global__ void __launch_bounds__(256, 1)
mma_gemm(int K, int climit,
         const f16* __restrict__ Ah, const f16* __restrict__ Al,
         int lda, long long sA,
         const f16* __restrict__ Bh, int ldb, long long sB,
         float* __restrict__ C, f16* __restrict__ Chi, f16* __restrict__ Clo,
         int ldc, long long sC,
         float alpha, int epi,
         const float* __restrict__ bias,
         const float* __restrict__ res, int ldres)
{
    extern __shared__ char smem[];
    const uint32_t sbase = smem_u32(smem);
    const int tid = threadIdx.x;
    const int wid = tid >> 5, lid = tid & 31;
    const int m0 = blockIdx.y * MT, n0 = blockIdx.x * NTT;

    Ah += (size_t)blockIdx.z * sA;
    if (NPROD == 2) Al += (size_t)blockIdx.z * sA;
    Bh += (size_t)blockIdx.z * sB;
    if (C)   C   += (size_t)blockIdx.z * sC;
    if (Chi) { Chi += (size_t)blockIdx.z * sC; Clo += (size_t)blockIdx.z * sC; }

    // fully-masked causal tile: nothing downstream reads it -> skip entirely
    if (epi == E_CAUSAL && n0 > m0 + (MT - 1)) return;

    const int Keff = climit ? (m0 + MT) : K;   // causal K-limit (multiple of KC)

    const int wm = (wid >> 2) * 64;
    const int wn = (wid & 3) * 32;

    float acc[4][4][4];
#pragma unroll
    for (int i = 0; i < 4; i++)
#pragma unroll
        for (int j = 0; j < 4; j++)
#pragma unroll
            for (int r = 0; r < 4; r++) acc[i][j][r] = 0.f;

    const int lrow = tid >> 3;     // 0..31 (plus p*32)
    const int lcol = tid & 7;      // 16B column within 128B row

    const int NC = Keff / KC;

#define ISSUE_STAGE(stg, kc_) do {                                              \
        const int kc__ = (kc_);                                                 \
        _Pragma("unroll")                                                       \
        for (int p = 0; p < 4; p++) {                                           \
            const int row = lrow + p * 32;                                      \
            const uint32_t dsw = SWZ((uint32_t)(row * 128 + lcol * 16));        \
            const uint32_t db = sbase + (uint32_t)(stg) * STAGE_B + dsw;        \
            CP16(db,          Ah + (size_t)(m0 + row) * lda + kc__ + lcol * 8); \
            if (NPROD == 2)                                                     \
                CP16(db + 16384u, Al + (size_t)(m0 + row) * lda + kc__ + lcol * 8); \
            CP16(db + 32768u, Bh + (size_t)(n0 + row) * ldb + kc__ + lcol * 8); \
        }                                                                       \
        CPCOMMIT();                                                             \
    } while (0)

    ISSUE_STAGE(0, 0);
    ISSUE_STAGE(1, KC);

    const uint32_t aRawBase = (uint32_t)((wm + (lid & 15)) * 128 + (lid >> 4) * 16);
    const uint32_t bRawBase = (uint32_t)((wn + (lid & 7) + ((lid >> 4) << 3)) * 128
                                         + (((lid >> 3) & 1) << 4));

    for (int c = 0; c < NC; ++c) {
        if (c + 2 < NC) {
            ISSUE_STAGE((c + 2) % NSTAGE, (c + 2) * KC);
            CPWAIT2();
        } else {
            CPWAIT0();
        }
        __syncthreads();

        const uint32_t st = sbase + (uint32_t)(c % NSTAGE) * STAGE_B;

#pragma unroll
        for (int ks = 0; ks < 4; ks++) {
            const uint32_t kb = (uint32_t)ks * 32;
            uint32_t ah[4][4], al[4][4], bh[4][2];
#pragma unroll
            for (int i = 0; i < 4; i++) {
                const uint32_t raw = aRawBase + (uint32_t)i * (16 * 128) + kb;
                ldm_x4(ah[i], st + SWZ(raw));
                if (NPROD == 2) ldm_x4(al[i], st + 16384u + SWZ(raw));
            }
#pragma unroll
            for (int j2 = 0; j2 < 2; j2++) {
                const uint32_t raw = bRawBase + (uint32_t)j2 * (16 * 128) + kb;
                uint32_t t4[4];
                ldm_x4(t4, st + 32768u + SWZ(raw));
                bh[2 * j2][0] = t4[0]; bh[2 * j2][1] = t4[1];
                bh[2 * j2 + 1][0] = t4[2]; bh[2 * j2 + 1][1] = t4[3];
            }
#pragma unroll
            for (int i = 0; i < 4; i++)
#pragma unroll
                for (int j = 0; j < 4; j++) {
                    mma16816(acc[i][j], ah[i], bh[j]);
                    if (NPROD == 2) mma16816(acc[i][j], al[i], bh[j]);
                }
        }
        __syncthreads();
    }
#undef ISSUE_STAGE

    // ---------------- epilogue ----------------
    const int tr = lid >> 2, tc = (lid & 3) * 2;
#pragma unroll
    for (int i = 0; i < 4; i++) {
        const int m1 = m0 + wm + i * 16 + tr;
        const int m2 = m1 + 8;
#pragma unroll
        for (int j = 0; j < 4; j++) {
            const int n = n0 + wn + j * 8 + tc;
            float v0 = acc[i][j][0] * alpha;
            float v1 = acc[i][j][1] * alpha;
            float v2 = acc[i][j][2] * alpha;
            float v3 = acc[i][j][3] * alpha;
            if (epi == E_CAUSAL) {
                if (n     > m1) v0 = -1e10f;
                if (n + 1 > m1) v1 = -1e10f;
                if (n     > m2) v2 = -1e10f;
                if (n + 1 > m2) v3 = -1e10f;
            } else if (epi == E_GELU_SPLIT) {
                const float b0 = bias[n], b1 = bias[n + 1];
                v0 = gelu_f(v0 + b0); v1 = gelu_f(v1 + b1);
                v2 = gelu_f(v2 + b0); v3 = gelu_f(v3 + b1);
            } else if (epi == E_BIASRES) {
                const float b0 = bias[n], b1 = bias[n + 1];
                const float2 r1 = *reinterpret_cast<const float2*>(res + (size_t)m1 * ldres + n);
                const float2 r2 = *reinterpret_cast<const float2*>(res + (size_t)m2 * ldres + n);
                v0 += b0 + r1.x; v1 += b1 + r1.y;
                v2 += b0 + r2.x; v3 += b1 + r2.y;
            }
            if (epi == E_SPLIT || epi == E_GELU_SPLIT) {
                uint32_t hi, lo;
                split2(v0, v1, hi, lo);
                *reinterpret_cast<uint32_t*>(Chi + (size_t)m1 * ldc + n) = hi;
                *reinterpret_cast<uint32_t*>(Clo + (size_t)m1 * ldc + n) = lo;
                split2(v2, v3, hi, lo);
                *reinterpret_cast<uint32_t*>(Chi + (size_t)m2 * ldc + n) = hi;
                *reinterpret_cast<uint32_t*>(Clo + (size_t)m2 * ldc + n) = lo;
            } else {
                *reinterpret_cast<float2*>(C + (size_t)m1 * ldc + n) = make_float2(v0, v1);
                *reinterpret_cast<float2*>(C + (size_t)m2 * ldc + n) = make_float2(v2, v3);
            }
        }
    }
}

// ---------------- launch -----------------------------------------------------
extern "C" void kernel_launch(void* const* d_in, const int* in_sizes, int n_in,
                              void* d_out, int out_size)
{
    const float* x    = (const float*)d_in[0];
    const float* ln_s = (const float*)d_in[1];
    const float* ln_o = (const float*)d_in[2];
    const float* wq   = (const float*)d_in[3];
    const float* wk   = (const float*)d_in[4];
    const float* wv   = (const float*)d_in[5];
    const float* wo   = (const float*)d_in[6];
    const float* w1   = (const float*)d_in[7];
    const float* b1   = (const float*)d_in[8];
    const float* w2   = (const float*)d_in[9];
    const float* b2   = (const float*)d_in[10];
    float* out = (float*)d_out;

    float *qkv, *attn, *sc, *tcs, *tsn;
    f16 *xnh, *xnl, *qh, *ql, *kh, *vth, *sch, *scl;
    f16 *cxh, *cxl, *hbh, *hbl;
    f16 *wqkvh, *woh, *w1h, *w2h;

    cudaGetSymbolAddress((void**)&qkv,  g_qkv);
    cudaGetSymbolAddress((void**)&attn, g_attn);
    cudaGetSymbolAddress((void**)&sc,   g_sc);
    cudaGetSymbolAddress((void**)&tcs,  g_tcos);
    cudaGetSymbolAddress((void**)&tsn,  g_tsin);
    cudaGetSymbolAddress((void**)&xnh,  g_xnh);
    cudaGetSymbolAddress((void**)&xnl,  g_xnl);
    cudaGetSymbolAddress((void**)&qh,   g_qh);
    cudaGetSymbolAddress((void**)&ql,   g_ql);
    cudaGetSymbolAddress((void**)&kh,   g_kh);
    cudaGetSymbolAddress((void**)&vth,  g_vth);
    cudaGetSymbolAddress((void**)&sch,  g_sch);
    cudaGetSymbolAddress((void**)&scl,  g_scl);
    cudaGetSymbolAddress((void**)&cxh,  g_cxh);
    cudaGetSymbolAddress((void**)&cxl,  g_cxl);
    cudaGetSymbolAddress((void**)&hbh,  g_hbh);
    cudaGetSymbolAddress((void**)&hbl,  g_hbl);
    cudaGetSymbolAddress((void**)&wqkvh, g_wqkvh);
    cudaGetSymbolAddress((void**)&woh,  g_woh);
    cudaGetSymbolAddress((void**)&w1h,  g_w1h);
    cudaGetSymbolAddress((void**)&w2h,  g_w2h);

    cudaFuncSetAttribute(mma_gemm<2>, cudaFuncAttributeMaxDynamicSharedMemorySize,
                         GEMM_SMEM_BYTES);
    cudaFuncSetAttribute(mma_gemm<1>, cudaFuncAttributeMaxDynamicSharedMemorySize,
                         GEMM_SMEM_BYTES);

    const dim3 tb32(32, 8);

    // 0) RoPE table + weight transposes (hi only)
    rope_table_kernel<<<T_, 32>>>(tcs, tsn);
    transpose_hi_kernel<<<dim3(D_ / 32, D_ / 32), tb32>>>(wq, wqkvh, D_, D_);
    transpose_hi_kernel<<<dim3(D_ / 32, D_ / 32), tb32>>>(wk, wqkvh + (size_t)D_ * D_, D_, D_);
    transpose_hi_kernel<<<dim3(D_ / 32, D_ / 32), tb32>>>(wv, wqkvh + (size_t)2 * D_ * D_, D_, D_);
    transpose_hi_kernel<<<dim3(FF_ / 32, D_ / 32), tb32>>>(w1, w1h, D_, FF_);   // w1h: [FF][D]
    transpose_hi_kernel<<<dim3(D_ / 32, FF_ / 32), tb32>>>(w2, w2h, FF_, D_);   // w2h: [D][FF]
    transpose_hi_kernel<<<dim3(D_ / 32, D_ / 32), tb32>>>(wo, woh, D_, D_);

    // 1) LayerNorm -> xn hi/lo
    ln_split_kernel<<<T_, 256>>>(x, ln_s, ln_o, xnh, xnl);

    // 2) fused QKV projection (2-product): [2048,4096]@[4096,12288]
    {
        dim3 g(D3_ / NTT, T_ / MT, 1);
        mma_gemm<2><<<g, 256, GEMM_SMEM_BYTES>>>(D_, 0, xnh, xnl, D_, 0, wqkvh, D_, 0,
            qkv, nullptr, nullptr, D3_, 0, 1.f, E_F32, nullptr, nullptr, 0);
    }

    // 3) RoPE + split q (hi/lo), k (hi)
    rope_split_kernel<<<T_, 256>>>(qkv, tcs, tsn, qh, ql, kh);

    // 4) V transpose (hi)
    transpose_v_hi_kernel<<<dim3(DH_ / 32, T_ / 32, H_), tb32>>>(qkv, vth);

    // 5) scores = scale * Q_h @ K_h^T + causal (2-product, masked tiles skipped)
    {
        dim3 g(T_ / NTT, T_ / MT, H_);
        mma_gemm<2><<<g, 256, GEMM_SMEM_BYTES>>>(DH_, 0,
            qh, ql, D_, DH_,
            kh, D_, DH_,
            sc, nullptr, nullptr, T_, (long long)T_ * T_,
            0.0625f, E_CAUSAL, nullptr, nullptr, 0);
    }

    // 6) softmax (causal length) -> P hi/lo
    softmax_split_kernel<<<H_ * T_, 256>>>(sc, sch, scl);

    // 7) ctx = P_h @ V_h  (2-product, causal K-limit, split out)
    {
        dim3 g(DH_ / NTT, T_ / MT, H_);
        mma_gemm<2><<<g, 256, GEMM_SMEM_BYTES>>>(T_, 1,
            sch, scl, T_, (long long)T_ * T_,
            vth, T_, (long long)DH_ * T_,
            nullptr, cxh, cxl, D_, DH_,
            1.f, E_SPLIT, nullptr, nullptr, 0);
    }

    // 8) attn_out = ctx @ wo (2-product)
    {
        dim3 g(D_ / NTT, T_ / MT, 1);
        mma_gemm<2><<<g, 256, GEMM_SMEM_BYTES>>>(D_, 0, cxh, cxl, D_, 0, woh, D_, 0,
            attn, nullptr, nullptr, D_, 0, 1.f, E_F32, nullptr, nullptr, 0);
    }

    // 9) h = gelu(xn @ w1 + b1)  (SINGLE product, split out) — w1h stride D_
    {
        dim3 g(FF_ / NTT, T_ / MT, 1);
        mma_gemm<1><<<g, 256, GEMM_SMEM_BYTES>>>(D_, 0, xnh, xnl, D_, 0, w1h, D_, 0,
            nullptr, hbh, hbl, FF_, 0, 1.f, E_GELU_SPLIT, b1, nullptr, 0);
    }

    // 10) out = h @ w2 + b2 + attn_out (2-product) — w2h stride FF_
    {
        dim3 g(D_ / NTT, T_ / MT, 1);
        mma_gemm<2><<<g, 256, GEMM_SMEM_BYTES>>>(FF_, 0, hbh, hbl, FF_, 0, w2h, FF_, 0,
            out, nullptr, nullptr, D_, 0, 1.f, E_BIASRES, b2, attn, D_);
    }
}

// round 14
// speedup vs baseline: 2.3655x; 1.2177x over previous
#include <cuda_runtime.h>
#include <cuda_fp16.h>
#include <math.h>
#include <stdint.h>

#define T_  2048
#define D_  4096
#define D3_ 12288
#define H_  16
#define DH_ 256
#define RR_ 64
#define FF_ 16384

// GEMM tiling — stages: Ah(16K)+Al(16K)+Bh(16K)
#define MT   128
#define NTT  128
#define KC   64
#define STAGE_B 49152
#define NSTAGE 3
#define GEMM_SMEM_BYTES (NSTAGE * STAGE_B)   // 144KB

typedef __half f16;

// ---------------- scratch (static device arrays: allocation-free) -----------
__device__ float g_qkv [(size_t)T_ * D3_];       // fused q|k|v fp32
__device__ float g_attn[(size_t)T_ * D_];
__device__ float g_sc  [(size_t)H_ * T_ * T_];
__device__ float g_tcos[(size_t)T_ * 32];
__device__ float g_tsin[(size_t)T_ * 32];

__device__ f16 g_xnh [(size_t)T_ * D_];
__device__ f16 g_xnl [(size_t)T_ * D_];
__device__ f16 g_qh  [(size_t)T_ * D_];
__device__ f16 g_ql  [(size_t)T_ * D_];
__device__ f16 g_kh  [(size_t)T_ * D_];
__device__ f16 g_vth [(size_t)H_ * DH_ * T_];
__device__ f16 g_sch [(size_t)H_ * T_ * T_];
__device__ f16 g_cxh [(size_t)T_ * D_];
__device__ f16 g_hbh [(size_t)T_ * FF_];
__device__ f16 g_wqkvh[(size_t)D3_ * D_];        // fused wq|wk|wv transposed hi
__device__ f16 g_woh [(size_t)D_ * D_];
__device__ f16 g_w1h [(size_t)FF_ * D_];         // [FF][D], row stride D
__device__ f16 g_w2h [(size_t)D_ * FF_];         // [D][FF], row stride FF

// ---------------- helpers ----------------------------------------------------
__device__ __forceinline__ uint32_t smem_u32(const void* p) {
    uint32_t a;
    asm("{ .reg .u64 t; cvta.to.shared.u64 t, %1; cvt.u32.u64 %0, t; }"
        : "=r"(a) : "l"(p));
    return a;
}

#define SWZ(o) ((o) ^ (((o) >> 3) & 0x70))

#define CP16(dst, src) \
    asm volatile("cp.async.cg.shared.global [%0], [%1], 16;" \
                 :: "r"(dst), "l"(src))
#define CPCOMMIT() asm volatile("cp.async.commit_group;" ::: "memory")
#define CPWAIT2()  asm volatile("cp.async.wait_group 2;" ::: "memory")
#define CPWAIT0()  asm volatile("cp.async.wait_group 0;" ::: "memory")

__device__ __forceinline__ void ldm_x4(uint32_t* r, uint32_t a) {
    asm volatile("ldmatrix.sync.aligned.m8n8.x4.shared.b16 {%0,%1,%2,%3}, [%4];"
                 : "=r"(r[0]), "=r"(r[1]), "=r"(r[2]), "=r"(r[3]) : "r"(a));
}

__device__ __forceinline__ void mma16816(float* d, const uint32_t* a, const uint32_t* b) {
    asm volatile("mma.sync.aligned.m16n8k16.row.col.f32.f16.f16.f32 "
                 "{%0,%1,%2,%3}, {%4,%5,%6,%7}, {%8,%9}, {%0,%1,%2,%3};"
                 : "+f"(d[0]), "+f"(d[1]), "+f"(d[2]), "+f"(d[3])
                 : "r"(a[0]), "r"(a[1]), "r"(a[2]), "r"(a[3]),
                   "r"(b[0]), "r"(b[1]));
}

// split fp32 pair -> packed fp16x2 hi and lo
__device__ __forceinline__ void split2(float x, float y, uint32_t& hi, uint32_t& lo) {
    f16 hx = __float2half_rn(x);
    f16 hy = __float2half_rn(y);
    float rx = x - __half2float(hx);
    float ry = y - __half2float(hy);
    f16 lx = __float2half_rn(rx);
    f16 ly = __float2half_rn(ry);
    hi = ((uint32_t)__half_as_ushort(hy) << 16) | (uint32_t)__half_as_ushort(hx);
    lo = ((uint32_t)__half_as_ushort(ly) << 16) | (uint32_t)__half_as_ushort(lx);
}

__device__ __forceinline__ uint32_t pack_hi2(float x, float y) {
    f16 hx = __float2half_rn(x);
    f16 hy = __float2half_rn(y);
    return ((uint32_t)__half_as_ushort(hy) << 16) | (uint32_t)__half_as_ushort(hx);
}

__device__ __forceinline__ float gelu_f(float x)
{
    const float x3 = x * x * x;
    return 0.5f * x * (1.0f + tanhf(0.7978845608028654f * (x + 0.044715f * x3)));
}

// ---------------- RoPE table (double-precision, computed once per launch) ----
__global__ void rope_table_kernel(float* __restrict__ tc, float* __restrict__ ts)
{
    const int t = blockIdx.x;
    const int i = threadIdx.x;          // 0..31
    const double inv = pow(10000.0, -2.0 * (double)i / (double)RR_);
    const double ang = (double)t * inv;
    tc[t * 32 + i] = (float)cos(ang);
    ts[t * 32 + i] = (float)sin(ang);
}

// ---------------- LayerNorm -> split fp16 ------------------------------------
__global__ void ln_split_kernel(const float* __restrict__ x,
                                const float* __restrict__ scale,
                                const float* __restrict__ offset,
                                f16* __restrict__ oh, f16* __restrict__ ol)
{
    const int t = blockIdx.x;
    const float* xr = x + (size_t)t * D_;
    const int base = threadIdx.x * 16;
    __shared__ float red[256];

    float v[16];
#pragma unroll
    for (int i = 0; i < 16; i += 4)
        *reinterpret_cast<float4*>(v + i) =
            *reinterpret_cast<const float4*>(xr + base + i);

    float s = 0.f;
#pragma unroll
    for (int i = 0; i < 16; i++) s += v[i];
    red[threadIdx.x] = s; __syncthreads();
    for (int o = 128; o > 0; o >>= 1) {
        if (threadIdx.x < o) red[threadIdx.x] += red[threadIdx.x + o];
        __syncthreads();
    }
    const float mean = red[0] * (1.0f / D_);
    __syncthreads();

    float vv = 0.f;
#pragma unroll
    for (int i = 0; i < 16; i++) { float d = v[i] - mean; vv += d * d; }
    red[threadIdx.x] = vv; __syncthreads();
    for (int o = 128; o > 0; o >>= 1) {
        if (threadIdx.x < o) red[threadIdx.x] += red[threadIdx.x + o];
        __syncthreads();
    }
    const float rstd = rsqrtf(red[0] * (1.0f / D_) + 1e-5f);

    f16* ohr = oh + (size_t)t * D_ + base;
    f16* olr = ol + (size_t)t * D_ + base;
#pragma unroll
    for (int i = 0; i < 16; i += 2) {
        float y0 = (v[i]     - mean) * rstd * scale[base + i]     + offset[base + i];
        float y1 = (v[i + 1] - mean) * rstd * scale[base + i + 1] + offset[base + i + 1];
        uint32_t hi, lo;
        split2(y0, y1, hi, lo);
        *reinterpret_cast<uint32_t*>(ohr + i) = hi;
        *reinterpret_cast<uint32_t*>(olr + i) = lo;
    }
}

// ---------------- RoPE + split q (hi/lo), k (hi only) ------------------------
__global__ void rope_split_kernel(const float* __restrict__ qkv,
                                  const float* __restrict__ tc,
                                  const float* __restrict__ ts,
                                  f16* __restrict__ qh, f16* __restrict__ ql,
                                  f16* __restrict__ kh)
{
    const int t = blockIdx.x;
    const int d0 = threadIdx.x * 16;
    const size_t src = (size_t)t * D3_ + d0;   // q at col 0, k at col D_
    const size_t dst = (size_t)t * D_ + d0;

#pragma unroll
    for (int j = 0; j < 8; j++) {
        const int d = d0 + 2 * j;
        float2 qv = *reinterpret_cast<const float2*>(qkv + src + 2 * j);
        float2 kv = *reinterpret_cast<const float2*>(qkv + src + D_ + 2 * j);
        const int dd = d & (DH_ - 1);
        if (dd < RR_) {
            const int i = dd >> 1;
            const float c = tc[t * 32 + i];
            const float s = ts[t * 32 + i];
            float q0 = qv.x, q1 = qv.y;
            qv.x = q0 * c - q1 * s; qv.y = q1 * c + q0 * s;
            float k0 = kv.x, k1 = kv.y;
            kv.x = k0 * c - k1 * s; kv.y = k1 * c + k0 * s;
        }
        uint32_t hi, lo;
        split2(qv.x, qv.y, hi, lo);
        *reinterpret_cast<uint32_t*>(qh + dst + 2 * j) = hi;
        *reinterpret_cast<uint32_t*>(ql + dst + 2 * j) = lo;
        *reinterpret_cast<uint32_t*>(kh + dst + 2 * j) = pack_hi2(kv.x, kv.y);
    }
}

// ---------------- softmax (causal-limited) -> fp16 hi ------------------------
__global__ void softmax_split_kernel(const float* __restrict__ scores,
                                     f16* __restrict__ ph)
{
    const size_t row = blockIdx.x;
    const int t = (int)(row & (T_ - 1));
    const int L = ((t >> 7) + 1) << 7;          // causal row length, mult of 128
    const float* r = scores + row * (size_t)T_;
    const int base = threadIdx.x * 8;
    const bool act = base < L;                  // 8-blocks fully in or out
    __shared__ float red[256];

    float v[8];
    if (act) {
#pragma unroll
        for (int i = 0; i < 8; i += 4)
            *reinterpret_cast<float4*>(v + i) =
                *reinterpret_cast<const float4*>(r + base + i);
    } else {
#pragma unroll
        for (int i = 0; i < 8; i++) v[i] = -1e30f;
    }

    float m = -1e30f;
#pragma unroll
    for (int i = 0; i < 8; i++) m = fmaxf(m, v[i]);
    red[threadIdx.x] = m; __syncthreads();
    for (int o = 128; o > 0; o >>= 1) {
        if (threadIdx.x < o) red[threadIdx.x] = fmaxf(red[threadIdx.x], red[threadIdx.x + o]);
        __syncthreads();
    }
    m = red[0]; __syncthreads();

    float s = 0.f;
    if (act) {
#pragma unroll
        for (int i = 0; i < 8; i++) { v[i] = __expf(v[i] - m); s += v[i]; }
    }
    red[threadIdx.x] = s; __syncthreads();
    for (int o = 128; o > 0; o >>= 1) {
        if (threadIdx.x < o) red[threadIdx.x] += red[threadIdx.x + o];
        __syncthreads();
    }
    const float invs = 1.0f / red[0];

    if (act) {
        f16* phr = ph + row * (size_t)T_ + base;
#pragma unroll
        for (int i = 0; i < 8; i += 2) {
            *reinterpret_cast<uint32_t*>(phr + i) =
                pack_hi2(v[i] * invs, v[i + 1] * invs);
        }
    }
}

// ---------------- transpose: in[R][C] fp32 -> out[C][R] fp16 hi only ---------
__global__ void transpose_hi_kernel(const float* __restrict__ in,
                                    f16* __restrict__ oh, int R, int C)
{
    __shared__ float t[32][33];
    const int c0 = blockIdx.x * 32, r0 = blockIdx.y * 32;
    const int x = threadIdx.x, y = threadIdx.y;
#pragma unroll
    for (int i = 0; i < 32; i += 8)
        t[y + i][x] = in[(size_t)(r0 + y + i) * C + c0 + x];
    __syncthreads();
#pragma unroll
    for (int i = 0; i < 32; i += 8) {
        const size_t o = (size_t)(c0 + y + i) * R + r0 + x;
        oh[o] = __float2half_rn(t[x][y + i]);
    }
}

// per-head transpose of V (cols 2D.. of fused qkv): vt[h][d][t], hi only
__global__ void transpose_v_hi_kernel(const float* __restrict__ qkv,
                                      f16* __restrict__ oh)
{
    __shared__ float s[32][33];
    const int h = blockIdx.z;
    const int d0 = blockIdx.x * 32, t0 = blockIdx.y * 32;
    const int x = threadIdx.x, y = threadIdx.y;
#pragma unroll
    for (int i = 0; i < 32; i += 8)
        s[y + i][x] = qkv[(size_t)(t0 + y + i) * D3_ + 2 * D_ + (size_t)h * DH_ + d0 + x];
    __syncthreads();
#pragma unroll
    for (int i = 0; i < 32; i += 8) {
        const size_t o = ((size_t)h * DH_ + d0 + y + i) * T_ + t0 + x;
        oh[o] = __float2half_rn(s[x][y + i]);
    }
}

// ---------------- split-fp16 GEMM: C = (Ah [+ Al]) @ Bh^T --------------------
// NPROD=2: A = Ah + Al.  NPROD=1: A = Ah only (Al never loaded).
// climit != 0: effective K for row-block at m0 is (m0 + MT) (causal PV).
// Chi != nullptr, Clo == nullptr -> epilogue writes hi plane only.
enum { E_F32 = 0, E_CAUSAL = 1, E_SPLIT = 2, E_GELU_SPLIT = 3, E_BIASRES = 4 };

template <int NPROD>
__global__ void __launch_bounds__(256, 1)
mma_gemm(int K, int climit,
         const f16* __restrict__ Ah, const f16* __restrict__ Al,
         int lda, long long sA,
         const f16* __restrict__ Bh, int ldb, long long sB,
         float* __restrict__ C, f16* __restrict__ Chi, f16* __restrict__ Clo,
         int ldc, long long sC,
         float alpha, int epi,
         const float* __restrict__ bias,
         const float* __restrict__ res, int ldres)
{
    extern __shared__ char smem[];
    const uint32_t sbase = smem_u32(smem);
    const int tid = threadIdx.x;
    const int wid = tid >> 5, lid = tid & 31;
    const int m0 = blockIdx.y * MT, n0 = blockIdx.x * NTT;

    Ah += (size_t)blockIdx.z * sA;
    if (NPROD == 2) Al += (size_t)blockIdx.z * sA;
    Bh += (size_t)blockIdx.z * sB;
    if (C)   C   += (size_t)blockIdx.z * sC;
    if (Chi) Chi += (size_t)blockIdx.z * sC;
    if (Clo) Clo += (size_t)blockIdx.z * sC;

    // fully-masked causal tile: nothing downstream reads it -> skip entirely
    if (epi == E_CAUSAL && n0 > m0 + (MT - 1)) return;

    const int Keff = climit ? (m0 + MT) : K;   // causal K-limit (multiple of KC)

    const int wm = (wid >> 2) * 64;
    const int wn = (wid & 3) * 32;

    float acc[4][4][4];
#pragma unroll
    for (int i = 0; i < 4; i++)
#pragma unroll
        for (int j = 0; j < 4; j++)
#pragma unroll
            for (int r = 0; r < 4; r++) acc[i][j][r] = 0.f;

    const int lrow = tid >> 3;     // 0..31 (plus p*32)
    const int lcol = tid & 7;      // 16B column within 128B row

    const int NC = Keff / KC;

#define ISSUE_STAGE(stg, kc_) do {                                              \
        const int kc__ = (kc_);                                                 \
        _Pragma("unroll")                                                       \
        for (int p = 0; p < 4; p++) {                                           \
            const int row = lrow + p * 32;                                      \
            const uint32_t dsw = SWZ((uint32_t)(row * 128 + lcol * 16));        \
            const uint32_t db = sbase + (uint32_t)(stg) * STAGE_B + dsw;        \
            CP16(db,          Ah + (size_t)(m0 + row) * lda + kc__ + lcol * 8); \
            if (NPROD == 2)                                                     \
                CP16(db + 16384u, Al + (size_t)(m0 + row) * lda + kc__ + lcol * 8); \
            CP16(db + 32768u, Bh + (size_t)(n0 + row) * ldb + kc__ + lcol * 8); \
        }                                                                       \
        CPCOMMIT();                                                             \
    } while (0)

    ISSUE_STAGE(0, 0);
    ISSUE_STAGE(1, KC);

    const uint32_t aRawBase = (uint32_t)((wm + (lid & 15)) * 128 + (lid >> 4) * 16);
    const uint32_t bRawBase = (uint32_t)((wn + (lid & 7) + ((lid >> 4) << 3)) * 128
                                         + (((lid >> 3) & 1) << 4));

    for (int c = 0; c < NC; ++c) {
        if (c + 2 < NC) {
            ISSUE_STAGE((c + 2) % NSTAGE, (c + 2) * KC);
            CPWAIT2();
        } else {
            CPWAIT0();
        }
        __syncthreads();

        const uint32_t st = sbase + (uint32_t)(c % NSTAGE) * STAGE_B;

#pragma unroll
        for (int ks = 0; ks < 4; ks++) {
            const uint32_t kb = (uint32_t)ks * 32;
            uint32_t ah[4][4], al[4][4], bh[4][2];
#pragma unroll
            for (int i = 0; i < 4; i++) {
                const uint32_t raw = aRawBase + (uint32_t)i * (16 * 128) + kb;
                ldm_x4(ah[i], st + SWZ(raw));
                if (NPROD == 2) ldm_x4(al[i], st + 16384u + SWZ(raw));
            }
#pragma unroll
            for (int j2 = 0; j2 < 2; j2++) {
                const uint32_t raw = bRawBase + (uint32_t)j2 * (16 * 128) + kb;
                uint32_t t4[4];
                ldm_x4(t4, st + 32768u + SWZ(raw));
                bh[2 * j2][0] = t4[0]; bh[2 * j2][1] = t4[1];
                bh[2 * j2 + 1][0] = t4[2]; bh[2 * j2 + 1][1] = t4[3];
            }
#pragma unroll
            for (int i = 0; i < 4; i++)
#pragma unroll
                for (int j = 0; j < 4; j++) {
                    mma16816(acc[i][j], ah[i], bh[j]);
                    if (NPROD == 2) mma16816(acc[i][j], al[i], bh[j]);
                }
        }
        __syncthreads();
    }
#undef ISSUE_STAGE

    // ---------------- epilogue ----------------
    const int tr = lid >> 2, tc = (lid & 3) * 2;
#pragma unroll
    for (int i = 0; i < 4; i++) {
        const int m1 = m0 + wm + i * 16 + tr;
        const int m2 = m1 + 8;
#pragma unroll
        for (int j = 0; j < 4; j++) {
            const int n = n0 + wn + j * 8 + tc;
            float v0 = acc[i][j][0] * alpha;
            float v1 = acc[i][j][1] * alpha;
            float v2 = acc[i][j][2] * alpha;
            float v3 = acc[i][j][3] * alpha;
            if (epi == E_CAUSAL) {
                if (n     > m1) v0 = -1e10f;
                if (n + 1 > m1) v1 = -1e10f;
                if (n     > m2) v2 = -1e10f;
                if (n + 1 > m2) v3 = -1e10f;
            } else if (epi == E_GELU_SPLIT) {
                const float b0 = bias[n], b1 = bias[n + 1];
                v0 = gelu_f(v0 + b0); v1 = gelu_f(v1 + b1);
                v2 = gelu_f(v2 + b0); v3 = gelu_f(v3 + b1);
            } else if (epi == E_BIASRES) {
                const float b0 = bias[n], b1 = bias[n + 1];
                const float2 r1 = *reinterpret_cast<const float2*>(res + (size_t)m1 * ldres + n);
                const float2 r2 = *reinterpret_cast<const float2*>(res + (size_t)m2 * ldres + n);
                v0 += b0 + r1.x; v1 += b1 + r1.y;
                v2 += b0 + r2.x; v3 += b1 + r2.y;
            }
            if (epi == E_SPLIT || epi == E_GELU_SPLIT) {
                if (Clo) {
                    uint32_t hi, lo;
                    split2(v0, v1, hi, lo);
                    *reinterpret_cast<uint32_t*>(Chi + (size_t)m1 * ldc + n) = hi;
                    *reinterpret_cast<uint32_t*>(Clo + (size_t)m1 * ldc + n) = lo;
                    split2(v2, v3, hi, lo);
                    *reinterpret_cast<uint32_t*>(Chi + (size_t)m2 * ldc + n) = hi;
                    *reinterpret_cast<uint32_t*>(Clo + (size_t)m2 * ldc + n) = lo;
                } else {
                    *reinterpret_cast<uint32_t*>(Chi + (size_t)m1 * ldc + n) = pack_hi2(v0, v1);
                    *reinterpret_cast<uint32_t*>(Chi + (size_t)m2 * ldc + n) = pack_hi2(v2, v3);
                }
            } else {
                *reinterpret_cast<float2*>(C + (size_t)m1 * ldc + n) = make_float2(v0, v1);
                *reinterpret_cast<float2*>(C + (size_t)m2 * ldc + n) = make_float2(v2, v3);
            }
        }
    }
}

// ---------------- launch -----------------------------------------------------
extern "C" void kernel_launch(void* const* d_in, const int* in_sizes, int n_in,
                              void* d_out, int out_size)
{
    const float* x    = (const float*)d_in[0];
    const float* ln_s = (const float*)d_in[1];
    const float* ln_o = (const float*)d_in[2];
    const float* wq   = (const float*)d_in[3];
    const float* wk   = (const float*)d_in[4];
    const float* wv   = (const float*)d_in[5];
    const float* wo   = (const float*)d_in[6];
    const float* w1   = (const float*)d_in[7];
    const float* b1   = (const float*)d_in[8];
    const float* w2   = (const float*)d_in[9];
    const float* b2   = (const float*)d_in[10];
    float* out = (float*)d_out;

    float *qkv, *attn, *sc, *tcs, *tsn;
    f16 *xnh, *xnl, *qh, *ql, *kh, *vth, *sch;
    f16 *cxh, *hbh;
    f16 *wqkvh, *woh, *w1h, *w2h;

    cudaGetSymbolAddress((void**)&qkv,  g_qkv);
    cudaGetSymbolAddress((void**)&attn, g_attn);
    cudaGetSymbolAddress((void**)&sc,   g_sc);
    cudaGetSymbolAddress((void**)&tcs,  g_tcos);
    cudaGetSymbolAddress((void**)&tsn,  g_tsin);
    cudaGetSymbolAddress((void**)&xnh,  g_xnh);
    cudaGetSymbolAddress((void**)&xnl,  g_xnl);
    cudaGetSymbolAddress((void**)&qh,   g_qh);
    cudaGetSymbolAddress((void**)&ql,   g_ql);
    cudaGetSymbolAddress((void**)&kh,   g_kh);
    cudaGetSymbolAddress((void**)&vth,  g_vth);
    cudaGetSymbolAddress((void**)&sch,  g_sch);
    cudaGetSymbolAddress((void**)&cxh,  g_cxh);
    cudaGetSymbolAddress((void**)&hbh,  g_hbh);
    cudaGetSymbolAddress((void**)&wqkvh, g_wqkvh);
    cudaGetSymbolAddress((void**)&woh,  g_woh);
    cudaGetSymbolAddress((void**)&w1h,  g_w1h);
    cudaGetSymbolAddress((void**)&w2h,  g_w2h);

    cudaFuncSetAttribute(mma_gemm<2>, cudaFuncAttributeMaxDynamicSharedMemorySize,
                         GEMM_SMEM_BYTES);
    cudaFuncSetAttribute(mma_gemm<1>, cudaFuncAttributeMaxDynamicSharedMemorySize,
                         GEMM_SMEM_BYTES);

    const dim3 tb32(32, 8);

    // 0) RoPE table + weight transposes (hi only)
    rope_table_kernel<<<T_, 32>>>(tcs, tsn);
    transpose_hi_kernel<<<dim3(D_ / 32, D_ / 32), tb32>>>(wq, wqkvh, D_, D_);
    transpose_hi_kernel<<<dim3(D_ / 32, D_ / 32), tb32>>>(wk, wqkvh + (size_t)D_ * D_, D_, D_);
    transpose_hi_kernel<<<dim3(D_ / 32, D_ / 32), tb32>>>(wv, wqkvh + (size_t)2 * D_ * D_, D_, D_);
    transpose_hi_kernel<<<dim3(FF_ / 32, D_ / 32), tb32>>>(w1, w1h, D_, FF_);   // w1h: [FF][D]
    transpose_hi_kernel<<<dim3(D_ / 32, FF_ / 32), tb32>>>(w2, w2h, FF_, D_);   // w2h: [D][FF]
    transpose_hi_kernel<<<dim3(D_ / 32, D_ / 32), tb32>>>(wo, woh, D_, D_);

    // 1) LayerNorm -> xn hi/lo
    ln_split_kernel<<<T_, 256>>>(x, ln_s, ln_o, xnh, xnl);

    // 2) fused QKV projection (2-product): [2048,4096]@[4096,12288]
    {
        dim3 g(D3_ / NTT, T_ / MT, 1);
        mma_gemm<2><<<g, 256, GEMM_SMEM_BYTES>>>(D_, 0, xnh, xnl, D_, 0, wqkvh, D_, 0,
            qkv, nullptr, nullptr, D3_, 0, 1.f, E_F32, nullptr, nullptr, 0);
    }

    // 3) RoPE + split q (hi/lo), k (hi)
    rope_split_kernel<<<T_, 256>>>(qkv, tcs, tsn, qh, ql, kh);

    // 4) V transpose (hi)
    transpose_v_hi_kernel<<<dim3(DH_ / 32, T_ / 32, H_), tb32>>>(qkv, vth);

    // 5) scores = scale * Q_h @ K_h^T + causal (2-product, masked tiles skipped)
    {
        dim3 g(T_ / NTT, T_ / MT, H_);
        mma_gemm<2><<<g, 256, GEMM_SMEM_BYTES>>>(DH_, 0,
            qh, ql, D_, DH_,
            kh, D_, DH_,
            sc, nullptr, nullptr, T_, (long long)T_ * T_,
            0.0625f, E_CAUSAL, nullptr, nullptr, 0);
    }

    // 6) softmax (causal length) -> P hi only
    softmax_split_kernel<<<H_ * T_, 256>>>(sc, sch);

    // 7) ctx = P_h @ V_h  (1-product, causal K-limit, hi out)
    {
        dim3 g(DH_ / NTT, T_ / MT, H_);
        mma_gemm<1><<<g, 256, GEMM_SMEM_BYTES>>>(T_, 1,
            sch, nullptr, T_, (long long)T_ * T_,
            vth, T_, (long long)DH_ * T_,
            nullptr, cxh, nullptr, D_, DH_,
            1.f, E_SPLIT, nullptr, nullptr, 0);
    }

    // 8) attn_out = ctx @ wo (1-product)
    {
        dim3 g(D_ / NTT, T_ / MT, 1);
        mma_gemm<1><<<g, 256, GEMM_SMEM_BYTES>>>(D_, 0, cxh, nullptr, D_, 0, woh, D_, 0,
            attn, nullptr, nullptr, D_, 0, 1.f, E_F32, nullptr, nullptr, 0);
    }

    // 9) h = gelu(xn @ w1 + b1)  (1-product, hi out) — w1h stride D_
    {
        dim3 g(FF_ / NTT, T_ / MT, 1);
        mma_gemm<1><<<g, 256, GEMM_SMEM_BYTES>>>(D_, 0, xnh, nullptr, D_, 0, w1h, D_, 0,
            nullptr, hbh, nullptr, FF_, 0, 1.f, E_GELU_SPLIT, b1, nullptr, 0);
    }

    // 10) out = h @ w2 + b2 + attn_out (1-product) — w2h stride FF_
    {
        dim3 g(D_ / NTT, T_ / MT, 1);
        mma_gemm<1><<<g, 256, GEMM_SMEM_BYTES>>>(FF_, 0, hbh, nullptr, FF_, 0, w2h, FF_, 0,
            out, nullptr, nullptr, D_, 0, 1.f, E_BIASRES, b2, attn, D_);
    }
}

// round 15
// speedup vs baseline: 2.7057x; 1.1438x over previous
#include <cuda_runtime.h>
#include <cuda_fp16.h>
#include <math.h>
#include <stdint.h>

#define T_  2048
#define D_  4096
#define D3_ 12288
#define H_  16
#define DH_ 256
#define RR_ 64
#define FF_ 16384

// GEMM tiling — pure fp16 stages: Ah(16K)+Bh(16K)
#define MT   128
#define NTT  128
#define KC   64
#define STAGE_B 32768
#define NSTAGE 3
#define GEMM_SMEM_BYTES (NSTAGE * STAGE_B)   // 96KB

typedef __half f16;

// ---------------- scratch (static device arrays: allocation-free) -----------
__device__ float g_qkv [(size_t)T_ * D3_];       // fused q|k|v fp32
__device__ float g_attn[(size_t)T_ * D_];
__device__ float g_sc  [(size_t)H_ * T_ * T_];
__device__ float g_tcos[(size_t)T_ * 32];
__device__ float g_tsin[(size_t)T_ * 32];

__device__ f16 g_xnh [(size_t)T_ * D_];
__device__ f16 g_qh  [(size_t)T_ * D_];
__device__ f16 g_kh  [(size_t)T_ * D_];
__device__ f16 g_vth [(size_t)H_ * DH_ * T_];
__device__ f16 g_sch [(size_t)H_ * T_ * T_];
__device__ f16 g_cxh [(size_t)T_ * D_];
__device__ f16 g_hbh [(size_t)T_ * FF_];
__device__ f16 g_wqkvh[(size_t)D3_ * D_];        // fused wq|wk|wv transposed
__device__ f16 g_woh [(size_t)D_ * D_];
__device__ f16 g_w1h [(size_t)FF_ * D_];         // [FF][D], row stride D
__device__ f16 g_w2h [(size_t)D_ * FF_];         // [D][FF], row stride FF

// ---------------- helpers ----------------------------------------------------
__device__ __forceinline__ uint32_t smem_u32(const void* p) {
    uint32_t a;
    asm("{ .reg .u64 t; cvta.to.shared.u64 t, %1; cvt.u32.u64 %0, t; }"
        : "=r"(a) : "l"(p));
    return a;
}

#define SWZ(o) ((o) ^ (((o) >> 3) & 0x70))

#define CP16(dst, src) \
    asm volatile("cp.async.cg.shared.global [%0], [%1], 16;" \
                 :: "r"(dst), "l"(src))
#define CPCOMMIT() asm volatile("cp.async.commit_group;" ::: "memory")
#define CPWAIT2()  asm volatile("cp.async.wait_group 2;" ::: "memory")
#define CPWAIT0()  asm volatile("cp.async.wait_group 0;" ::: "memory")

__device__ __forceinline__ void ldm_x4(uint32_t* r, uint32_t a) {
    asm volatile("ldmatrix.sync.aligned.m8n8.x4.shared.b16 {%0,%1,%2,%3}, [%4];"
                 : "=r"(r[0]), "=r"(r[1]), "=r"(r[2]), "=r"(r[3]) : "r"(a));
}

__device__ __forceinline__ void mma16816(float* d, const uint32_t* a, const uint32_t* b) {
    asm volatile("mma.sync.aligned.m16n8k16.row.col.f32.f16.f16.f32 "
                 "{%0,%1,%2,%3}, {%4,%5,%6,%7}, {%8,%9}, {%0,%1,%2,%3};"
                 : "+f"(d[0]), "+f"(d[1]), "+f"(d[2]), "+f"(d[3])
                 : "r"(a[0]), "r"(a[1]), "r"(a[2]), "r"(a[3]),
                   "r"(b[0]), "r"(b[1]));
}

__device__ __forceinline__ uint32_t pack_hi2(float x, float y) {
    f16 hx = __float2half_rn(x);
    f16 hy = __float2half_rn(y);
    return ((uint32_t)__half_as_ushort(hy) << 16) | (uint32_t)__half_as_ushort(hx);
}

__device__ __forceinline__ float gelu_f(float x)
{
    const float x3 = x * x * x;
    return 0.5f * x * (1.0f + tanhf(0.7978845608028654f * (x + 0.044715f * x3)));
}

// ---------------- RoPE table (double-precision, computed once per launch) ----
__global__ void rope_table_kernel(float* __restrict__ tc, float* __restrict__ ts)
{
    const int t = blockIdx.x;
    const int i = threadIdx.x;          // 0..31
    const double inv = pow(10000.0, -2.0 * (double)i / (double)RR_);
    const double ang = (double)t * inv;
    tc[t * 32 + i] = (float)cos(ang);
    ts[t * 32 + i] = (float)sin(ang);
}

// ---------------- LayerNorm -> fp16 ------------------------------------------
__global__ void ln_kernel(const float* __restrict__ x,
                          const float* __restrict__ scale,
                          const float* __restrict__ offset,
                          f16* __restrict__ oh)
{
    const int t = blockIdx.x;
    const float* xr = x + (size_t)t * D_;
    const int base = threadIdx.x * 16;
    __shared__ float red[256];

    float v[16];
#pragma unroll
    for (int i = 0; i < 16; i += 4)
        *reinterpret_cast<float4*>(v + i) =
            *reinterpret_cast<const float4*>(xr + base + i);

    float s = 0.f;
#pragma unroll
    for (int i = 0; i < 16; i++) s += v[i];
    red[threadIdx.x] = s; __syncthreads();
    for (int o = 128; o > 0; o >>= 1) {
        if (threadIdx.x < o) red[threadIdx.x] += red[threadIdx.x + o];
        __syncthreads();
    }
    const float mean = red[0] * (1.0f / D_);
    __syncthreads();

    float vv = 0.f;
#pragma unroll
    for (int i = 0; i < 16; i++) { float d = v[i] - mean; vv += d * d; }
    red[threadIdx.x] = vv; __syncthreads();
    for (int o = 128; o > 0; o >>= 1) {
        if (threadIdx.x < o) red[threadIdx.x] += red[threadIdx.x + o];
        __syncthreads();
    }
    const float rstd = rsqrtf(red[0] * (1.0f / D_) + 1e-5f);

    f16* ohr = oh + (size_t)t * D_ + base;
#pragma unroll
    for (int i = 0; i < 16; i += 2) {
        float y0 = (v[i]     - mean) * rstd * scale[base + i]     + offset[base + i];
        float y1 = (v[i + 1] - mean) * rstd * scale[base + i + 1] + offset[base + i + 1];
        *reinterpret_cast<uint32_t*>(ohr + i) = pack_hi2(y0, y1);
    }
}

// ---------------- RoPE -> q, k fp16 ------------------------------------------
__global__ void rope_kernel(const float* __restrict__ qkv,
                            const float* __restrict__ tc,
                            const float* __restrict__ ts,
                            f16* __restrict__ qh, f16* __restrict__ kh)
{
    const int t = blockIdx.x;
    const int d0 = threadIdx.x * 16;
    const size_t src = (size_t)t * D3_ + d0;   // q at col 0, k at col D_
    const size_t dst = (size_t)t * D_ + d0;

#pragma unroll
    for (int j = 0; j < 8; j++) {
        const int d = d0 + 2 * j;
        float2 qv = *reinterpret_cast<const float2*>(qkv + src + 2 * j);
        float2 kv = *reinterpret_cast<const float2*>(qkv + src + D_ + 2 * j);
        const int dd = d & (DH_ - 1);
        if (dd < RR_) {
            const int i = dd >> 1;
            const float c = tc[t * 32 + i];
            const float s = ts[t * 32 + i];
            float q0 = qv.x, q1 = qv.y;
            qv.x = q0 * c - q1 * s; qv.y = q1 * c + q0 * s;
            float k0 = kv.x, k1 = kv.y;
            kv.x = k0 * c - k1 * s; kv.y = k1 * c + k0 * s;
        }
        *reinterpret_cast<uint32_t*>(qh + dst + 2 * j) = pack_hi2(qv.x, qv.y);
        *reinterpret_cast<uint32_t*>(kh + dst + 2 * j) = pack_hi2(kv.x, kv.y);
    }
}

// ---------------- softmax (causal-limited) -> fp16 ---------------------------
__global__ void softmax_kernel(const float* __restrict__ scores,
                               f16* __restrict__ ph)
{
    const size_t row = blockIdx.x;
    const int t = (int)(row & (T_ - 1));
    const int L = ((t >> 7) + 1) << 7;          // causal row length, mult of 128
    const float* r = scores + row * (size_t)T_;
    const int base = threadIdx.x * 8;
    const bool act = base < L;                  // 8-blocks fully in or out
    __shared__ float red[256];

    float v[8];
    if (act) {
#pragma unroll
        for (int i = 0; i < 8; i += 4)
            *reinterpret_cast<float4*>(v + i) =
                *reinterpret_cast<const float4*>(r + base + i);
    } else {
#pragma unroll
        for (int i = 0; i < 8; i++) v[i] = -1e30f;
    }

    float m = -1e30f;
#pragma unroll
    for (int i = 0; i < 8; i++) m = fmaxf(m, v[i]);
    red[threadIdx.x] = m; __syncthreads();
    for (int o = 128; o > 0; o >>= 1) {
        if (threadIdx.x < o) red[threadIdx.x] = fmaxf(red[threadIdx.x], red[threadIdx.x + o]);
        __syncthreads();
    }
    m = red[0]; __syncthreads();

    float s = 0.f;
    if (act) {
#pragma unroll
        for (int i = 0; i < 8; i++) { v[i] = __expf(v[i] - m); s += v[i]; }
    }
    red[threadIdx.x] = s; __syncthreads();
    for (int o = 128; o > 0; o >>= 1) {
        if (threadIdx.x < o) red[threadIdx.x] += red[threadIdx.x + o];
        __syncthreads();
    }
    const float invs = 1.0f / red[0];

    if (act) {
        f16* phr = ph + row * (size_t)T_ + base;
#pragma unroll
        for (int i = 0; i < 8; i += 2) {
            *reinterpret_cast<uint32_t*>(phr + i) =
                pack_hi2(v[i] * invs, v[i + 1] * invs);
        }
    }
}

// ---------------- transpose: in[R][C] fp32 -> out[C][R] fp16 ------------------
__global__ void transpose_hi_kernel(const float* __restrict__ in,
                                    f16* __restrict__ oh, int R, int C)
{
    __shared__ float t[32][33];
    const int c0 = blockIdx.x * 32, r0 = blockIdx.y * 32;
    const int x = threadIdx.x, y = threadIdx.y;
#pragma unroll
    for (int i = 0; i < 32; i += 8)
        t[y + i][x] = in[(size_t)(r0 + y + i) * C + c0 + x];
    __syncthreads();
#pragma unroll
    for (int i = 0; i < 32; i += 8) {
        const size_t o = (size_t)(c0 + y + i) * R + r0 + x;
        oh[o] = __float2half_rn(t[x][y + i]);
    }
}

// per-head transpose of V (cols 2D.. of fused qkv): vt[h][d][t]
__global__ void transpose_v_hi_kernel(const float* __restrict__ qkv,
                                      f16* __restrict__ oh)
{
    __shared__ float s[32][33];
    const int h = blockIdx.z;
    const int d0 = blockIdx.x * 32, t0 = blockIdx.y * 32;
    const int x = threadIdx.x, y = threadIdx.y;
#pragma unroll
    for (int i = 0; i < 32; i += 8)
        s[y + i][x] = qkv[(size_t)(t0 + y + i) * D3_ + 2 * D_ + (size_t)h * DH_ + d0 + x];
    __syncthreads();
#pragma unroll
    for (int i = 0; i < 32; i += 8) {
        const size_t o = ((size_t)h * DH_ + d0 + y + i) * T_ + t0 + x;
        oh[o] = __float2half_rn(s[x][y + i]);
    }
}

// ---------------- fp16 GEMM: C = A @ B^T (fp32 accum) ------------------------
// climit != 0: effective K for row-block at m0 is (m0 + MT) (causal PV).
enum { E_F32 = 0, E_CAUSAL = 1, E_F16 = 2, E_GELU_F16 = 3, E_BIASRES = 4 };

__global__ void __launch_bounds__(256, 1)
mma_gemm(int K, int climit,
         const f16* __restrict__ A, int lda, long long sA,
         const f16* __restrict__ B, int ldb, long long sB,
         float* __restrict__ C, f16* __restrict__ Ch,
         int ldc, long long sC,
         float alpha, int epi,
         const float* __restrict__ bias,
         const float* __restrict__ res, int ldres)
{
    extern __shared__ char smem[];
    const uint32_t sbase = smem_u32(smem);
    const int tid = threadIdx.x;
    const int wid = tid >> 5, lid = tid & 31;
    const int m0 = blockIdx.y * MT, n0 = blockIdx.x * NTT;

    A += (size_t)blockIdx.z * sA;
    B += (size_t)blockIdx.z * sB;
    if (C)  C  += (size_t)blockIdx.z * sC;
    if (Ch) Ch += (size_t)blockIdx.z * sC;

    // fully-masked causal tile: nothing downstream reads it -> skip entirely
    if (epi == E_CAUSAL && n0 > m0 + (MT - 1)) return;

    const int Keff = climit ? (m0 + MT) : K;   // causal K-limit (multiple of KC)

    const int wm = (wid >> 2) * 64;
    const int wn = (wid & 3) * 32;

    float acc[4][4][4];
#pragma unroll
    for (int i = 0; i < 4; i++)
#pragma unroll
        for (int j = 0; j < 4; j++)
#pragma unroll
            for (int r = 0; r < 4; r++) acc[i][j][r] = 0.f;

    const int lrow = tid >> 3;     // 0..31 (plus p*32)
    const int lcol = tid & 7;      // 16B column within 128B row

    const int NC = Keff / KC;

#define ISSUE_STAGE(stg, kc_) do {                                              \
        const int kc__ = (kc_);                                                 \
        _Pragma("unroll")                                                       \
        for (int p = 0; p < 4; p++) {                                           \
            const int row = lrow + p * 32;                                      \
            const uint32_t dsw = SWZ((uint32_t)(row * 128 + lcol * 16));        \
            const uint32_t db = sbase + (uint32_t)(stg) * STAGE_B + dsw;        \
            CP16(db,          A + (size_t)(m0 + row) * lda + kc__ + lcol * 8);  \
            CP16(db + 16384u, B + (size_t)(n0 + row) * ldb + kc__ + lcol * 8);  \
        }                                                                       \
        CPCOMMIT();                                                             \
    } while (0)

    ISSUE_STAGE(0, 0);
    ISSUE_STAGE(1, KC);

    const uint32_t aRawBase = (uint32_t)((wm + (lid & 15)) * 128 + (lid >> 4) * 16);
    const uint32_t bRawBase = (uint32_t)((wn + (lid & 7) + ((lid >> 4) << 3)) * 128
                                         + (((lid >> 3) & 1) << 4));

    for (int c = 0; c < NC; ++c) {
        if (c + 2 < NC) {
            ISSUE_STAGE((c + 2) % NSTAGE, (c + 2) * KC);
            CPWAIT2();
        } else {
            CPWAIT0();
        }
        __syncthreads();

        const uint32_t st = sbase + (uint32_t)(c % NSTAGE) * STAGE_B;

#pragma unroll
        for (int ks = 0; ks < 4; ks++) {
            const uint32_t kb = (uint32_t)ks * 32;
            uint32_t ah[4][4], bh[4][2];
#pragma unroll
            for (int i = 0; i < 4; i++) {
                const uint32_t raw = aRawBase + (uint32_t)i * (16 * 128) + kb;
                ldm_x4(ah[i], st + SWZ(raw));
            }
#pragma unroll
            for (int j2 = 0; j2 < 2; j2++) {
                const uint32_t raw = bRawBase + (uint32_t)j2 * (16 * 128) + kb;
                uint32_t t4[4];
                ldm_x4(t4, st + 16384u + SWZ(raw));
                bh[2 * j2][0] = t4[0]; bh[2 * j2][1] = t4[1];
                bh[2 * j2 + 1][0] = t4[2]; bh[2 * j2 + 1][1] = t4[3];
            }
#pragma unroll
            for (int i = 0; i < 4; i++)
#pragma unroll
                for (int j = 0; j < 4; j++)
                    mma16816(acc[i][j], ah[i], bh[j]);
        }
        __syncthreads();
    }
#undef ISSUE_STAGE

    // ---------------- epilogue ----------------
    const int tr = lid >> 2, tc = (lid & 3) * 2;
#pragma unroll
    for (int i = 0; i < 4; i++) {
        const int m1 = m0 + wm + i * 16 + tr;
        const int m2 = m1 + 8;
#pragma unroll
        for (int j = 0; j < 4; j++) {
            const int n = n0 + wn + j * 8 + tc;
            float v0 = acc[i][j][0] * alpha;
            float v1 = acc[i][j][1] * alpha;
            float v2 = acc[i][j][2] * alpha;
            float v3 = acc[i][j][3] * alpha;
            if (epi == E_CAUSAL) {
                if (n     > m1) v0 = -1e10f;
                if (n + 1 > m1) v1 = -1e10f;
                if (n     > m2) v2 = -1e10f;
                if (n + 1 > m2) v3 = -1e10f;
            } else if (epi == E_GELU_F16) {
                const float b0 = bias[n], b1 = bias[n + 1];
                v0 = gelu_f(v0 + b0); v1 = gelu_f(v1 + b1);
                v2 = gelu_f(v2 + b0); v3 = gelu_f(v3 + b1);
            } else if (epi == E_BIASRES) {
                const float b0 = bias[n], b1 = bias[n + 1];
                const float2 r1 = *reinterpret_cast<const float2*>(res + (size_t)m1 * ldres + n);
                const float2 r2 = *reinterpret_cast<const float2*>(res + (size_t)m2 * ldres + n);
                v0 += b0 + r1.x; v1 += b1 + r1.y;
                v2 += b0 + r2.x; v3 += b1 + r2.y;
            }
            if (epi == E_F16 || epi == E_GELU_F16) {
                *reinterpret_cast<uint32_t*>(Ch + (size_t)m1 * ldc + n) = pack_hi2(v0, v1);
                *reinterpret_cast<uint32_t*>(Ch + (size_t)m2 * ldc + n) = pack_hi2(v2, v3);
            } else {
                *reinterpret_cast<float2*>(C + (size_t)m1 * ldc + n) = make_float2(v0, v1);
                *reinterpret_cast<float2*>(C + (size_t)m2 * ldc + n) = make_float2(v2, v3);
            }
        }
    }
}

// ---------------- launch -----------------------------------------------------
extern "C" void kernel_launch(void* const* d_in, const int* in_sizes, int n_in,
                              void* d_out, int out_size)
{
    const float* x    = (const float*)d_in[0];
    const float* ln_s = (const float*)d_in[1];
    const float* ln_o = (const float*)d_in[2];
    const float* wq   = (const float*)d_in[3];
    const float* wk   = (const float*)d_in[4];
    const float* wv   = (const float*)d_in[5];
    const float* wo   = (const float*)d_in[6];
    const float* w1   = (const float*)d_in[7];
    const float* b1   = (const float*)d_in[8];
    const float* w2   = (const float*)d_in[9];
    const float* b2   = (const float*)d_in[10];
    float* out = (float*)d_out;

    float *qkv, *attn, *sc, *tcs, *tsn;
    f16 *xnh, *qh, *kh, *vth, *sch, *cxh, *hbh;
    f16 *wqkvh, *woh, *w1h, *w2h;

    cudaGetSymbolAddress((void**)&qkv,  g_qkv);
    cudaGetSymbolAddress((void**)&attn, g_attn);
    cudaGetSymbolAddress((void**)&sc,   g_sc);
    cudaGetSymbolAddress((void**)&tcs,  g_tcos);
    cudaGetSymbolAddress((void**)&tsn,  g_tsin);
    cudaGetSymbolAddress((void**)&xnh,  g_xnh);
    cudaGetSymbolAddress((void**)&qh,   g_qh);
    cudaGetSymbolAddress((void**)&kh,   g_kh);
    cudaGetSymbolAddress((void**)&vth,  g_vth);
    cudaGetSymbolAddress((void**)&sch,  g_sch);
    cudaGetSymbolAddress((void**)&cxh,  g_cxh);
    cudaGetSymbolAddress((void**)&hbh,  g_hbh);
    cudaGetSymbolAddress((void**)&wqkvh, g_wqkvh);
    cudaGetSymbolAddress((void**)&woh,  g_woh);
    cudaGetSymbolAddress((void**)&w1h,  g_w1h);
    cudaGetSymbolAddress((void**)&w2h,  g_w2h);

    cudaFuncSetAttribute(mma_gemm, cudaFuncAttributeMaxDynamicSharedMemorySize,
                         GEMM_SMEM_BYTES);

    const dim3 tb32(32, 8);

    // 0) RoPE table + weight transposes
    rope_table_kernel<<<T_, 32>>>(tcs, tsn);
    transpose_hi_kernel<<<dim3(D_ / 32, D_ / 32), tb32>>>(wq, wqkvh, D_, D_);
    transpose_hi_kernel<<<dim3(D_ / 32, D_ / 32), tb32>>>(wk, wqkvh + (size_t)D_ * D_, D_, D_);
    transpose_hi_kernel<<<dim3(D_ / 32, D_ / 32), tb32>>>(wv, wqkvh + (size_t)2 * D_ * D_, D_, D_);
    transpose_hi_kernel<<<dim3(FF_ / 32, D_ / 32), tb32>>>(w1, w1h, D_, FF_);   // w1h: [FF][D]
    transpose_hi_kernel<<<dim3(D_ / 32, FF_ / 32), tb32>>>(w2, w2h, FF_, D_);   // w2h: [D][FF]
    transpose_hi_kernel<<<dim3(D_ / 32, D_ / 32), tb32>>>(wo, woh, D_, D_);

    // 1) LayerNorm -> xn fp16
    ln_kernel<<<T_, 256>>>(x, ln_s, ln_o, xnh);

    // 2) fused QKV projection: [2048,4096]@[4096,12288]
    {
        dim3 g(D3_ / NTT, T_ / MT, 1);
        mma_gemm<<<g, 256, GEMM_SMEM_BYTES>>>(D_, 0, xnh, D_, 0, wqkvh, D_, 0,
            qkv, nullptr, D3_, 0, 1.f, E_F32, nullptr, nullptr, 0);
    }

    // 3) RoPE -> q, k fp16
    rope_kernel<<<T_, 256>>>(qkv, tcs, tsn, qh, kh);

    // 4) V transpose
    transpose_v_hi_kernel<<<dim3(DH_ / 32, T_ / 32, H_), tb32>>>(qkv, vth);

    // 5) scores = scale * Q_h @ K_h^T + causal (masked tiles skipped)
    {
        dim3 g(T_ / NTT, T_ / MT, H_);
        mma_gemm<<<g, 256, GEMM_SMEM_BYTES>>>(DH_, 0,
            qh, D_, DH_,
            kh, D_, DH_,
            sc, nullptr, T_, (long long)T_ * T_,
            0.0625f, E_CAUSAL, nullptr, nullptr, 0);
    }

    // 6) softmax (causal length) -> P fp16
    softmax_kernel<<<H_ * T_, 256>>>(sc, sch);

    // 7) ctx = P_h @ V_h  (causal K-limit, fp16 out)
    {
        dim3 g(DH_ / NTT, T_ / MT, H_);
        mma_gemm<<<g, 256, GEMM_SMEM_BYTES>>>(T_, 1,
            sch, T_, (long long)T_ * T_,
            vth, T_, (long long)DH_ * T_,
            nullptr, cxh, D_, DH_,
            1.f, E_F16, nullptr, nullptr, 0);
    }

    // 8) attn_out = ctx @ wo
    {
        dim3 g(D_ / NTT, T_ / MT, 1);
        mma_gemm<<<g, 256, GEMM_SMEM_BYTES>>>(D_, 0, cxh, D_, 0, woh, D_, 0,
            attn, nullptr, D_, 0, 1.f, E_F32, nullptr, nullptr, 0);
    }

    // 9) h = gelu(xn @ w1 + b1) (fp16 out) — w1h stride D_
    {
        dim3 g(FF_ / NTT, T_ / MT, 1);
        mma_gemm<<<g, 256, GEMM_SMEM_BYTES>>>(D_, 0, xnh, D_, 0, w1h, D_, 0,
            nullptr, hbh, FF_, 0, 1.f, E_GELU_F16, b1, nullptr, 0);
    }

    // 10) out = h @ w2 + b2 + attn_out — w2h stride FF_
    {
        dim3 g(D_ / NTT, T_ / MT, 1);
        mma_gemm<<<g, 256, GEMM_SMEM_BYTES>>>(FF_, 0, hbh, FF_, 0, w2h, FF_, 0,
            out, nullptr, D_, 0, 1.f, E_BIASRES, b2, attn, D_);
    }
}

// round 16
// speedup vs baseline: 2.7672x; 1.0227x over previous
#include <cuda_runtime.h>
#include <cuda_fp16.h>
#include <math.h>
#include <stdint.h>

#define T_  2048
#define D_  4096
#define D3_ 12288
#define H_  16
#define DH_ 256
#define RR_ 64
#define FF_ 16384

// GEMM tiling — pure fp16 stages: Ah(16K)+Bh(16K)
#define MT   128
#define NTT  128
#define KC   64
#define STAGE_B 32768
#define NSTAGE 3
#define GEMM_SMEM_BYTES (NSTAGE * STAGE_B)   // 96KB

typedef __half f16;

// ---------------- scratch (static device arrays: allocation-free) -----------
__device__ float g_attn[(size_t)T_ * D_];
__device__ float g_sc  [(size_t)H_ * T_ * T_];
__device__ float g_tcos[(size_t)T_ * 32];
__device__ float g_tsin[(size_t)T_ * 32];

__device__ f16 g_qkv16[(size_t)T_ * D3_];        // fused q|k|v fp16
__device__ f16 g_xnh [(size_t)T_ * D_];
__device__ f16 g_qh  [(size_t)T_ * D_];
__device__ f16 g_kh  [(size_t)T_ * D_];
__device__ f16 g_vth [(size_t)H_ * DH_ * T_];
__device__ f16 g_sch [(size_t)H_ * T_ * T_];
__device__ f16 g_cxh [(size_t)T_ * D_];
__device__ f16 g_hbh [(size_t)T_ * FF_];
__device__ f16 g_wqkvh[(size_t)D3_ * D_];        // fused wq|wk|wv transposed
__device__ f16 g_woh [(size_t)D_ * D_];
__device__ f16 g_w1h [(size_t)FF_ * D_];         // [FF][D], row stride D
__device__ f16 g_w2h [(size_t)D_ * FF_];         // [D][FF], row stride FF

// ---------------- helpers ----------------------------------------------------
__device__ __forceinline__ uint32_t smem_u32(const void* p) {
    uint32_t a;
    asm("{ .reg .u64 t; cvta.to.shared.u64 t, %1; cvt.u32.u64 %0, t; }"
        : "=r"(a) : "l"(p));
    return a;
}

#define SWZ(o) ((o) ^ (((o) >> 3) & 0x70))

#define CP16(dst, src) \
    asm volatile("cp.async.cg.shared.global [%0], [%1], 16;" \
                 :: "r"(dst), "l"(src))
#define CPCOMMIT() asm volatile("cp.async.commit_group;" ::: "memory")
#define CPWAIT2()  asm volatile("cp.async.wait_group 2;" ::: "memory")
#define CPWAIT0()  asm volatile("cp.async.wait_group 0;" ::: "memory")

__device__ __forceinline__ void ldm_x4(uint32_t* r, uint32_t a) {
    asm volatile("ldmatrix.sync.aligned.m8n8.x4.shared.b16 {%0,%1,%2,%3}, [%4];"
                 : "=r"(r[0]), "=r"(r[1]), "=r"(r[2]), "=r"(r[3]) : "r"(a));
}

__device__ __forceinline__ void mma16816(float* d, const uint32_t* a, const uint32_t* b) {
    asm volatile("mma.sync.aligned.m16n8k16.row.col.f32.f16.f16.f32 "
                 "{%0,%1,%2,%3}, {%4,%5,%6,%7}, {%8,%9}, {%0,%1,%2,%3};"
                 : "+f"(d[0]), "+f"(d[1]), "+f"(d[2]), "+f"(d[3])
                 : "r"(a[0]), "r"(a[1]), "r"(a[2]), "r"(a[3]),
                   "r"(b[0]), "r"(b[1]));
}

__device__ __forceinline__ uint32_t pack_hi2(float x, float y) {
    f16 hx = __float2half_rn(x);
    f16 hy = __float2half_rn(y);
    return ((uint32_t)__half_as_ushort(hy) << 16) | (uint32_t)__half_as_ushort(hx);
}

__device__ __forceinline__ float gelu_f(float x)
{
    const float x3 = x * x * x;
    return 0.5f * x * (1.0f + tanhf(0.7978845608028654f * (x + 0.044715f * x3)));
}

// ---------------- RoPE table (double-precision, computed once per launch) ----
__global__ void rope_table_kernel(float* __restrict__ tc, float* __restrict__ ts)
{
    const int t = blockIdx.x;
    const int i = threadIdx.x;          // 0..31
    const double inv = pow(10000.0, -2.0 * (double)i / (double)RR_);
    const double ang = (double)t * inv;
    tc[t * 32 + i] = (float)cos(ang);
    ts[t * 32 + i] = (float)sin(ang);
}

// ---------------- LayerNorm -> fp16 ------------------------------------------
__global__ void ln_kernel(const float* __restrict__ x,
                          const float* __restrict__ scale,
                          const float* __restrict__ offset,
                          f16* __restrict__ oh)
{
    const int t = blockIdx.x;
    const float* xr = x + (size_t)t * D_;
    const int base = threadIdx.x * 16;
    __shared__ float red[256];

    float v[16];
#pragma unroll
    for (int i = 0; i < 16; i += 4)
        *reinterpret_cast<float4*>(v + i) =
            *reinterpret_cast<const float4*>(xr + base + i);

    float s = 0.f;
#pragma unroll
    for (int i = 0; i < 16; i++) s += v[i];
    red[threadIdx.x] = s; __syncthreads();
    for (int o = 128; o > 0; o >>= 1) {
        if (threadIdx.x < o) red[threadIdx.x] += red[threadIdx.x + o];
        __syncthreads();
    }
    const float mean = red[0] * (1.0f / D_);
    __syncthreads();

    float vv = 0.f;
#pragma unroll
    for (int i = 0; i < 16; i++) { float d = v[i] - mean; vv += d * d; }
    red[threadIdx.x] = vv; __syncthreads();
    for (int o = 128; o > 0; o >>= 1) {
        if (threadIdx.x < o) red[threadIdx.x] += red[threadIdx.x + o];
        __syncthreads();
    }
    const float rstd = rsqrtf(red[0] * (1.0f / D_) + 1e-5f);

    f16* ohr = oh + (size_t)t * D_ + base;
#pragma unroll
    for (int i = 0; i < 16; i += 2) {
        float y0 = (v[i]     - mean) * rstd * scale[base + i]     + offset[base + i];
        float y1 = (v[i + 1] - mean) * rstd * scale[base + i + 1] + offset[base + i + 1];
        *reinterpret_cast<uint32_t*>(ohr + i) = pack_hi2(y0, y1);
    }
}

// ---------------- RoPE (fp16 qkv in) -> q, k fp16 ----------------------------
__global__ void rope_kernel(const f16* __restrict__ qkv,
                            const float* __restrict__ tc,
                            const float* __restrict__ ts,
                            f16* __restrict__ qh, f16* __restrict__ kh)
{
    const int t = blockIdx.x;
    const int d0 = threadIdx.x * 16;
    const size_t src = (size_t)t * D3_ + d0;   // q at col 0, k at col D_
    const size_t dst = (size_t)t * D_ + d0;

#pragma unroll
    for (int j = 0; j < 8; j++) {
        const int d = d0 + 2 * j;
        float2 qv = __half22float2(*reinterpret_cast<const __half2*>(qkv + src + 2 * j));
        float2 kv = __half22float2(*reinterpret_cast<const __half2*>(qkv + src + D_ + 2 * j));
        const int dd = d & (DH_ - 1);
        if (dd < RR_) {
            const int i = dd >> 1;
            const float c = tc[t * 32 + i];
            const float s = ts[t * 32 + i];
            float q0 = qv.x, q1 = qv.y;
            qv.x = q0 * c - q1 * s; qv.y = q1 * c + q0 * s;
            float k0 = kv.x, k1 = kv.y;
            kv.x = k0 * c - k1 * s; kv.y = k1 * c + k0 * s;
        }
        *reinterpret_cast<uint32_t*>(qh + dst + 2 * j) = pack_hi2(qv.x, qv.y);
        *reinterpret_cast<uint32_t*>(kh + dst + 2 * j) = pack_hi2(kv.x, kv.y);
    }
}

// ---------------- softmax (causal-limited, fp32 scores) -> fp16 --------------
__global__ void softmax_kernel(const float* __restrict__ scores,
                               f16* __restrict__ ph)
{
    const size_t row = blockIdx.x;
    const int t = (int)(row & (T_ - 1));
    const int L = ((t >> 7) + 1) << 7;          // causal row length, mult of 128
    const float* r = scores + row * (size_t)T_;
    const int base = threadIdx.x * 8;
    const bool act = base < L;                  // 8-blocks fully in or out
    __shared__ float red[256];

    float v[8];
    if (act) {
#pragma unroll
        for (int i = 0; i < 8; i += 4)
            *reinterpret_cast<float4*>(v + i) =
                *reinterpret_cast<const float4*>(r + base + i);
    } else {
#pragma unroll
        for (int i = 0; i < 8; i++) v[i] = -1e30f;
    }

    float m = -1e30f;
#pragma unroll
    for (int i = 0; i < 8; i++) m = fmaxf(m, v[i]);
    red[threadIdx.x] = m; __syncthreads();
    for (int o = 128; o > 0; o >>= 1) {
        if (threadIdx.x < o) red[threadIdx.x] = fmaxf(red[threadIdx.x], red[threadIdx.x + o]);
        __syncthreads();
    }
    m = red[0]; __syncthreads();

    float s = 0.f;
    if (act) {
#pragma unroll
        for (int i = 0; i < 8; i++) { v[i] = __expf(v[i] - m); s += v[i]; }
    }
    red[threadIdx.x] = s; __syncthreads();
    for (int o = 128; o > 0; o >>= 1) {
        if (threadIdx.x < o) red[threadIdx.x] += red[threadIdx.x + o];
        __syncthreads();
    }
    const float invs = 1.0f / red[0];

    if (act) {
        f16* phr = ph + row * (size_t)T_ + base;
#pragma unroll
        for (int i = 0; i < 8; i += 2) {
            *reinterpret_cast<uint32_t*>(phr + i) =
                pack_hi2(v[i] * invs, v[i + 1] * invs);
        }
    }
}

// ---------------- transpose: in[R][C] fp32 -> out[C][R] fp16 ------------------
__global__ void transpose_hi_kernel(const float* __restrict__ in,
                                    f16* __restrict__ oh, int R, int C)
{
    __shared__ float t[32][33];
    const int c0 = blockIdx.x * 32, r0 = blockIdx.y * 32;
    const int x = threadIdx.x, y = threadIdx.y;
#pragma unroll
    for (int i = 0; i < 32; i += 8)
        t[y + i][x] = in[(size_t)(r0 + y + i) * C + c0 + x];
    __syncthreads();
#pragma unroll
    for (int i = 0; i < 32; i += 8) {
        const size_t o = (size_t)(c0 + y + i) * R + r0 + x;
        oh[o] = __float2half_rn(t[x][y + i]);
    }
}

// per-head transpose of V (cols 2D.. of fp16 qkv): vt[h][d][t]
__global__ void transpose_v_hi_kernel(const f16* __restrict__ qkv,
                                      f16* __restrict__ oh)
{
    __shared__ f16 s[32][33];
    const int h = blockIdx.z;
    const int d0 = blockIdx.x * 32, t0 = blockIdx.y * 32;
    const int x = threadIdx.x, y = threadIdx.y;
#pragma unroll
    for (int i = 0; i < 32; i += 8)
        s[y + i][x] = qkv[(size_t)(t0 + y + i) * D3_ + 2 * D_ + (size_t)h * DH_ + d0 + x];
    __syncthreads();
#pragma unroll
    for (int i = 0; i < 32; i += 8) {
        const size_t o = ((size_t)h * DH_ + d0 + y + i) * T_ + t0 + x;
        oh[o] = s[x][y + i];
    }
}

// ---------------- fp16 GEMM: C = A @ B^T (fp32 accum) ------------------------
// climit != 0: effective K for row-block at m0 is (m0 + MT) (causal PV).
enum { E_F32 = 0, E_CAUSAL = 1, E_F16 = 2, E_GELU_F16 = 3, E_BIASRES = 4 };

__global__ void __launch_bounds__(256, 1)
mma_gemm(int K, int climit,
         const f16* __restrict__ A, int lda, long long sA,
         const f16* __restrict__ B, int ldb, long long sB,
         float* __restrict__ C, f16* __restrict__ Ch,
         int ldc, long long sC,
         float alpha, int epi,
         const float* __restrict__ bias,
         const float* __restrict__ res, int ldres)
{
    extern __shared__ char smem[];
    const uint32_t sbase = smem_u32(smem);
    const int tid = threadIdx.x;
    const int wid = tid >> 5, lid = tid & 31;
    const int m0 = blockIdx.y * MT, n0 = blockIdx.x * NTT;

    A += (size_t)blockIdx.z * sA;
    B += (size_t)blockIdx.z * sB;
    if (C)  C  += (size_t)blockIdx.z * sC;
    if (Ch) Ch += (size_t)blockIdx.z * sC;

    // fully-masked causal tile: nothing downstream reads it -> skip entirely
    if (epi == E_CAUSAL && n0 > m0 + (MT - 1)) return;

    const int Keff = climit ? (m0 + MT) : K;   // causal K-limit (multiple of KC)

    const int wm = (wid >> 2) * 64;
    const int wn = (wid & 3) * 32;

    float acc[4][4][4];
#pragma unroll
    for (int i = 0; i < 4; i++)
#pragma unroll
        for (int j = 0; j < 4; j++)
#pragma unroll
            for (int r = 0; r < 4; r++) acc[i][j][r] = 0.f;

    const int lrow = tid >> 3;     // 0..31 (plus p*32)
    const int lcol = tid & 7;      // 16B column within 128B row

    const int NC = Keff / KC;

#define ISSUE_STAGE(stg, kc_) do {                                              \
        const int kc__ = (kc_);                                                 \
        _Pragma("unroll")                                                       \
        for (int p = 0; p < 4; p++) {                                           \
            const int row = lrow + p * 32;                                      \
            const uint32_t dsw = SWZ((uint32_t)(row * 128 + lcol * 16));        \
            const uint32_t db = sbase + (uint32_t)(stg) * STAGE_B + dsw;        \
            CP16(db,          A + (size_t)(m0 + row) * lda + kc__ + lcol * 8);  \
            CP16(db + 16384u, B + (size_t)(n0 + row) * ldb + kc__ + lcol * 8);  \
        }                                                                       \
        CPCOMMIT();                                                             \
    } while (0)

    ISSUE_STAGE(0, 0);
    ISSUE_STAGE(1, KC);

    const uint32_t aRawBase = (uint32_t)((wm + (lid & 15)) * 128 + (lid >> 4) * 16);
    const uint32_t bRawBase = (uint32_t)((wn + (lid & 7) + ((lid >> 4) << 3)) * 128
                                         + (((lid >> 3) & 1) << 4));

    for (int c = 0; c < NC; ++c) {
        if (c + 2 < NC) {
            ISSUE_STAGE((c + 2) % NSTAGE, (c + 2) * KC);
            CPWAIT2();
        } else {
            CPWAIT0();
        }
        __syncthreads();

        const uint32_t st = sbase + (uint32_t)(c % NSTAGE) * STAGE_B;

#pragma unroll
        for (int ks = 0; ks < 4; ks++) {
            const uint32_t kb = (uint32_t)ks * 32;
            uint32_t ah[4][4], bh[4][2];
#pragma unroll
            for (int i = 0; i < 4; i++) {
                const uint32_t raw = aRawBase + (uint32_t)i * (16 * 128) + kb;
                ldm_x4(ah[i], st + SWZ(raw));
            }
#pragma unroll
            for (int j2 = 0; j2 < 2; j2++) {
                const uint32_t raw = bRawBase + (uint32_t)j2 * (16 * 128) + kb;
                uint32_t t4[4];
                ldm_x4(t4, st + 16384u + SWZ(raw));
                bh[2 * j2][0] = t4[0]; bh[2 * j2][1] = t4[1];
                bh[2 * j2 + 1][0] = t4[2]; bh[2 * j2 + 1][1] = t4[3];
            }
#pragma unroll
            for (int i = 0; i < 4; i++)
#pragma unroll
                for (int j = 0; j < 4; j++)
                    mma16816(acc[i][j], ah[i], bh[j]);
        }
        __syncthreads();
    }
#undef ISSUE_STAGE

    // ---------------- epilogue ----------------
    const int tr = lid >> 2, tc = (lid & 3) * 2;
#pragma unroll
    for (int i = 0; i < 4; i++) {
        const int m1 = m0 + wm + i * 16 + tr;
        const int m2 = m1 + 8;
#pragma unroll
        for (int j = 0; j < 4; j++) {
            const int n = n0 + wn + j * 8 + tc;
            float v0 = acc[i][j][0] * alpha;
            float v1 = acc[i][j][1] * alpha;
            float v2 = acc[i][j][2] * alpha;
            float v3 = acc[i][j][3] * alpha;
            if (epi == E_CAUSAL) {
                if (n     > m1) v0 = -1e10f;
                if (n + 1 > m1) v1 = -1e10f;
                if (n     > m2) v2 = -1e10f;
                if (n + 1 > m2) v3 = -1e10f;
            } else if (epi == E_GELU_F16) {
                const float b0 = bias[n], b1 = bias[n + 1];
                v0 = gelu_f(v0 + b0); v1 = gelu_f(v1 + b1);
                v2 = gelu_f(v2 + b0); v3 = gelu_f(v3 + b1);
            } else if (epi == E_BIASRES) {
                const float b0 = bias[n], b1 = bias[n + 1];
                const float2 r1 = *reinterpret_cast<const float2*>(res + (size_t)m1 * ldres + n);
                const float2 r2 = *reinterpret_cast<const float2*>(res + (size_t)m2 * ldres + n);
                v0 += b0 + r1.x; v1 += b1 + r1.y;
                v2 += b0 + r2.x; v3 += b1 + r2.y;
            }
            if (epi == E_F16 || epi == E_GELU_F16) {
                *reinterpret_cast<uint32_t*>(Ch + (size_t)m1 * ldc + n) = pack_hi2(v0, v1);
                *reinterpret_cast<uint32_t*>(Ch + (size_t)m2 * ldc + n) = pack_hi2(v2, v3);
            } else {
                *reinterpret_cast<float2*>(C + (size_t)m1 * ldc + n) = make_float2(v0, v1);
                *reinterpret_cast<float2*>(C + (size_t)m2 * ldc + n) = make_float2(v2, v3);
            }
        }
    }
}

// ---------------- launch -----------------------------------------------------
extern "C" void kernel_launch(void* const* d_in, const int* in_sizes, int n_in,
                              void* d_out, int out_size)
{
    const float* x    = (const float*)d_in[0];
    const float* ln_s = (const float*)d_in[1];
    const float* ln_o = (const float*)d_in[2];
    const float* wq   = (const float*)d_in[3];
    const float* wk   = (const float*)d_in[4];
    const float* wv   = (const float*)d_in[5];
    const float* wo   = (const float*)d_in[6];
    const float* w1   = (const float*)d_in[7];
    const float* b1   = (const float*)d_in[8];
    const float* w2   = (const float*)d_in[9];
    const float* b2   = (const float*)d_in[10];
    float* out = (float*)d_out;

    float *attn, *sc, *tcs, *tsn;
    f16 *qkv16, *xnh, *qh, *kh, *vth, *sch, *cxh, *hbh;
    f16 *wqkvh, *woh, *w1h, *w2h;

    cudaGetSymbolAddress((void**)&attn, g_attn);
    cudaGetSymbolAddress((void**)&sc,   g_sc);
    cudaGetSymbolAddress((void**)&tcs,  g_tcos);
    cudaGetSymbolAddress((void**)&tsn,  g_tsin);
    cudaGetSymbolAddress((void**)&qkv16, g_qkv16);
    cudaGetSymbolAddress((void**)&xnh,  g_xnh);
    cudaGetSymbolAddress((void**)&qh,   g_qh);
    cudaGetSymbolAddress((void**)&kh,   g_kh);
    cudaGetSymbolAddress((void**)&vth,  g_vth);
    cudaGetSymbolAddress((void**)&sch,  g_sch);
    cudaGetSymbolAddress((void**)&cxh,  g_cxh);
    cudaGetSymbolAddress((void**)&hbh,  g_hbh);
    cudaGetSymbolAddress((void**)&wqkvh, g_wqkvh);
    cudaGetSymbolAddress((void**)&woh,  g_woh);
    cudaGetSymbolAddress((void**)&w1h,  g_w1h);
    cudaGetSymbolAddress((void**)&w2h,  g_w2h);

    cudaFuncSetAttribute(mma_gemm, cudaFuncAttributeMaxDynamicSharedMemorySize,
                         GEMM_SMEM_BYTES);

    // side stream + fork/join events (host-side resources, created once)
    static cudaStream_t sW = nullptr;
    static cudaEvent_t evFork = nullptr, evJoin = nullptr;
    if (sW == nullptr) {
        cudaStreamCreateWithFlags(&sW, cudaStreamNonBlocking);
        cudaEventCreateWithFlags(&evFork, cudaEventDisableTiming);
        cudaEventCreateWithFlags(&evJoin, cudaEventDisableTiming);
    }

    const dim3 tb32(32, 8);

    // 0) RoPE table + weight transposes
    rope_table_kernel<<<T_, 32>>>(tcs, tsn);
    transpose_hi_kernel<<<dim3(D_ / 32, D_ / 32), tb32>>>(wq, wqkvh, D_, D_);
    transpose_hi_kernel<<<dim3(D_ / 32, D_ / 32), tb32>>>(wk, wqkvh + (size_t)D_ * D_, D_, D_);
    transpose_hi_kernel<<<dim3(D_ / 32, D_ / 32), tb32>>>(wv, wqkvh + (size_t)2 * D_ * D_, D_, D_);
    transpose_hi_kernel<<<dim3(FF_ / 32, D_ / 32), tb32>>>(w1, w1h, D_, FF_);   // w1h: [FF][D]
    transpose_hi_kernel<<<dim3(D_ / 32, FF_ / 32), tb32>>>(w2, w2h, FF_, D_);   // w2h: [D][FF]
    transpose_hi_kernel<<<dim3(D_ / 32, D_ / 32), tb32>>>(wo, woh, D_, D_);

    // 1) LayerNorm -> xn fp16
    ln_kernel<<<T_, 256>>>(x, ln_s, ln_o, xnh);

    // ---- fork: W1 (independent of attention chain) runs on side stream ----
    cudaEventRecord(evFork, 0);
    cudaStreamWaitEvent(sW, evFork, 0);
    {
        dim3 g(FF_ / NTT, T_ / MT, 1);
        mma_gemm<<<g, 256, GEMM_SMEM_BYTES, sW>>>(D_, 0, xnh, D_, 0, w1h, D_, 0,
            nullptr, hbh, FF_, 0, 1.f, E_GELU_F16, b1, nullptr, 0);
    }
    cudaEventRecord(evJoin, sW);

    // 2) fused QKV projection (fp16 out): [2048,4096]@[4096,12288]
    {
        dim3 g(D3_ / NTT, T_ / MT, 1);
        mma_gemm<<<g, 256, GEMM_SMEM_BYTES>>>(D_, 0, xnh, D_, 0, wqkvh, D_, 0,
            nullptr, qkv16, D3_, 0, 1.f, E_F16, nullptr, nullptr, 0);
    }

    // 3) RoPE -> q, k fp16
    rope_kernel<<<T_, 256>>>(qkv16, tcs, tsn, qh, kh);

    // 4) V transpose
    transpose_v_hi_kernel<<<dim3(DH_ / 32, T_ / 32, H_), tb32>>>(qkv16, vth);

    // 5) scores = scale * Q_h @ K_h^T + causal (fp32 out, masked tiles skipped)
    {
        dim3 g(T_ / NTT, T_ / MT, H_);
        mma_gemm<<<g, 256, GEMM_SMEM_BYTES>>>(DH_, 0,
            qh, D_, DH_,
            kh, D_, DH_,
            sc, nullptr, T_, (long long)T_ * T_,
            0.0625f, E_CAUSAL, nullptr, nullptr, 0);
    }

    // 6) softmax (causal length) -> P fp16
    softmax_kernel<<<H_ * T_, 256>>>(sc, sch);

    // 7) ctx = P_h @ V_h  (causal K-limit, fp16 out)
    {
        dim3 g(DH_ / NTT, T_ / MT, H_);
        mma_gemm<<<g, 256, GEMM_SMEM_BYTES>>>(T_, 1,
            sch, T_, (long long)T_ * T_,
            vth, T_, (long long)DH_ * T_,
            nullptr, cxh, D_, DH_,
            1.f, E_F16, nullptr, nullptr, 0);
    }

    // 8) attn_out = ctx @ wo
    {
        dim3 g(D_ / NTT, T_ / MT, 1);
        mma_gemm<<<g, 256, GEMM_SMEM_BYTES>>>(D_, 0, cxh, D_, 0, woh, D_, 0,
            attn, nullptr, D_, 0, 1.f, E_F32, nullptr, nullptr, 0);
    }

    // ---- join: W2 needs h (side stream) and attn (this stream) ----
    cudaStreamWaitEvent(0, evJoin, 0);

    // 10) out = h @ w2 + b2 + attn_out — w2h stride FF_
    {
        dim3 g(D_ / NTT, T_ / MT, 1);
        mma_gemm<<<g, 256, GEMM_SMEM_BYTES>>>(FF_, 0, hbh, FF_, 0, w2h, FF_, 0,
            out, nullptr, D_, 0, 1.f, E_BIASRES, b2, attn, D_);
    }
}

// round 17
// speedup vs baseline: 2.8383x; 1.0257x over previous
#include <cuda_runtime.h>
#include <cuda_fp16.h>
#include <math.h>
#include <stdint.h>

#define T_  2048
#define D_  4096
#define D3_ 12288
#define H_  16
#define DH_ 256
#define RR_ 64
#define FF_ 16384

// GEMM tiling — pure fp16 stages: Ah(16K)+Bh(16K)
#define MT   128
#define NTT  128
#define KC   64
#define STAGE_B 32768
#define NSTAGE 3
#define GEMM_SMEM_BYTES (NSTAGE * STAGE_B)   // 96KB

typedef __half f16;

// ---------------- scratch (static device arrays: allocation-free) -----------
__device__ float g_attn[(size_t)T_ * D_];
__device__ float g_sc  [(size_t)H_ * T_ * T_];
__device__ float g_tcos[(size_t)T_ * 32];
__device__ float g_tsin[(size_t)T_ * 32];

__device__ f16 g_qkv16[(size_t)T_ * D3_];        // fused q|k|v fp16 (RoPE in-place)
__device__ f16 g_xnh [(size_t)T_ * D_];
__device__ f16 g_vth [(size_t)H_ * DH_ * T_];
__device__ f16 g_sch [(size_t)H_ * T_ * T_];
__device__ f16 g_cxh [(size_t)T_ * D_];
__device__ f16 g_hbh [(size_t)T_ * FF_];
__device__ f16 g_wqkvh[(size_t)D3_ * D_];        // fused wq|wk|wv transposed
__device__ f16 g_woh [(size_t)D_ * D_];
__device__ f16 g_w1h [(size_t)FF_ * D_];         // [FF][D], row stride D
__device__ f16 g_w2h [(size_t)D_ * FF_];         // [D][FF], row stride FF

// ---------------- helpers ----------------------------------------------------
__device__ __forceinline__ uint32_t smem_u32(const void* p) {
    uint32_t a;
    asm("{ .reg .u64 t; cvta.to.shared.u64 t, %1; cvt.u32.u64 %0, t; }"
        : "=r"(a) : "l"(p));
    return a;
}

#define SWZ(o) ((o) ^ (((o) >> 3) & 0x70))

#define CP16(dst, src) \
    asm volatile("cp.async.cg.shared.global [%0], [%1], 16;" \
                 :: "r"(dst), "l"(src))
#define CPCOMMIT() asm volatile("cp.async.commit_group;" ::: "memory")
#define CPWAIT2()  asm volatile("cp.async.wait_group 2;" ::: "memory")
#define CPWAIT0()  asm volatile("cp.async.wait_group 0;" ::: "memory")

__device__ __forceinline__ void ldm_x4(uint32_t* r, uint32_t a) {
    asm volatile("ldmatrix.sync.aligned.m8n8.x4.shared.b16 {%0,%1,%2,%3}, [%4];"
                 : "=r"(r[0]), "=r"(r[1]), "=r"(r[2]), "=r"(r[3]) : "r"(a));
}

__device__ __forceinline__ void mma16816(float* d, const uint32_t* a, const uint32_t* b) {
    asm volatile("mma.sync.aligned.m16n8k16.row.col.f32.f16.f16.f32 "
                 "{%0,%1,%2,%3}, {%4,%5,%6,%7}, {%8,%9}, {%0,%1,%2,%3};"
                 : "+f"(d[0]), "+f"(d[1]), "+f"(d[2]), "+f"(d[3])
                 : "r"(a[0]), "r"(a[1]), "r"(a[2]), "r"(a[3]),
                   "r"(b[0]), "r"(b[1]));
}

__device__ __forceinline__ uint32_t pack_hi2(float x, float y) {
    f16 hx = __float2half_rn(x);
    f16 hy = __float2half_rn(y);
    return ((uint32_t)__half_as_ushort(hy) << 16) | (uint32_t)__half_as_ushort(hx);
}

__device__ __forceinline__ float gelu_f(float x)
{
    const float x3 = x * x * x;
    return 0.5f * x * (1.0f + tanhf(0.7978845608028654f * (x + 0.044715f * x3)));
}

// ---------------- RoPE table (double-precision, computed once per launch) ----
__global__ void rope_table_kernel(float* __restrict__ tc, float* __restrict__ ts)
{
    const int t = blockIdx.x;
    const int i = threadIdx.x;          // 0..31
    const double inv = pow(10000.0, -2.0 * (double)i / (double)RR_);
    const double ang = (double)t * inv;
    tc[t * 32 + i] = (float)cos(ang);
    ts[t * 32 + i] = (float)sin(ang);
}

// ---------------- LayerNorm -> fp16 ------------------------------------------
__global__ void ln_kernel(const float* __restrict__ x,
                          const float* __restrict__ scale,
                          const float* __restrict__ offset,
                          f16* __restrict__ oh)
{
    const int t = blockIdx.x;
    const float* xr = x + (size_t)t * D_;
    const int base = threadIdx.x * 16;
    __shared__ float red[256];

    float v[16];
#pragma unroll
    for (int i = 0; i < 16; i += 4)
        *reinterpret_cast<float4*>(v + i) =
            *reinterpret_cast<const float4*>(xr + base + i);

    float s = 0.f;
#pragma unroll
    for (int i = 0; i < 16; i++) s += v[i];
    red[threadIdx.x] = s; __syncthreads();
    for (int o = 128; o > 0; o >>= 1) {
        if (threadIdx.x < o) red[threadIdx.x] += red[threadIdx.x + o];
        __syncthreads();
    }
    const float mean = red[0] * (1.0f / D_);
    __syncthreads();

    float vv = 0.f;
#pragma unroll
    for (int i = 0; i < 16; i++) { float d = v[i] - mean; vv += d * d; }
    red[threadIdx.x] = vv; __syncthreads();
    for (int o = 128; o > 0; o >>= 1) {
        if (threadIdx.x < o) red[threadIdx.x] += red[threadIdx.x + o];
        __syncthreads();
    }
    const float rstd = rsqrtf(red[0] * (1.0f / D_) + 1e-5f);

    f16* ohr = oh + (size_t)t * D_ + base;
#pragma unroll
    for (int i = 0; i < 16; i += 2) {
        float y0 = (v[i]     - mean) * rstd * scale[base + i]     + offset[base + i];
        float y1 = (v[i + 1] - mean) * rstd * scale[base + i + 1] + offset[base + i + 1];
        *reinterpret_cast<uint32_t*>(ohr + i) = pack_hi2(y0, y1);
    }
}

// ---------------- RoPE in place on fp16 qkv (q and k slices) ------------------
__global__ void rope_kernel(f16* __restrict__ qkv,
                            const float* __restrict__ tc,
                            const float* __restrict__ ts)
{
    const int t = blockIdx.x;
    const int d0 = threadIdx.x * 16;
    const size_t src = (size_t)t * D3_ + d0;   // q at col 0, k at col D_

#pragma unroll
    for (int j = 0; j < 8; j++) {
        const int d = d0 + 2 * j;
        const int dd = d & (DH_ - 1);
        if (dd >= RR_) continue;
        const int i = dd >> 1;
        const float c = tc[t * 32 + i];
        const float s = ts[t * 32 + i];
        float2 qv = __half22float2(*reinterpret_cast<const __half2*>(qkv + src + 2 * j));
        float2 kv = __half22float2(*reinterpret_cast<const __half2*>(qkv + src + D_ + 2 * j));
        float q0 = qv.x, q1 = qv.y;
        float k0 = kv.x, k1 = kv.y;
        *reinterpret_cast<uint32_t*>(qkv + src + 2 * j) =
            pack_hi2(q0 * c - q1 * s, q1 * c + q0 * s);
        *reinterpret_cast<uint32_t*>(qkv + src + D_ + 2 * j) =
            pack_hi2(k0 * c - k1 * s, k1 * c + k0 * s);
    }
}

// ---------------- softmax (causal-limited, fp32 scores) -> fp16 --------------
__global__ void softmax_kernel(const float* __restrict__ scores,
                               f16* __restrict__ ph)
{
    const size_t row = blockIdx.x;
    const int t = (int)(row & (T_ - 1));
    const int L = ((t >> 7) + 1) << 7;          // causal row length, mult of 128
    const float* r = scores + row * (size_t)T_;
    const int base = threadIdx.x * 8;
    const bool act = base < L;                  // 8-blocks fully in or out
    __shared__ float red[256];

    float v[8];
    if (act) {
#pragma unroll
        for (int i = 0; i < 8; i += 4)
            *reinterpret_cast<float4*>(v + i) =
                *reinterpret_cast<const float4*>(r + base + i);
    } else {
#pragma unroll
        for (int i = 0; i < 8; i++) v[i] = -1e30f;
    }

    float m = -1e30f;
#pragma unroll
    for (int i = 0; i < 8; i++) m = fmaxf(m, v[i]);
    red[threadIdx.x] = m; __syncthreads();
    for (int o = 128; o > 0; o >>= 1) {
        if (threadIdx.x < o) red[threadIdx.x] = fmaxf(red[threadIdx.x], red[threadIdx.x + o]);
        __syncthreads();
    }
    m = red[0]; __syncthreads();

    float s = 0.f;
    if (act) {
#pragma unroll
        for (int i = 0; i < 8; i++) { v[i] = __expf(v[i] - m); s += v[i]; }
    }
    red[threadIdx.x] = s; __syncthreads();
    for (int o = 128; o > 0; o >>= 1) {
        if (threadIdx.x < o) red[threadIdx.x] += red[threadIdx.x + o];
        __syncthreads();
    }
    const float invs = 1.0f / red[0];

    if (act) {
        f16* phr = ph + row * (size_t)T_ + base;
#pragma unroll
        for (int i = 0; i < 8; i += 2) {
            *reinterpret_cast<uint32_t*>(phr + i) =
                pack_hi2(v[i] * invs, v[i + 1] * invs);
        }
    }
}

// ---------------- transpose: in[R][C] fp32 -> out[C][R] fp16 ------------------
__global__ void transpose_hi_kernel(const float* __restrict__ in,
                                    f16* __restrict__ oh, int R, int C)
{
    __shared__ float t[32][33];
    const int c0 = blockIdx.x * 32, r0 = blockIdx.y * 32;
    const int x = threadIdx.x, y = threadIdx.y;
#pragma unroll
    for (int i = 0; i < 32; i += 8)
        t[y + i][x] = in[(size_t)(r0 + y + i) * C + c0 + x];
    __syncthreads();
#pragma unroll
    for (int i = 0; i < 32; i += 8) {
        const size_t o = (size_t)(c0 + y + i) * R + r0 + x;
        oh[o] = __float2half_rn(t[x][y + i]);
    }
}

// per-head transpose of V (cols 2D.. of fp16 qkv): vt[h][d][t]
__global__ void transpose_v_hi_kernel(const f16* __restrict__ qkv,
                                      f16* __restrict__ oh)
{
    __shared__ f16 s[32][33];
    const int h = blockIdx.z;
    const int d0 = blockIdx.x * 32, t0 = blockIdx.y * 32;
    const int x = threadIdx.x, y = threadIdx.y;
#pragma unroll
    for (int i = 0; i < 32; i += 8)
        s[y + i][x] = qkv[(size_t)(t0 + y + i) * D3_ + 2 * D_ + (size_t)h * DH_ + d0 + x];
    __syncthreads();
#pragma unroll
    for (int i = 0; i < 32; i += 8) {
        const size_t o = ((size_t)h * DH_ + d0 + y + i) * T_ + t0 + x;
        oh[o] = s[x][y + i];
    }
}

// ---------------- fp16 GEMM: C = A @ B^T (fp32 accum) ------------------------
// climit != 0: effective K for row-block at m0 is (m0 + MT) (causal PV).
enum { E_F32 = 0, E_CAUSAL = 1, E_F16 = 2, E_GELU_F16 = 3, E_BIASRES = 4 };

__global__ void __launch_bounds__(256, 1)
mma_gemm(int K, int climit,
         const f16* __restrict__ A, int lda, long long sA,
         const f16* __restrict__ B, int ldb, long long sB,
         float* __restrict__ C, f16* __restrict__ Ch,
         int ldc, long long sC,
         float alpha, int epi,
         const float* __restrict__ bias,
         const float* __restrict__ res, int ldres)
{
    extern __shared__ char smem[];
    const uint32_t sbase = smem_u32(smem);
    const int tid = threadIdx.x;
    const int wid = tid >> 5, lid = tid & 31;
    const int m0 = blockIdx.y * MT, n0 = blockIdx.x * NTT;

    A += (size_t)blockIdx.z * sA;
    B += (size_t)blockIdx.z * sB;
    if (C)  C  += (size_t)blockIdx.z * sC;
    if (Ch) Ch += (size_t)blockIdx.z * sC;

    // fully-masked causal tile: nothing downstream reads it -> skip entirely
    if (epi == E_CAUSAL && n0 > m0 + (MT - 1)) return;

    const int Keff = climit ? (m0 + MT) : K;   // causal K-limit (multiple of KC)

    const int wm = (wid >> 2) * 64;
    const int wn = (wid & 3) * 32;

    float acc[4][4][4];
#pragma unroll
    for (int i = 0; i < 4; i++)
#pragma unroll
        for (int j = 0; j < 4; j++)
#pragma unroll
            for (int r = 0; r < 4; r++) acc[i][j][r] = 0.f;

    const int lrow = tid >> 3;     // 0..31 (plus p*32)
    const int lcol = tid & 7;      // 16B column within 128B row

    const int NC = Keff / KC;

#define ISSUE_STAGE(stg, kc_) do {                                              \
        const int kc__ = (kc_);                                                 \
        _Pragma("unroll")                                                       \
        for (int p = 0; p < 4; p++) {                                           \
            const int row = lrow + p * 32;                                      \
            const uint32_t dsw = SWZ((uint32_t)(row * 128 + lcol * 16));        \
            const uint32_t db = sbase + (uint32_t)(stg) * STAGE_B + dsw;        \
            CP16(db,          A + (size_t)(m0 + row) * lda + kc__ + lcol * 8);  \
            CP16(db + 16384u, B + (size_t)(n0 + row) * ldb + kc__ + lcol * 8);  \
        }                                                                       \
        CPCOMMIT();                                                             \
    } while (0)

    ISSUE_STAGE(0, 0);
    ISSUE_STAGE(1, KC);

    const uint32_t aRawBase = (uint32_t)((wm + (lid & 15)) * 128 + (lid >> 4) * 16);
    const uint32_t bRawBase = (uint32_t)((wn + (lid & 7) + ((lid >> 4) << 3)) * 128
                                         + (((lid >> 3) & 1) << 4));

    for (int c = 0; c < NC; ++c) {
        if (c + 2 < NC) {
            ISSUE_STAGE((c + 2) % NSTAGE, (c + 2) * KC);
            CPWAIT2();
        } else {
            CPWAIT0();
        }
        __syncthreads();

        const uint32_t st = sbase + (uint32_t)(c % NSTAGE) * STAGE_B;

#pragma unroll
        for (int ks = 0; ks < 4; ks++) {
            const uint32_t kb = (uint32_t)ks * 32;
            uint32_t ah[4][4], bh[4][2];
#pragma unroll
            for (int i = 0; i < 4; i++) {
                const uint32_t raw = aRawBase + (uint32_t)i * (16 * 128) + kb;
                ldm_x4(ah[i], st + SWZ(raw));
            }
#pragma unroll
            for (int j2 = 0; j2 < 2; j2++) {
                const uint32_t raw = bRawBase + (uint32_t)j2 * (16 * 128) + kb;
                uint32_t t4[4];
                ldm_x4(t4, st + 16384u + SWZ(raw));
                bh[2 * j2][0] = t4[0]; bh[2 * j2][1] = t4[1];
                bh[2 * j2 + 1][0] = t4[2]; bh[2 * j2 + 1][1] = t4[3];
            }
#pragma unroll
            for (int i = 0; i < 4; i++)
#pragma unroll
                for (int j = 0; j < 4; j++)
                    mma16816(acc[i][j], ah[i], bh[j]);
        }
        __syncthreads();
    }
#undef ISSUE_STAGE

    // ---------------- epilogue ----------------
    const int tr = lid >> 2, tc = (lid & 3) * 2;
#pragma unroll
    for (int i = 0; i < 4; i++) {
        const int m1 = m0 + wm + i * 16 + tr;
        const int m2 = m1 + 8;
#pragma unroll
        for (int j = 0; j < 4; j++) {
            const int n = n0 + wn + j * 8 + tc;
            float v0 = acc[i][j][0] * alpha;
            float v1 = acc[i][j][1] * alpha;
            float v2 = acc[i][j][2] * alpha;
            float v3 = acc[i][j][3] * alpha;
            if (epi == E_CAUSAL) {
                if (n     > m1) v0 = -1e10f;
                if (n + 1 > m1) v1 = -1e10f;
                if (n     > m2) v2 = -1e10f;
                if (n + 1 > m2) v3 = -1e10f;
            } else if (epi == E_GELU_F16) {
                const float b0 = bias[n], b1 = bias[n + 1];
                v0 = gelu_f(v0 + b0); v1 = gelu_f(v1 + b1);
                v2 = gelu_f(v2 + b0); v3 = gelu_f(v3 + b1);
            } else if (epi == E_BIASRES) {
                const float b0 = bias[n], b1 = bias[n + 1];
                const float2 r1 = *reinterpret_cast<const float2*>(res + (size_t)m1 * ldres + n);
                const float2 r2 = *reinterpret_cast<const float2*>(res + (size_t)m2 * ldres + n);
                v0 += b0 + r1.x; v1 += b1 + r1.y;
                v2 += b0 + r2.x; v3 += b1 + r2.y;
            }
            if (epi == E_F16 || epi == E_GELU_F16) {
                *reinterpret_cast<uint32_t*>(Ch + (size_t)m1 * ldc + n) = pack_hi2(v0, v1);
                *reinterpret_cast<uint32_t*>(Ch + (size_t)m2 * ldc + n) = pack_hi2(v2, v3);
            } else {
                *reinterpret_cast<float2*>(C + (size_t)m1 * ldc + n) = make_float2(v0, v1);
                *reinterpret_cast<float2*>(C + (size_t)m2 * ldc + n) = make_float2(v2, v3);
            }
        }
    }
}

// ---------------- launch -----------------------------------------------------
extern "C" void kernel_launch(void* const* d_in, const int* in_sizes, int n_in,
                              void* d_out, int out_size)
{
    const float* x    = (const float*)d_in[0];
    const float* ln_s = (const float*)d_in[1];
    const float* ln_o = (const float*)d_in[2];
    const float* wq   = (const float*)d_in[3];
    const float* wk   = (const float*)d_in[4];
    const float* wv   = (const float*)d_in[5];
    const float* wo   = (const float*)d_in[6];
    const float* w1   = (const float*)d_in[7];
    const float* b1   = (const float*)d_in[8];
    const float* w2   = (const float*)d_in[9];
    const float* b2   = (const float*)d_in[10];
    float* out = (float*)d_out;

    float *attn, *sc, *tcs, *tsn;
    f16 *qkv16, *xnh, *vth, *sch, *cxh, *hbh;
    f16 *wqkvh, *woh, *w1h, *w2h;

    cudaGetSymbolAddress((void**)&attn, g_attn);
    cudaGetSymbolAddress((void**)&sc,   g_sc);
    cudaGetSymbolAddress((void**)&tcs,  g_tcos);
    cudaGetSymbolAddress((void**)&tsn,  g_tsin);
    cudaGetSymbolAddress((void**)&qkv16, g_qkv16);
    cudaGetSymbolAddress((void**)&xnh,  g_xnh);
    cudaGetSymbolAddress((void**)&vth,  g_vth);
    cudaGetSymbolAddress((void**)&sch,  g_sch);
    cudaGetSymbolAddress((void**)&cxh,  g_cxh);
    cudaGetSymbolAddress((void**)&hbh,  g_hbh);
    cudaGetSymbolAddress((void**)&wqkvh, g_wqkvh);
    cudaGetSymbolAddress((void**)&woh,  g_woh);
    cudaGetSymbolAddress((void**)&w1h,  g_w1h);
    cudaGetSymbolAddress((void**)&w2h,  g_w2h);

    cudaFuncSetAttribute(mma_gemm, cudaFuncAttributeMaxDynamicSharedMemorySize,
                         GEMM_SMEM_BYTES);

    // side stream + events (host-side resources, created once)
    static cudaStream_t sW = nullptr;
    static cudaEvent_t evStart = nullptr, evFork = nullptr, evWo = nullptr, evJoin = nullptr;
    if (sW == nullptr) {
        cudaStreamCreateWithFlags(&sW, cudaStreamNonBlocking);
        cudaEventCreateWithFlags(&evStart, cudaEventDisableTiming);
        cudaEventCreateWithFlags(&evFork,  cudaEventDisableTiming);
        cudaEventCreateWithFlags(&evWo,    cudaEventDisableTiming);
        cudaEventCreateWithFlags(&evJoin,  cudaEventDisableTiming);
    }

    const dim3 tb32(32, 8);

    // ---- fork side stream at position 0 (pulls sW into graph capture) ----
    cudaEventRecord(evStart, 0);
    cudaStreamWaitEvent(sW, evStart, 0);

    // side stream: wo/w1/w2 weight conversions (not needed until late)
    transpose_hi_kernel<<<dim3(D_ / 32, D_ / 32), tb32, 0, sW>>>(wo, woh, D_, D_);
    cudaEventRecord(evWo, sW);
    transpose_hi_kernel<<<dim3(FF_ / 32, D_ / 32), tb32, 0, sW>>>(w1, w1h, D_, FF_);  // w1h: [FF][D]
    transpose_hi_kernel<<<dim3(D_ / 32, FF_ / 32), tb32, 0, sW>>>(w2, w2h, FF_, D_);  // w2h: [D][FF]

    // main stream: rope table + wqkv conversions + LN
    rope_table_kernel<<<T_, 32>>>(tcs, tsn);
    transpose_hi_kernel<<<dim3(D_ / 32, D_ / 32), tb32>>>(wq, wqkvh, D_, D_);
    transpose_hi_kernel<<<dim3(D_ / 32, D_ / 32), tb32>>>(wk, wqkvh + (size_t)D_ * D_, D_, D_);
    transpose_hi_kernel<<<dim3(D_ / 32, D_ / 32), tb32>>>(wv, wqkvh + (size_t)2 * D_ * D_, D_, D_);
    ln_kernel<<<T_, 256>>>(x, ln_s, ln_o, xnh);

    // fork for W1 (needs xnh + w1h; w1h already ordered on sW)
    cudaEventRecord(evFork, 0);
    cudaStreamWaitEvent(sW, evFork, 0);
    {
        dim3 g(FF_ / NTT, T_ / MT, 1);
        mma_gemm<<<g, 256, GEMM_SMEM_BYTES, sW>>>(D_, 0, xnh, D_, 0, w1h, D_, 0,
            nullptr, hbh, FF_, 0, 1.f, E_GELU_F16, b1, nullptr, 0);
    }
    cudaEventRecord(evJoin, sW);

    // 2) fused QKV projection (fp16 out): [2048,4096]@[4096,12288]
    {
        dim3 g(D3_ / NTT, T_ / MT, 1);
        mma_gemm<<<g, 256, GEMM_SMEM_BYTES>>>(D_, 0, xnh, D_, 0, wqkvh, D_, 0,
            nullptr, qkv16, D3_, 0, 1.f, E_F16, nullptr, nullptr, 0);
    }

    // 3) RoPE in place on qkv16 (q and k slices)
    rope_kernel<<<T_, 256>>>(qkv16, tcs, tsn);

    // 4) V transpose
    transpose_v_hi_kernel<<<dim3(DH_ / 32, T_ / 32, H_), tb32>>>(qkv16, vth);

    // 5) scores = scale * Q_h @ K_h^T + causal (reads qkv16 directly)
    {
        dim3 g(T_ / NTT, T_ / MT, H_);
        mma_gemm<<<g, 256, GEMM_SMEM_BYTES>>>(DH_, 0,
            qkv16,      D3_, DH_,      // Q_h: head h at col h*DH
            qkv16 + D_, D3_, DH_,      // K_h: head h at col D + h*DH
            sc, nullptr, T_, (long long)T_ * T_,
            0.0625f, E_CAUSAL, nullptr, nullptr, 0);
    }

    // 6) softmax (causal length) -> P fp16
    softmax_kernel<<<H_ * T_, 256>>>(sc, sch);

    // 7) ctx = P_h @ V_h  (causal K-limit, fp16 out)
    {
        dim3 g(DH_ / NTT, T_ / MT, H_);
        mma_gemm<<<g, 256, GEMM_SMEM_BYTES>>>(T_, 1,
            sch, T_, (long long)T_ * T_,
            vth, T_, (long long)DH_ * T_,
            nullptr, cxh, D_, DH_,
            1.f, E_F16, nullptr, nullptr, 0);
    }

    // 8) attn_out = ctx @ wo (needs woh from side stream)
    cudaStreamWaitEvent(0, evWo, 0);
    {
        dim3 g(D_ / NTT, T_ / MT, 1);
        mma_gemm<<<g, 256, GEMM_SMEM_BYTES>>>(D_, 0, cxh, D_, 0, woh, D_, 0,
            attn, nullptr, D_, 0, 1.f, E_F32, nullptr, nullptr, 0);
    }

    // ---- join: W2 needs h (side stream) and attn (this stream) ----
    cudaStreamWaitEvent(0, evJoin, 0);

    // 10) out = h @ w2 + b2 + attn_out — w2h stride FF_
    {
        dim3 g(D_ / NTT, T_ / MT, 1);
        mma_gemm<<<g, 256, GEMM_SMEM_BYTES>>>(FF_, 0, hbh, FF_, 0, w2h, FF_, 0,
            out, nullptr, D_, 0, 1.f, E_BIASRES, b2, attn, D_);
    }
}